// round 6
// baseline (speedup 1.0000x reference)
#include <cuda_runtime.h>
#include <cuda_bf16.h>
#include <math.h>
#include <stdint.h>

// Problem constants
#define BB 4
#define NN 1024
#define DM 1024
#define NH 16
#define DK 64

// ---------------------------------------------------------------------------
// Scratch (__device__ globals; allocation-free rule)
// ---------------------------------------------------------------------------
#define ACT_ELEMS (4096 * 1024)
#define W_ELEMS   (1024 * 1024)
__device__ __align__(16) __nv_bfloat16 g_ah[3ull * ACT_ELEMS];
__device__ __align__(16) __nv_bfloat16 g_al[3ull * ACT_ELEMS];
__device__ __align__(16) __nv_bfloat16 g_wh[4ull * W_ELEMS];
__device__ __align__(16) __nv_bfloat16 g_wl[4ull * W_ELEMS];
__device__ __align__(16) __nv_bfloat16 g_qkvh[3ull * ACT_ELEMS];
__device__ __align__(16) __nv_bfloat16 g_qkvl[3ull * ACT_ELEMS];
__device__ __align__(16) __nv_bfloat16 g_ch[ACT_ELEMS], g_cl[ACT_ELEMS];

// ---------------------------------------------------------------------------
// PTX helpers (compute_103-safe)
// ---------------------------------------------------------------------------
__device__ __forceinline__ uint32_t smem_u32(const void* p) {
    uint32_t a;
    asm("{ .reg .u64 t; cvta.to.shared.u64 t, %1; cvt.u32.u64 %0, t; }"
        : "=r"(a) : "l"(p));
    return a;
}

#define CP16(dst, src) \
    asm volatile("cp.async.cg.shared.global [%0], [%1], 16;" \
        :: "r"(dst), "l"(src) : "memory")
#define CP_COMMIT() asm volatile("cp.async.commit_group;" ::: "memory")
#define CP_WAIT1()  asm volatile("cp.async.wait_group 1;" ::: "memory")
#define CP_WAIT0()  asm volatile("cp.async.wait_group 0;" ::: "memory")

__device__ __forceinline__ void ldsm_x4(uint32_t* r, uint32_t addr) {
    asm volatile("ldmatrix.sync.aligned.m8n8.x4.shared.b16 {%0,%1,%2,%3}, [%4];"
        : "=r"(r[0]), "=r"(r[1]), "=r"(r[2]), "=r"(r[3]) : "r"(addr));
}
__device__ __forceinline__ void ldsm_x4_t(uint32_t* r, uint32_t addr) {
    asm volatile("ldmatrix.sync.aligned.m8n8.x4.trans.shared.b16 {%0,%1,%2,%3}, [%4];"
        : "=r"(r[0]), "=r"(r[1]), "=r"(r[2]), "=r"(r[3]) : "r"(addr));
}

__device__ __forceinline__ void mma16816(float* c, const uint32_t* a,
                                         const uint32_t* b) {
    asm volatile(
        "mma.sync.aligned.m16n8k16.row.col.f32.bf16.bf16.f32 "
        "{%0,%1,%2,%3}, {%4,%5,%6,%7}, {%8,%9}, {%0,%1,%2,%3};"
        : "+f"(c[0]), "+f"(c[1]), "+f"(c[2]), "+f"(c[3])
        : "r"(a[0]), "r"(a[1]), "r"(a[2]), "r"(a[3]), "r"(b[0]), "r"(b[1]));
}

__device__ __forceinline__ void split2(float x, float y, uint32_t& h, uint32_t& l) {
    __nv_bfloat16 hx = __float2bfloat16(x), hy = __float2bfloat16(y);
    __nv_bfloat16 lx = __float2bfloat16(x - __bfloat162float(hx));
    __nv_bfloat16 ly = __float2bfloat16(y - __bfloat162float(hy));
    __nv_bfloat162 th(hx, hy), tl(lx, ly);
    h = *(uint32_t*)&th;
    l = *(uint32_t*)&tl;
}

// ---------------------------------------------------------------------------
// Conversions (fused launches)
// ---------------------------------------------------------------------------
__global__ __launch_bounds__(256) void conv_act3(
    const float* __restrict__ q, const float* __restrict__ k,
    const float* __restrict__ v)
{
    const float* X = blockIdx.y == 0 ? q : (blockIdx.y == 1 ? k : v);
    __nv_bfloat16* hi = g_ah + (size_t)blockIdx.y * ACT_ELEMS;
    __nv_bfloat16* lo = g_al + (size_t)blockIdx.y * ACT_ELEMS;
    int e = (blockIdx.x * 256 + threadIdx.x) * 4;
    float4 x = *(const float4*)(X + e);
    float xs[4] = {x.x, x.y, x.z, x.w};
    union { __nv_bfloat16 b[4]; uint2 u; } ph, pl;
    #pragma unroll
    for (int j = 0; j < 4; j++) {
        __nv_bfloat16 h = __float2bfloat16(xs[j]);
        ph.b[j] = h;
        pl.b[j] = __float2bfloat16(xs[j] - __bfloat162float(h));
    }
    *(uint2*)(hi + e) = ph.u;
    *(uint2*)(lo + e) = pl.u;
}

__global__ void conv_wt4(const float* __restrict__ Wq, const float* __restrict__ Wk,
                         const float* __restrict__ Wv, const float* __restrict__ Wo)
{
    __shared__ float t[32][33];
    const int z = blockIdx.z;
    const float* W = z == 0 ? Wq : (z == 1 ? Wk : (z == 2 ? Wv : Wo));
    __nv_bfloat16* hi = g_wh + (size_t)z * W_ELEMS;
    __nv_bfloat16* lo = g_wl + (size_t)z * W_ELEMS;
    int n0 = blockIdx.x * 32, k0 = blockIdx.y * 32;
    int tx = threadIdx.x, ty = threadIdx.y;  // 32 x 8

    #pragma unroll
    for (int j = 0; j < 32; j += 8)
        t[ty + j][tx] = W[(size_t)(k0 + ty + j) * 1024 + n0 + tx];
    __syncthreads();

    #pragma unroll
    for (int j = 0; j < 32; j += 8) {
        int n = n0 + ty + j, k = k0 + tx;
        float x = t[tx][ty + j];
        __nv_bfloat16 h = __float2bfloat16(x);
        __nv_bfloat16 l = __float2bfloat16(x - __bfloat162float(h));
        hi[(size_t)n * 1024 + k] = h;
        lo[(size_t)n * 1024 + k] = l;
    }
}

// ---------------------------------------------------------------------------
// HMMA GEMM body, bf16 hi/lo split (3-term), RAW-chain-free MMA ordering.
// ---------------------------------------------------------------------------
#define ROWB 80
#define ARR_B (128 * ROWB)
#define STAGE_B (4 * ARR_B)
#define GEMM_SMEM (2 * STAGE_B)

__device__ __forceinline__ void gemm_load_stage(
    uint32_t dbase, int m0, int n0, int k0, int tid,
    const __nv_bfloat16* Ah, const __nv_bfloat16* Al,
    const __nv_bfloat16* Bh, const __nv_bfloat16* Bl)
{
    int ldc = tid & 3;
    int r0 = tid >> 2;
    #pragma unroll
    for (int h = 0; h < 2; h++) {
        int row = r0 + h * 64;
        uint32_t doff = dbase + row * ROWB + ldc * 16;
        size_t ga = (size_t)(m0 + row) * 1024 + k0 + ldc * 8;
        size_t gb = (size_t)(n0 + row) * 1024 + k0 + ldc * 8;
        CP16(doff,             Ah + ga);
        CP16(doff + ARR_B,     Al + ga);
        CP16(doff + 2 * ARR_B, Bh + gb);
        CP16(doff + 3 * ARR_B, Bl + gb);
    }
}

template <bool OUT_BF16>
__device__ __forceinline__ void gemm_body(
    const __nv_bfloat16* __restrict__ Ah, const __nv_bfloat16* __restrict__ Al,
    const __nv_bfloat16* __restrict__ Bh, const __nv_bfloat16* __restrict__ Bl,
    const float* __restrict__ bias, float* __restrict__ C,
    __nv_bfloat16* __restrict__ Ch, __nv_bfloat16* __restrict__ Cl,
    float scale, int m0, int n0, char* sm)
{
    const uint32_t sb = smem_u32(sm);
    const int tid = threadIdx.x;
    const int lid = tid & 31, wid = tid >> 5;
    const int wm = wid >> 1, wn = wid & 1;

    float acc[2][8][4];
    #pragma unroll
    for (int f = 0; f < 2; f++)
        #pragma unroll
        for (int n = 0; n < 8; n++)
            #pragma unroll
            for (int j = 0; j < 4; j++) acc[f][n][j] = 0.0f;

    const uint32_t a_rel = (uint32_t)(wm * 32 + (lid & 15)) * ROWB + ((lid >> 4) << 4);
    const uint32_t b_rel = (uint32_t)(wn * 64 + (lid & 7) + ((lid >> 4) << 3)) * ROWB
                           + (((lid >> 3) & 1) << 4);

    gemm_load_stage(sb, m0, n0, 0, tid, Ah, Al, Bh, Bl);
    CP_COMMIT();

    for (int c = 0; c < 32; c++) {
        const int s = c & 1;
        if (c < 31) {
            gemm_load_stage(sb + (s ^ 1) * STAGE_B, m0, n0, (c + 1) * 32, tid,
                            Ah, Al, Bh, Bl);
            CP_COMMIT();
            CP_WAIT1();
        } else {
            CP_WAIT0();
        }
        __syncthreads();

        const uint32_t base = sb + s * STAGE_B;
        #pragma unroll
        for (int ks = 0; ks < 2; ks++) {
            const uint32_t koff = ks * 32;
            uint32_t ah[2][4], al[2][4];
            #pragma unroll
            for (int f = 0; f < 2; f++) {
                ldsm_x4(ah[f], base + a_rel + f * 16 * ROWB + koff);
                ldsm_x4(al[f], base + ARR_B + a_rel + f * 16 * ROWB + koff);
            }
            #pragma unroll
            for (int nfp = 0; nfp < 4; nfp++) {
                uint32_t bh[4], bl[4];
                ldsm_x4(bh, base + 2 * ARR_B + b_rel + nfp * 16 * ROWB + koff);
                ldsm_x4(bl, base + 3 * ARR_B + b_rel + nfp * 16 * ROWB + koff);
                float* a00 = acc[0][nfp * 2 + 0];
                float* a01 = acc[0][nfp * 2 + 1];
                float* a10 = acc[1][nfp * 2 + 0];
                float* a11 = acc[1][nfp * 2 + 1];
                // rotate 4 accumulators: RAW gap = 4
                mma16816(a00, ah[0], bh + 0);
                mma16816(a10, ah[1], bh + 0);
                mma16816(a01, ah[0], bh + 2);
                mma16816(a11, ah[1], bh + 2);
                mma16816(a00, ah[0], bl + 0);
                mma16816(a10, ah[1], bl + 0);
                mma16816(a01, ah[0], bl + 2);
                mma16816(a11, ah[1], bl + 2);
                mma16816(a00, al[0], bh + 0);
                mma16816(a10, al[1], bh + 0);
                mma16816(a01, al[0], bh + 2);
                mma16816(a11, al[1], bh + 2);
            }
        }
        __syncthreads();
    }

    const int r_base = m0 + wm * 32 + (lid >> 2);
    const int c_lane = (lid & 3) * 2;
    #pragma unroll
    for (int f = 0; f < 2; f++) {
        #pragma unroll
        for (int nf = 0; nf < 8; nf++) {
            int col = n0 + wn * 64 + nf * 8 + c_lane;
            float2 bb = *(const float2*)(bias + col);
            int r0 = r_base + f * 16;
            float* a = acc[f][nf];
            float v0 = (a[0] + bb.x) * scale, v1 = (a[1] + bb.y) * scale;
            float v2 = (a[2] + bb.x) * scale, v3 = (a[3] + bb.y) * scale;
            if (OUT_BF16) {
                uint32_t h0, l0, h1, l1;
                split2(v0, v1, h0, l0);
                split2(v2, v3, h1, l1);
                *(uint32_t*)(Ch + (size_t)r0 * 1024 + col) = h0;
                *(uint32_t*)(Cl + (size_t)r0 * 1024 + col) = l0;
                *(uint32_t*)(Ch + (size_t)(r0 + 8) * 1024 + col) = h1;
                *(uint32_t*)(Cl + (size_t)(r0 + 8) * 1024 + col) = l1;
            } else {
                *(float2*)(C + (size_t)r0 * 1024 + col) = make_float2(v0, v1);
                *(float2*)(C + (size_t)(r0 + 8) * 1024 + col) = make_float2(v2, v3);
            }
        }
    }
}

// Fused QKV projection: grid (8, 32, 3)
__global__ __launch_bounds__(256, 2) void qkv_gemm(
    const float* __restrict__ bq, const float* __restrict__ bk,
    const float* __restrict__ bv)
{
    extern __shared__ __align__(16) char sm[];
    const int z = blockIdx.z;
    const float* bias = z == 0 ? bq : (z == 1 ? bk : bv);
    gemm_body<true>(g_ah + (size_t)z * ACT_ELEMS, g_al + (size_t)z * ACT_ELEMS,
                    g_wh + (size_t)z * W_ELEMS,  g_wl + (size_t)z * W_ELEMS,
                    bias, nullptr,
                    g_qkvh + (size_t)z * ACT_ELEMS, g_qkvl + (size_t)z * ACT_ELEMS,
                    z == 0 ? 0.125f : 1.0f,
                    blockIdx.y * 128, blockIdx.x * 128, sm);
}

// Output projection: grid (8, 32)
__global__ __launch_bounds__(256, 2) void out_gemm(
    const float* __restrict__ bo, float* __restrict__ out)
{
    extern __shared__ __align__(16) char sm[];
    gemm_body<false>(g_ch, g_cl, g_wh + 3ull * W_ELEMS, g_wl + 3ull * W_ELEMS,
                     bo, out, nullptr, nullptr, 1.0f,
                     blockIdx.y * 128, blockIdx.x * 128, sm);
}

// ---------------------------------------------------------------------------
// Tensor-core flash attention, Q tile 128 rows, 256 threads (8 warps),
// RAW-chain-free MMA ordering in S and PV stages.
// ---------------------------------------------------------------------------
#define KROWB 144
#define TILE9K (64 * KROWB)
#define QTILE (128 * KROWB)
#define BROWB 272
#define BIAS_B (128 * BROWB)
#define STAGE_A (4 * TILE9K + BIAS_B)
#define Q_OFF (2 * STAGE_A)
#define ATTN_SMEM (Q_OFF + 2 * QTILE)

__device__ __forceinline__ void attn_load_stage(
    uint32_t dst, int b, int h, int qt, int kt, int tid,
    const float* __restrict__ bias)
{
    const __nv_bfloat16* kh = g_qkvh + 1ull * ACT_ELEMS;
    const __nv_bfloat16* kl = g_qkvl + 1ull * ACT_ELEMS;
    const __nv_bfloat16* vh = g_qkvh + 2ull * ACT_ELEMS;
    const __nv_bfloat16* vl = g_qkvl + 2ull * ACT_ELEMS;
    const size_t krow = (size_t)(b * NN + kt * 64);
    #pragma unroll
    for (int t = 0; t < 2; t++) {
        int chunk = tid + t * 256;
        int r = chunk >> 3, c = chunk & 7;
        size_t g = (krow + r) * DM + h * 64 + c * 8;
        uint32_t d = dst + r * KROWB + c * 16;
        CP16(d,              kh + g);
        CP16(d + TILE9K,     kl + g);
        CP16(d + 2 * TILE9K, vh + g);
        CP16(d + 3 * TILE9K, vl + g);
    }
    const float* bg = bias + (((size_t)(b * NH + h)) * NN + qt * 128) * NN + kt * 64;
    #pragma unroll
    for (int t = 0; t < 8; t++) {
        int chunk = tid + t * 256;
        int r = chunk >> 4, c = chunk & 15;
        CP16(dst + 4 * TILE9K + r * BROWB + c * 16, bg + (size_t)r * NN + c * 4);
    }
}

__global__ __launch_bounds__(256) void attn_mma(const float* __restrict__ bias)
{
    extern __shared__ __align__(16) char sm[];
    const uint32_t sb = smem_u32(sm);
    const int tid = threadIdx.x, lid = tid & 31, wid = tid >> 5;
    const int bh = blockIdx.x;
    const int qt = blockIdx.y;
    const int b = bh >> 4, h = bh & 15;
    const size_t qrow0 = (size_t)(b * NN + qt * 128);

    #pragma unroll
    for (int t = 0; t < 4; t++) {
        int chunk = tid + t * 256;
        int r = chunk >> 3, c = chunk & 7;
        size_t g = (qrow0 + r) * DM + h * 64 + c * 8;
        CP16(sb + Q_OFF + r * KROWB + c * 16, g_qkvh + g);
        CP16(sb + Q_OFF + QTILE + r * KROWB + c * 16, g_qkvl + g);
    }
    attn_load_stage(sb, b, h, qt, 0, tid, bias);
    CP_COMMIT();
    attn_load_stage(sb + STAGE_A, b, h, qt, 1, tid, bias);
    CP_COMMIT();
    CP_WAIT1();
    __syncthreads();

    uint32_t aqh[4][4], aql[4][4];
    {
        const uint32_t qrel = sb + Q_OFF + (uint32_t)(wid * 16 + (lid & 15)) * KROWB
                              + ((lid >> 4) << 4);
        #pragma unroll
        for (int ks = 0; ks < 4; ks++) {
            ldsm_x4(aqh[ks], qrel + ks * 32);
            ldsm_x4(aql[ks], qrel + QTILE + ks * 32);
        }
    }

    float o[8][4];
    #pragma unroll
    for (int j = 0; j < 8; j++)
        #pragma unroll
        for (int e = 0; e < 4; e++) o[j][e] = 0.0f;
    float m0 = -1e30f, m1 = -1e30f, l0 = 0.0f, l1 = 0.0f;

    const int rrow = (lid >> 2);
    const uint32_t krel_lane = (uint32_t)((lid & 7) + ((lid >> 4) << 3)) * KROWB
                               + (((lid >> 3) & 1) << 4);
    const uint32_t vcol_lane = ((lid >> 4) << 4);
    const uint32_t vrow_lane = (uint32_t)(lid & 15) * KROWB;

    for (int kt = 0; kt < 16; kt++) {
        const uint32_t st = sb + (kt & 1) * STAGE_A;
        const uint32_t strel = (kt & 1) * STAGE_A;

        // ---- S = Q K^T : process np pairs, rotate 4 accumulators ----
        float s[8][4];
        #pragma unroll
        for (int j = 0; j < 8; j++)
            #pragma unroll
            for (int e = 0; e < 4; e++) s[j][e] = 0.0f;

        #pragma unroll
        for (int ks = 0; ks < 4; ks++) {
            const uint32_t kbase = st + krel_lane + ks * 32;
            #pragma unroll
            for (int npp = 0; npp < 2; npp++) {
                uint32_t bh0[4], bl0[4], bh1[4], bl1[4];
                ldsm_x4(bh0, kbase + (2 * npp + 0) * 16 * KROWB);
                ldsm_x4(bl0, kbase + TILE9K + (2 * npp + 0) * 16 * KROWB);
                ldsm_x4(bh1, kbase + (2 * npp + 1) * 16 * KROWB);
                ldsm_x4(bl1, kbase + TILE9K + (2 * npp + 1) * 16 * KROWB);
                float* s0 = s[4 * npp + 0];
                float* s1 = s[4 * npp + 1];
                float* s2 = s[4 * npp + 2];
                float* s3 = s[4 * npp + 3];
                mma16816(s0, aqh[ks], bh0 + 0);
                mma16816(s1, aqh[ks], bh0 + 2);
                mma16816(s2, aqh[ks], bh1 + 0);
                mma16816(s3, aqh[ks], bh1 + 2);
                mma16816(s0, aqh[ks], bl0 + 0);
                mma16816(s1, aqh[ks], bl0 + 2);
                mma16816(s2, aqh[ks], bl1 + 0);
                mma16816(s3, aqh[ks], bl1 + 2);
                mma16816(s0, aql[ks], bh0 + 0);
                mma16816(s1, aql[ks], bh0 + 2);
                mma16816(s2, aql[ks], bh1 + 0);
                mma16816(s3, aql[ks], bh1 + 2);
            }
        }

        // ---- + bias ----
        {
            const char* bsm = sm + strel + 4 * TILE9K
                              + (wid * 16 + rrow) * BROWB + (lid & 3) * 8;
            #pragma unroll
            for (int j = 0; j < 8; j++) {
                float2 b0 = *(const float2*)(bsm + j * 32);
                float2 b1 = *(const float2*)(bsm + 8 * BROWB + j * 32);
                s[j][0] += b0.x; s[j][1] += b0.y;
                s[j][2] += b1.x; s[j][3] += b1.y;
            }
        }

        // ---- online softmax ----
        float mx0 = -1e30f, mx1 = -1e30f;
        #pragma unroll
        for (int j = 0; j < 8; j++) {
            mx0 = fmaxf(mx0, fmaxf(s[j][0], s[j][1]));
            mx1 = fmaxf(mx1, fmaxf(s[j][2], s[j][3]));
        }
        mx0 = fmaxf(mx0, __shfl_xor_sync(0xffffffffu, mx0, 1));
        mx0 = fmaxf(mx0, __shfl_xor_sync(0xffffffffu, mx0, 2));
        mx1 = fmaxf(mx1, __shfl_xor_sync(0xffffffffu, mx1, 1));
        mx1 = fmaxf(mx1, __shfl_xor_sync(0xffffffffu, mx1, 2));

        float mn0 = fmaxf(m0, mx0), mn1 = fmaxf(m1, mx1);
        float sc0 = __expf(m0 - mn0), sc1 = __expf(m1 - mn1);
        m0 = mn0; m1 = mn1;

        float rs0 = 0.0f, rs1 = 0.0f;
        #pragma unroll
        for (int j = 0; j < 8; j++) {
            s[j][0] = __expf(s[j][0] - m0);
            s[j][1] = __expf(s[j][1] - m0);
            s[j][2] = __expf(s[j][2] - m1);
            s[j][3] = __expf(s[j][3] - m1);
            rs0 += s[j][0] + s[j][1];
            rs1 += s[j][2] + s[j][3];
        }
        rs0 += __shfl_xor_sync(0xffffffffu, rs0, 1);
        rs0 += __shfl_xor_sync(0xffffffffu, rs0, 2);
        rs1 += __shfl_xor_sync(0xffffffffu, rs1, 1);
        rs1 += __shfl_xor_sync(0xffffffffu, rs1, 2);
        l0 = l0 * sc0 + rs0;
        l1 = l1 * sc1 + rs1;

        #pragma unroll
        for (int j = 0; j < 8; j++) {
            o[j][0] *= sc0; o[j][1] *= sc0;
            o[j][2] *= sc1; o[j][3] *= sc1;
        }

        // ---- pack P -> bf16 hi/lo A-fragments ----
        uint32_t pah[4][4], pal[4][4];
        #pragma unroll
        for (int ks = 0; ks < 4; ks++) {
            split2(s[2 * ks][0],     s[2 * ks][1],     pah[ks][0], pal[ks][0]);
            split2(s[2 * ks][2],     s[2 * ks][3],     pah[ks][1], pal[ks][1]);
            split2(s[2 * ks + 1][0], s[2 * ks + 1][1], pah[ks][2], pal[ks][2]);
            split2(s[2 * ks + 1][2], s[2 * ks + 1][3], pah[ks][3], pal[ks][3]);
        }

        // ---- O += P V : process np pairs, rotate 4 accumulators ----
        #pragma unroll
        for (int ks = 0; ks < 4; ks++) {
            const uint32_t vbase = st + 2 * TILE9K + ks * 16 * KROWB
                                   + vrow_lane + vcol_lane;
            #pragma unroll
            for (int npp = 0; npp < 2; npp++) {
                uint32_t bv0h[4], bv0l[4], bv1h[4], bv1l[4];
                ldsm_x4_t(bv0h, vbase + (2 * npp + 0) * 32);
                ldsm_x4_t(bv0l, vbase + TILE9K + (2 * npp + 0) * 32);
                ldsm_x4_t(bv1h, vbase + (2 * npp + 1) * 32);
                ldsm_x4_t(bv1l, vbase + TILE9K + (2 * npp + 1) * 32);
                float* o0 = o[4 * npp + 0];
                float* o1 = o[4 * npp + 1];
                float* o2 = o[4 * npp + 2];
                float* o3 = o[4 * npp + 3];
                mma16816(o0, pah[ks], bv0h + 0);
                mma16816(o1, pah[ks], bv0h + 2);
                mma16816(o2, pah[ks], bv1h + 0);
                mma16816(o3, pah[ks], bv1h + 2);
                mma16816(o0, pah[ks], bv0l + 0);
                mma16816(o1, pah[ks], bv0l + 2);
                mma16816(o2, pah[ks], bv1l + 0);
                mma16816(o3, pah[ks], bv1l + 2);
                mma16816(o0, pal[ks], bv0h + 0);
                mma16816(o1, pal[ks], bv0h + 2);
                mma16816(o2, pal[ks], bv1h + 0);
                mma16816(o3, pal[ks], bv1h + 2);
            }
        }

        __syncthreads();
        if (kt < 15) {
            if (kt + 2 < 16) {
                attn_load_stage(sb + (kt & 1) * STAGE_A, b, h, qt, kt + 2, tid, bias);
                CP_COMMIT();
                CP_WAIT1();
            } else {
                CP_WAIT0();
            }
            __syncthreads();
        }
    }

    // ---- epilogue -> ctx bf16 hi/lo ----
    const float inv0 = 1.0f / l0, inv1 = 1.0f / l1;
    const size_t grow0 = qrow0 + wid * 16 + rrow;
    #pragma unroll
    for (int j = 0; j < 8; j++) {
        int col = h * 64 + j * 8 + (lid & 3) * 2;
        uint32_t h0, lo0, h1, lo1;
        split2(o[j][0] * inv0, o[j][1] * inv0, h0, lo0);
        split2(o[j][2] * inv1, o[j][3] * inv1, h1, lo1);
        *(uint32_t*)(g_ch + grow0 * DM + col) = h0;
        *(uint32_t*)(g_cl + grow0 * DM + col) = lo0;
        *(uint32_t*)(g_ch + (grow0 + 8) * DM + col) = h1;
        *(uint32_t*)(g_cl + (grow0 + 8) * DM + col) = lo1;
    }
}

// ---------------------------------------------------------------------------
// Launch
// ---------------------------------------------------------------------------
extern "C" void kernel_launch(void* const* d_in, const int* in_sizes, int n_in,
                              void* d_out, int out_size)
{
    const float* queries   = (const float*)d_in[0];
    const float* keys      = (const float*)d_in[1];
    const float* values    = (const float*)d_in[2];
    const float* attn_bias = (const float*)d_in[3];
    const float* Wq = (const float*)d_in[4];
    const float* bq = (const float*)d_in[5];
    const float* Wk = (const float*)d_in[6];
    const float* bk = (const float*)d_in[7];
    const float* Wv = (const float*)d_in[8];
    const float* bv = (const float*)d_in[9];
    const float* Wo = (const float*)d_in[10];
    const float* bo = (const float*)d_in[11];
    float* out = (float*)d_out;

    cudaFuncSetAttribute(attn_mma,
                         cudaFuncAttributeMaxDynamicSharedMemorySize, ATTN_SMEM);
    cudaFuncSetAttribute(qkv_gemm,
                         cudaFuncAttributeMaxDynamicSharedMemorySize, GEMM_SMEM);
    cudaFuncSetAttribute(out_gemm,
                         cudaFuncAttributeMaxDynamicSharedMemorySize, GEMM_SMEM);

    conv_act3<<<dim3(4096, 3), 256>>>(queries, keys, values);
    conv_wt4<<<dim3(32, 32, 4), dim3(32, 8)>>>(Wq, Wk, Wv, Wo);

    qkv_gemm<<<dim3(8, 32, 3), 256, GEMM_SMEM>>>(bq, bk, bv);

    attn_mma<<<dim3(64, 8), 256, ATTN_SMEM>>>(attn_bias);

    out_gemm<<<dim3(8, 32), 256, GEMM_SMEM>>>(bo, out);
}

// round 7
// speedup vs baseline: 1.0366x; 1.0366x over previous
#include <cuda_runtime.h>
#include <cuda_bf16.h>
#include <math.h>
#include <stdint.h>

// Problem constants
#define BB 4
#define NN 1024
#define DM 1024
#define NH 16
#define DK 64

// ---------------------------------------------------------------------------
// Scratch (__device__ globals; allocation-free rule)
// ---------------------------------------------------------------------------
#define ACT_ELEMS (4096 * 1024)
#define W_ELEMS   (1024 * 1024)
__device__ __align__(16) __nv_bfloat16 g_ah[3ull * ACT_ELEMS];
__device__ __align__(16) __nv_bfloat16 g_al[3ull * ACT_ELEMS];
__device__ __align__(16) __nv_bfloat16 g_wh[4ull * W_ELEMS];
__device__ __align__(16) __nv_bfloat16 g_wl[4ull * W_ELEMS];
__device__ __align__(16) __nv_bfloat16 g_qkvh[3ull * ACT_ELEMS];
__device__ __align__(16) __nv_bfloat16 g_qkvl[3ull * ACT_ELEMS];
__device__ __align__(16) __nv_bfloat16 g_ch[ACT_ELEMS], g_cl[ACT_ELEMS];

// ---------------------------------------------------------------------------
// PTX helpers (compute_103-safe)
// ---------------------------------------------------------------------------
__device__ __forceinline__ uint32_t smem_u32(const void* p) {
    uint32_t a;
    asm("{ .reg .u64 t; cvta.to.shared.u64 t, %1; cvt.u32.u64 %0, t; }"
        : "=r"(a) : "l"(p));
    return a;
}

#define CP16(dst, src) \
    asm volatile("cp.async.cg.shared.global [%0], [%1], 16;" \
        :: "r"(dst), "l"(src) : "memory")
#define CP_COMMIT() asm volatile("cp.async.commit_group;" ::: "memory")
#define CP_WAIT1()  asm volatile("cp.async.wait_group 1;" ::: "memory")
#define CP_WAIT0()  asm volatile("cp.async.wait_group 0;" ::: "memory")

__device__ __forceinline__ void ldsm_x4(uint32_t* r, uint32_t addr) {
    asm volatile("ldmatrix.sync.aligned.m8n8.x4.shared.b16 {%0,%1,%2,%3}, [%4];"
        : "=r"(r[0]), "=r"(r[1]), "=r"(r[2]), "=r"(r[3]) : "r"(addr));
}
__device__ __forceinline__ void ldsm_x4_t(uint32_t* r, uint32_t addr) {
    asm volatile("ldmatrix.sync.aligned.m8n8.x4.trans.shared.b16 {%0,%1,%2,%3}, [%4];"
        : "=r"(r[0]), "=r"(r[1]), "=r"(r[2]), "=r"(r[3]) : "r"(addr));
}

__device__ __forceinline__ void mma16816(float* c, const uint32_t* a,
                                         const uint32_t* b) {
    asm volatile(
        "mma.sync.aligned.m16n8k16.row.col.f32.bf16.bf16.f32 "
        "{%0,%1,%2,%3}, {%4,%5,%6,%7}, {%8,%9}, {%0,%1,%2,%3};"
        : "+f"(c[0]), "+f"(c[1]), "+f"(c[2]), "+f"(c[3])
        : "r"(a[0]), "r"(a[1]), "r"(a[2]), "r"(a[3]), "r"(b[0]), "r"(b[1]));
}

__device__ __forceinline__ void split2(float x, float y, uint32_t& h, uint32_t& l) {
    __nv_bfloat16 hx = __float2bfloat16(x), hy = __float2bfloat16(y);
    __nv_bfloat16 lx = __float2bfloat16(x - __bfloat162float(hx));
    __nv_bfloat16 ly = __float2bfloat16(y - __bfloat162float(hy));
    __nv_bfloat162 th(hx, hy), tl(lx, ly);
    h = *(uint32_t*)&th;
    l = *(uint32_t*)&tl;
}

// ---------------------------------------------------------------------------
// Conversions (fused launches)
// ---------------------------------------------------------------------------
__global__ __launch_bounds__(256) void conv_act3(
    const float* __restrict__ q, const float* __restrict__ k,
    const float* __restrict__ v)
{
    const float* X = blockIdx.y == 0 ? q : (blockIdx.y == 1 ? k : v);
    __nv_bfloat16* hi = g_ah + (size_t)blockIdx.y * ACT_ELEMS;
    __nv_bfloat16* lo = g_al + (size_t)blockIdx.y * ACT_ELEMS;
    int e = (blockIdx.x * 256 + threadIdx.x) * 4;
    float4 x = *(const float4*)(X + e);
    float xs[4] = {x.x, x.y, x.z, x.w};
    union { __nv_bfloat16 b[4]; uint2 u; } ph, pl;
    #pragma unroll
    for (int j = 0; j < 4; j++) {
        __nv_bfloat16 h = __float2bfloat16(xs[j]);
        ph.b[j] = h;
        pl.b[j] = __float2bfloat16(xs[j] - __bfloat162float(h));
    }
    *(uint2*)(hi + e) = ph.u;
    *(uint2*)(lo + e) = pl.u;
}

__global__ void conv_wt4(const float* __restrict__ Wq, const float* __restrict__ Wk,
                         const float* __restrict__ Wv, const float* __restrict__ Wo)
{
    __shared__ float t[32][33];
    const int z = blockIdx.z;
    const float* W = z == 0 ? Wq : (z == 1 ? Wk : (z == 2 ? Wv : Wo));
    __nv_bfloat16* hi = g_wh + (size_t)z * W_ELEMS;
    __nv_bfloat16* lo = g_wl + (size_t)z * W_ELEMS;
    int n0 = blockIdx.x * 32, k0 = blockIdx.y * 32;
    int tx = threadIdx.x, ty = threadIdx.y;  // 32 x 8

    #pragma unroll
    for (int j = 0; j < 32; j += 8)
        t[ty + j][tx] = W[(size_t)(k0 + ty + j) * 1024 + n0 + tx];
    __syncthreads();

    #pragma unroll
    for (int j = 0; j < 32; j += 8) {
        int n = n0 + ty + j, k = k0 + tx;
        float x = t[tx][ty + j];
        __nv_bfloat16 h = __float2bfloat16(x);
        __nv_bfloat16 l = __float2bfloat16(x - __bfloat162float(h));
        hi[(size_t)n * 1024 + k] = h;
        lo[(size_t)n * 1024 + k] = l;
    }
}

// ---------------------------------------------------------------------------
// HMMA GEMM body, bf16 hi/lo split (3-term). Round-5 MMA ordering (measured
// faster than interleaved variant).
// ---------------------------------------------------------------------------
#define ROWB 80
#define ARR_B (128 * ROWB)
#define STAGE_B (4 * ARR_B)
#define GEMM_SMEM (2 * STAGE_B)

__device__ __forceinline__ void gemm_load_stage(
    uint32_t dbase, int m0, int n0, int k0, int tid,
    const __nv_bfloat16* Ah, const __nv_bfloat16* Al,
    const __nv_bfloat16* Bh, const __nv_bfloat16* Bl)
{
    int ldc = tid & 3;
    int r0 = tid >> 2;
    #pragma unroll
    for (int h = 0; h < 2; h++) {
        int row = r0 + h * 64;
        uint32_t doff = dbase + row * ROWB + ldc * 16;
        size_t ga = (size_t)(m0 + row) * 1024 + k0 + ldc * 8;
        size_t gb = (size_t)(n0 + row) * 1024 + k0 + ldc * 8;
        CP16(doff,             Ah + ga);
        CP16(doff + ARR_B,     Al + ga);
        CP16(doff + 2 * ARR_B, Bh + gb);
        CP16(doff + 3 * ARR_B, Bl + gb);
    }
}

template <bool OUT_BF16>
__device__ __forceinline__ void gemm_body(
    const __nv_bfloat16* __restrict__ Ah, const __nv_bfloat16* __restrict__ Al,
    const __nv_bfloat16* __restrict__ Bh, const __nv_bfloat16* __restrict__ Bl,
    const float* __restrict__ bias, float* __restrict__ C,
    __nv_bfloat16* __restrict__ Ch, __nv_bfloat16* __restrict__ Cl,
    float scale, int m0, int n0, char* sm)
{
    const uint32_t sb = smem_u32(sm);
    const int tid = threadIdx.x;
    const int lid = tid & 31, wid = tid >> 5;
    const int wm = wid >> 1, wn = wid & 1;

    float acc[2][8][4];
    #pragma unroll
    for (int f = 0; f < 2; f++)
        #pragma unroll
        for (int n = 0; n < 8; n++)
            #pragma unroll
            for (int j = 0; j < 4; j++) acc[f][n][j] = 0.0f;

    const uint32_t a_rel = (uint32_t)(wm * 32 + (lid & 15)) * ROWB + ((lid >> 4) << 4);
    const uint32_t b_rel = (uint32_t)(wn * 64 + (lid & 7) + ((lid >> 4) << 3)) * ROWB
                           + (((lid >> 3) & 1) << 4);

    gemm_load_stage(sb, m0, n0, 0, tid, Ah, Al, Bh, Bl);
    CP_COMMIT();

    for (int c = 0; c < 32; c++) {
        const int s = c & 1;
        if (c < 31) {
            gemm_load_stage(sb + (s ^ 1) * STAGE_B, m0, n0, (c + 1) * 32, tid,
                            Ah, Al, Bh, Bl);
            CP_COMMIT();
            CP_WAIT1();
        } else {
            CP_WAIT0();
        }
        __syncthreads();

        const uint32_t base = sb + s * STAGE_B;
        #pragma unroll
        for (int ks = 0; ks < 2; ks++) {
            const uint32_t koff = ks * 32;
            uint32_t ah[2][4], al[2][4];
            #pragma unroll
            for (int f = 0; f < 2; f++) {
                ldsm_x4(ah[f], base + a_rel + f * 16 * ROWB + koff);
                ldsm_x4(al[f], base + ARR_B + a_rel + f * 16 * ROWB + koff);
            }
            #pragma unroll
            for (int nfp = 0; nfp < 4; nfp++) {
                uint32_t bh[4], bl[4];
                ldsm_x4(bh, base + 2 * ARR_B + b_rel + nfp * 16 * ROWB + koff);
                ldsm_x4(bl, base + 3 * ARR_B + b_rel + nfp * 16 * ROWB + koff);
                #pragma unroll
                for (int f = 0; f < 2; f++) {
                    mma16816(acc[f][nfp * 2 + 0], ah[f], bh + 0);
                    mma16816(acc[f][nfp * 2 + 0], ah[f], bl + 0);
                    mma16816(acc[f][nfp * 2 + 0], al[f], bh + 0);
                    mma16816(acc[f][nfp * 2 + 1], ah[f], bh + 2);
                    mma16816(acc[f][nfp * 2 + 1], ah[f], bl + 2);
                    mma16816(acc[f][nfp * 2 + 1], al[f], bh + 2);
                }
            }
        }
        __syncthreads();
    }

    const int r_base = m0 + wm * 32 + (lid >> 2);
    const int c_lane = (lid & 3) * 2;
    #pragma unroll
    for (int f = 0; f < 2; f++) {
        #pragma unroll
        for (int nf = 0; nf < 8; nf++) {
            int col = n0 + wn * 64 + nf * 8 + c_lane;
            float2 bb = *(const float2*)(bias + col);
            int r0 = r_base + f * 16;
            float* a = acc[f][nf];
            float v0 = (a[0] + bb.x) * scale, v1 = (a[1] + bb.y) * scale;
            float v2 = (a[2] + bb.x) * scale, v3 = (a[3] + bb.y) * scale;
            if (OUT_BF16) {
                uint32_t h0, l0, h1, l1;
                split2(v0, v1, h0, l0);
                split2(v2, v3, h1, l1);
                *(uint32_t*)(Ch + (size_t)r0 * 1024 + col) = h0;
                *(uint32_t*)(Cl + (size_t)r0 * 1024 + col) = l0;
                *(uint32_t*)(Ch + (size_t)(r0 + 8) * 1024 + col) = h1;
                *(uint32_t*)(Cl + (size_t)(r0 + 8) * 1024 + col) = l1;
            } else {
                *(float2*)(C + (size_t)r0 * 1024 + col) = make_float2(v0, v1);
                *(float2*)(C + (size_t)(r0 + 8) * 1024 + col) = make_float2(v2, v3);
            }
        }
    }
}

// Fused QKV projection: grid (8, 32, 3)
__global__ __launch_bounds__(256, 2) void qkv_gemm(
    const float* __restrict__ bq, const float* __restrict__ bk,
    const float* __restrict__ bv)
{
    extern __shared__ __align__(16) char sm[];
    const int z = blockIdx.z;
    const float* bias = z == 0 ? bq : (z == 1 ? bk : bv);
    gemm_body<true>(g_ah + (size_t)z * ACT_ELEMS, g_al + (size_t)z * ACT_ELEMS,
                    g_wh + (size_t)z * W_ELEMS,  g_wl + (size_t)z * W_ELEMS,
                    bias, nullptr,
                    g_qkvh + (size_t)z * ACT_ELEMS, g_qkvl + (size_t)z * ACT_ELEMS,
                    z == 0 ? 0.125f : 1.0f,
                    blockIdx.y * 128, blockIdx.x * 128, sm);
}

// Output projection: grid (8, 32)
__global__ __launch_bounds__(256, 2) void out_gemm(
    const float* __restrict__ bo, float* __restrict__ out)
{
    extern __shared__ __align__(16) char sm[];
    gemm_body<false>(g_ch, g_cl, g_wh + 3ull * W_ELEMS, g_wl + 3ull * W_ELEMS,
                     bo, out, nullptr, nullptr, 1.0f,
                     blockIdx.y * 128, blockIdx.x * 128, sm);
}

// ---------------------------------------------------------------------------
// Tensor-core flash attention, Q tile 128 rows, 256 threads (8 warps).
// Bias loaded via direct LDG (no smem staging) -> smem 110.6KB -> 2 CTAs/SM.
// ---------------------------------------------------------------------------
#define KROWB 144
#define TILE9K (64 * KROWB)            // 9216
#define QTILE (128 * KROWB)            // 18432
#define STAGE_A (4 * TILE9K)           // 36864: Kh,Kl,Vh,Vl
#define Q_OFF (2 * STAGE_A)            // 73728
#define ATTN_SMEM (Q_OFF + 2 * QTILE)  // 110592

__device__ __forceinline__ void attn_load_stage(
    uint32_t dst, int b, int h, int kt, int tid)
{
    const __nv_bfloat16* kh = g_qkvh + 1ull * ACT_ELEMS;
    const __nv_bfloat16* kl = g_qkvl + 1ull * ACT_ELEMS;
    const __nv_bfloat16* vh = g_qkvh + 2ull * ACT_ELEMS;
    const __nv_bfloat16* vl = g_qkvl + 2ull * ACT_ELEMS;
    const size_t krow = (size_t)(b * NN + kt * 64);
    #pragma unroll
    for (int t = 0; t < 2; t++) {
        int chunk = tid + t * 256;
        int r = chunk >> 3, c = chunk & 7;
        size_t g = (krow + r) * DM + h * 64 + c * 8;
        uint32_t d = dst + r * KROWB + c * 16;
        CP16(d,              kh + g);
        CP16(d + TILE9K,     kl + g);
        CP16(d + 2 * TILE9K, vh + g);
        CP16(d + 3 * TILE9K, vl + g);
    }
}

__global__ __launch_bounds__(256, 2) void attn_mma(const float* __restrict__ bias)
{
    extern __shared__ __align__(16) char sm[];
    const uint32_t sb = smem_u32(sm);
    const int tid = threadIdx.x, lid = tid & 31, wid = tid >> 5;
    const int bh = blockIdx.x;
    const int qt = blockIdx.y;
    const int b = bh >> 4, h = bh & 15;
    const size_t qrow0 = (size_t)(b * NN + qt * 128);

    // Q tile hi/lo (128x64) + stage0/stage1 prefetch
    #pragma unroll
    for (int t = 0; t < 4; t++) {
        int chunk = tid + t * 256;
        int r = chunk >> 3, c = chunk & 7;
        size_t g = (qrow0 + r) * DM + h * 64 + c * 8;
        CP16(sb + Q_OFF + r * KROWB + c * 16, g_qkvh + g);
        CP16(sb + Q_OFF + QTILE + r * KROWB + c * 16, g_qkvl + g);
    }
    attn_load_stage(sb, b, h, 0, tid);
    CP_COMMIT();
    attn_load_stage(sb + STAGE_A, b, h, 1, tid);
    CP_COMMIT();
    CP_WAIT1();
    __syncthreads();

    float o[8][4];
    #pragma unroll
    for (int j = 0; j < 8; j++)
        #pragma unroll
        for (int e = 0; e < 4; e++) o[j][e] = 0.0f;
    float m0 = -1e30f, m1 = -1e30f, l0 = 0.0f, l1 = 0.0f;

    const int rrow = (lid >> 2);
    const uint32_t qrel = sb + Q_OFF + (uint32_t)(wid * 16 + (lid & 15)) * KROWB
                          + ((lid >> 4) << 4);
    const uint32_t krel_lane = (uint32_t)((lid & 7) + ((lid >> 4) << 3)) * KROWB
                               + (((lid >> 3) & 1) << 4);
    const uint32_t vcol_lane = ((lid >> 4) << 4);
    const uint32_t vrow_lane = (uint32_t)(lid & 15) * KROWB;

    // per-thread bias base: row (qt*128 + wid*16 + rrow), col lane offset
    const float* bias_pt = bias
        + (((size_t)(b * NH + h)) * NN + qt * 128 + wid * 16 + rrow) * NN
        + (lid & 3) * 2;

    for (int kt = 0; kt < 16; kt++) {
        const uint32_t st = sb + (kt & 1) * STAGE_A;

        // ---- bias LDG for this tile (consumed after S MMAs) ----
        const float* bg = bias_pt + kt * 64;
        float2 bb0[8], bb1[8];
        #pragma unroll
        for (int j = 0; j < 8; j++) {
            bb0[j] = *(const float2*)(bg + j * 8);
            bb1[j] = *(const float2*)(bg + 8 * NN + j * 8);
        }

        // ---- S = Q K^T (Q frags reloaded from smem each ks) ----
        float s[8][4];
        #pragma unroll
        for (int j = 0; j < 8; j++)
            #pragma unroll
            for (int e = 0; e < 4; e++) s[j][e] = 0.0f;

        #pragma unroll
        for (int ks = 0; ks < 4; ks++) {
            uint32_t aqh[4], aql[4];
            ldsm_x4(aqh, qrel + ks * 32);
            ldsm_x4(aql, qrel + QTILE + ks * 32);
            const uint32_t kbase = st + krel_lane + ks * 32;
            #pragma unroll
            for (int np = 0; np < 4; np++) {
                uint32_t bkh[4], bkl[4];
                ldsm_x4(bkh, kbase + np * 16 * KROWB);
                ldsm_x4(bkl, kbase + TILE9K + np * 16 * KROWB);
                mma16816(s[2 * np + 0], aqh, bkh + 0);
                mma16816(s[2 * np + 0], aqh, bkl + 0);
                mma16816(s[2 * np + 0], aql, bkh + 0);
                mma16816(s[2 * np + 1], aqh, bkh + 2);
                mma16816(s[2 * np + 1], aqh, bkl + 2);
                mma16816(s[2 * np + 1], aql, bkh + 2);
            }
        }

        // ---- + bias ----
        #pragma unroll
        for (int j = 0; j < 8; j++) {
            s[j][0] += bb0[j].x; s[j][1] += bb0[j].y;
            s[j][2] += bb1[j].x; s[j][3] += bb1[j].y;
        }

        // ---- online softmax ----
        float mx0 = -1e30f, mx1 = -1e30f;
        #pragma unroll
        for (int j = 0; j < 8; j++) {
            mx0 = fmaxf(mx0, fmaxf(s[j][0], s[j][1]));
            mx1 = fmaxf(mx1, fmaxf(s[j][2], s[j][3]));
        }
        mx0 = fmaxf(mx0, __shfl_xor_sync(0xffffffffu, mx0, 1));
        mx0 = fmaxf(mx0, __shfl_xor_sync(0xffffffffu, mx0, 2));
        mx1 = fmaxf(mx1, __shfl_xor_sync(0xffffffffu, mx1, 1));
        mx1 = fmaxf(mx1, __shfl_xor_sync(0xffffffffu, mx1, 2));

        float mn0 = fmaxf(m0, mx0), mn1 = fmaxf(m1, mx1);
        float sc0 = __expf(m0 - mn0), sc1 = __expf(m1 - mn1);
        m0 = mn0; m1 = mn1;

        float rs0 = 0.0f, rs1 = 0.0f;
        #pragma unroll
        for (int j = 0; j < 8; j++) {
            s[j][0] = __expf(s[j][0] - m0);
            s[j][1] = __expf(s[j][1] - m0);
            s[j][2] = __expf(s[j][2] - m1);
            s[j][3] = __expf(s[j][3] - m1);
            rs0 += s[j][0] + s[j][1];
            rs1 += s[j][2] + s[j][3];
        }
        rs0 += __shfl_xor_sync(0xffffffffu, rs0, 1);
        rs0 += __shfl_xor_sync(0xffffffffu, rs0, 2);
        rs1 += __shfl_xor_sync(0xffffffffu, rs1, 1);
        rs1 += __shfl_xor_sync(0xffffffffu, rs1, 2);
        l0 = l0 * sc0 + rs0;
        l1 = l1 * sc1 + rs1;

        #pragma unroll
        for (int j = 0; j < 8; j++) {
            o[j][0] *= sc0; o[j][1] *= sc0;
            o[j][2] *= sc1; o[j][3] *= sc1;
        }

        // ---- pack P -> bf16 hi/lo A-fragments ----
        uint32_t pah[4][4], pal[4][4];
        #pragma unroll
        for (int ks = 0; ks < 4; ks++) {
            split2(s[2 * ks][0],     s[2 * ks][1],     pah[ks][0], pal[ks][0]);
            split2(s[2 * ks][2],     s[2 * ks][3],     pah[ks][1], pal[ks][1]);
            split2(s[2 * ks + 1][0], s[2 * ks + 1][1], pah[ks][2], pal[ks][2]);
            split2(s[2 * ks + 1][2], s[2 * ks + 1][3], pah[ks][3], pal[ks][3]);
        }

        // ---- O += P V ----
        #pragma unroll
        for (int ks = 0; ks < 4; ks++) {
            const uint32_t vbase = st + 2 * TILE9K + ks * 16 * KROWB
                                   + vrow_lane + vcol_lane;
            #pragma unroll
            for (int np = 0; np < 4; np++) {
                uint32_t bvh[4], bvl[4];
                ldsm_x4_t(bvh, vbase + np * 32);
                ldsm_x4_t(bvl, vbase + TILE9K + np * 32);
                mma16816(o[2 * np + 0], pah[ks], bvh + 0);
                mma16816(o[2 * np + 0], pah[ks], bvl + 0);
                mma16816(o[2 * np + 0], pal[ks], bvh + 0);
                mma16816(o[2 * np + 1], pah[ks], bvh + 2);
                mma16816(o[2 * np + 1], pah[ks], bvl + 2);
                mma16816(o[2 * np + 1], pal[ks], bvh + 2);
            }
        }

        __syncthreads();
        if (kt < 15) {
            if (kt + 2 < 16) {
                attn_load_stage(sb + (kt & 1) * STAGE_A, b, h, kt + 2, tid);
                CP_COMMIT();
                CP_WAIT1();
            } else {
                CP_WAIT0();
            }
            __syncthreads();
        }
    }

    // ---- epilogue -> ctx bf16 hi/lo ----
    const float inv0 = 1.0f / l0, inv1 = 1.0f / l1;
    const size_t grow0 = qrow0 + wid * 16 + rrow;
    #pragma unroll
    for (int j = 0; j < 8; j++) {
        int col = h * 64 + j * 8 + (lid & 3) * 2;
        uint32_t h0, lo0, h1, lo1;
        split2(o[j][0] * inv0, o[j][1] * inv0, h0, lo0);
        split2(o[j][2] * inv1, o[j][3] * inv1, h1, lo1);
        *(uint32_t*)(g_ch + grow0 * DM + col) = h0;
        *(uint32_t*)(g_cl + grow0 * DM + col) = lo0;
        *(uint32_t*)(g_ch + (grow0 + 8) * DM + col) = h1;
        *(uint32_t*)(g_cl + (grow0 + 8) * DM + col) = lo1;
    }
}

// ---------------------------------------------------------------------------
// Launch
// ---------------------------------------------------------------------------
extern "C" void kernel_launch(void* const* d_in, const int* in_sizes, int n_in,
                              void* d_out, int out_size)
{
    const float* queries   = (const float*)d_in[0];
    const float* keys      = (const float*)d_in[1];
    const float* values    = (const float*)d_in[2];
    const float* attn_bias = (const float*)d_in[3];
    const float* Wq = (const float*)d_in[4];
    const float* bq = (const float*)d_in[5];
    const float* Wk = (const float*)d_in[6];
    const float* bk = (const float*)d_in[7];
    const float* Wv = (const float*)d_in[8];
    const float* bv = (const float*)d_in[9];
    const float* Wo = (const float*)d_in[10];
    const float* bo = (const float*)d_in[11];
    float* out = (float*)d_out;

    cudaFuncSetAttribute(attn_mma,
                         cudaFuncAttributeMaxDynamicSharedMemorySize, ATTN_SMEM);
    cudaFuncSetAttribute(qkv_gemm,
                         cudaFuncAttributeMaxDynamicSharedMemorySize, GEMM_SMEM);
    cudaFuncSetAttribute(out_gemm,
                         cudaFuncAttributeMaxDynamicSharedMemorySize, GEMM_SMEM);

    conv_act3<<<dim3(4096, 3), 256>>>(queries, keys, values);
    conv_wt4<<<dim3(32, 32, 4), dim3(32, 8)>>>(Wq, Wk, Wv, Wo);

    qkv_gemm<<<dim3(8, 32, 3), 256, GEMM_SMEM>>>(bq, bk, bv);

    attn_mma<<<dim3(64, 8), 256, ATTN_SMEM>>>(attn_bias);

    out_gemm<<<dim3(8, 32), 256, GEMM_SMEM>>>(bo, out);
}

// round 8
// speedup vs baseline: 1.0733x; 1.0353x over previous
#include <cuda_runtime.h>
#include <cuda_bf16.h>
#include <cuda_fp16.h>
#include <math.h>
#include <stdint.h>

// Problem constants
#define BB 4
#define NN 1024
#define DM 1024
#define NH 16
#define DK 64
#define LOG2E 1.4426950408889634f

// ---------------------------------------------------------------------------
// Scratch (__device__ globals; allocation-free rule)
// ---------------------------------------------------------------------------
#define ACT_ELEMS (4096 * 1024)
#define W_ELEMS   (1024 * 1024)
__device__ __align__(16) __nv_bfloat16 g_ah[3ull * ACT_ELEMS];
__device__ __align__(16) __nv_bfloat16 g_al[3ull * ACT_ELEMS];
__device__ __align__(16) __nv_bfloat16 g_wh[4ull * W_ELEMS];
__device__ __align__(16) __nv_bfloat16 g_wl[4ull * W_ELEMS];
// slot 0=Q (bf16), 1=K (bf16), 2=V (fp16 bits)
__device__ __align__(16) __nv_bfloat16 g_qkvh[3ull * ACT_ELEMS];
__device__ __align__(16) __nv_bfloat16 g_qkvl[3ull * ACT_ELEMS];
__device__ __align__(16) __nv_bfloat16 g_ch[ACT_ELEMS], g_cl[ACT_ELEMS];

// ---------------------------------------------------------------------------
// PTX helpers (compute_103-safe)
// ---------------------------------------------------------------------------
__device__ __forceinline__ uint32_t smem_u32(const void* p) {
    uint32_t a;
    asm("{ .reg .u64 t; cvta.to.shared.u64 t, %1; cvt.u32.u64 %0, t; }"
        : "=r"(a) : "l"(p));
    return a;
}

#define CP16(dst, src) \
    asm volatile("cp.async.cg.shared.global [%0], [%1], 16;" \
        :: "r"(dst), "l"(src) : "memory")
#define CP_COMMIT() asm volatile("cp.async.commit_group;" ::: "memory")
#define CP_WAIT1()  asm volatile("cp.async.wait_group 1;" ::: "memory")
#define CP_WAIT0()  asm volatile("cp.async.wait_group 0;" ::: "memory")

__device__ __forceinline__ void ldsm_x4(uint32_t* r, uint32_t addr) {
    asm volatile("ldmatrix.sync.aligned.m8n8.x4.shared.b16 {%0,%1,%2,%3}, [%4];"
        : "=r"(r[0]), "=r"(r[1]), "=r"(r[2]), "=r"(r[3]) : "r"(addr));
}
__device__ __forceinline__ void ldsm_x4_t(uint32_t* r, uint32_t addr) {
    asm volatile("ldmatrix.sync.aligned.m8n8.x4.trans.shared.b16 {%0,%1,%2,%3}, [%4];"
        : "=r"(r[0]), "=r"(r[1]), "=r"(r[2]), "=r"(r[3]) : "r"(addr));
}

__device__ __forceinline__ void mma16816(float* c, const uint32_t* a,
                                         const uint32_t* b) {
    asm volatile(
        "mma.sync.aligned.m16n8k16.row.col.f32.bf16.bf16.f32 "
        "{%0,%1,%2,%3}, {%4,%5,%6,%7}, {%8,%9}, {%0,%1,%2,%3};"
        : "+f"(c[0]), "+f"(c[1]), "+f"(c[2]), "+f"(c[3])
        : "r"(a[0]), "r"(a[1]), "r"(a[2]), "r"(a[3]), "r"(b[0]), "r"(b[1]));
}
__device__ __forceinline__ void mma16816h(float* c, const uint32_t* a,
                                          const uint32_t* b) {
    asm volatile(
        "mma.sync.aligned.m16n8k16.row.col.f32.f16.f16.f32 "
        "{%0,%1,%2,%3}, {%4,%5,%6,%7}, {%8,%9}, {%0,%1,%2,%3};"
        : "+f"(c[0]), "+f"(c[1]), "+f"(c[2]), "+f"(c[3])
        : "r"(a[0]), "r"(a[1]), "r"(a[2]), "r"(a[3]), "r"(b[0]), "r"(b[1]));
}

__device__ __forceinline__ float ex2(float x) {
    float r; asm("ex2.approx.f32 %0, %1;" : "=f"(r) : "f"(x)); return r;
}

// fast bf16 hi/lo split of a float pair (lo = x in low half)
__device__ __forceinline__ void split2(float x, float y, uint32_t& h, uint32_t& l) {
    asm("cvt.rn.bf16x2.f32 %0, %1, %2;" : "=r"(h) : "f"(y), "f"(x));
    float hx = __uint_as_float(h << 16);
    float hy = __uint_as_float(h & 0xFFFF0000u);
    float lx = x - hx, ly = y - hy;
    asm("cvt.rn.bf16x2.f32 %0, %1, %2;" : "=r"(l) : "f"(ly), "f"(lx));
}
// fp16 hi/lo split of a float pair
__device__ __forceinline__ void split2h(float x, float y, uint32_t& h, uint32_t& l) {
    asm("cvt.rn.f16x2.f32 %0, %1, %2;" : "=r"(h) : "f"(y), "f"(x));
    __half2 hh = *(__half2*)&h;
    float hx = __half2float(__low2half(hh)), hy = __half2float(__high2half(hh));
    float lx = x - hx, ly = y - hy;
    asm("cvt.rn.f16x2.f32 %0, %1, %2;" : "=r"(l) : "f"(ly), "f"(lx));
}

// ---------------------------------------------------------------------------
// Conversions (fused launches)
// ---------------------------------------------------------------------------
__global__ __launch_bounds__(256) void conv_act3(
    const float* __restrict__ q, const float* __restrict__ k,
    const float* __restrict__ v)
{
    const float* X = blockIdx.y == 0 ? q : (blockIdx.y == 1 ? k : v);
    __nv_bfloat16* hi = g_ah + (size_t)blockIdx.y * ACT_ELEMS;
    __nv_bfloat16* lo = g_al + (size_t)blockIdx.y * ACT_ELEMS;
    int e = (blockIdx.x * 256 + threadIdx.x) * 4;
    float4 x = *(const float4*)(X + e);
    uint32_t h0, l0, h1, l1;
    split2(x.x, x.y, h0, l0);
    split2(x.z, x.w, h1, l1);
    *(uint2*)(hi + e) = make_uint2(h0, h1);
    *(uint2*)(lo + e) = make_uint2(l0, l1);
}

__global__ void conv_wt4(const float* __restrict__ Wq, const float* __restrict__ Wk,
                         const float* __restrict__ Wv, const float* __restrict__ Wo)
{
    __shared__ float t[32][33];
    const int z = blockIdx.z;
    const float* W = z == 0 ? Wq : (z == 1 ? Wk : (z == 2 ? Wv : Wo));
    __nv_bfloat16* hi = g_wh + (size_t)z * W_ELEMS;
    __nv_bfloat16* lo = g_wl + (size_t)z * W_ELEMS;
    int n0 = blockIdx.x * 32, k0 = blockIdx.y * 32;
    int tx = threadIdx.x, ty = threadIdx.y;  // 32 x 8

    #pragma unroll
    for (int j = 0; j < 32; j += 8)
        t[ty + j][tx] = W[(size_t)(k0 + ty + j) * 1024 + n0 + tx];
    __syncthreads();

    #pragma unroll
    for (int j = 0; j < 32; j += 8) {
        int n = n0 + ty + j, k = k0 + tx;
        float x = t[tx][ty + j];
        __nv_bfloat16 h = __float2bfloat16(x);
        __nv_bfloat16 l = __float2bfloat16(x - __bfloat162float(h));
        hi[(size_t)n * 1024 + k] = h;
        lo[(size_t)n * 1024 + k] = l;
    }
}

// ---------------------------------------------------------------------------
// HMMA GEMM body, bf16 hi/lo split (3-term), Round-5 ordering.
// ---------------------------------------------------------------------------
#define ROWB 80
#define ARR_B (128 * ROWB)
#define STAGE_B (4 * ARR_B)
#define GEMM_SMEM (2 * STAGE_B)

__device__ __forceinline__ void gemm_load_stage(
    uint32_t dbase, int m0, int n0, int k0, int tid,
    const __nv_bfloat16* Ah, const __nv_bfloat16* Al,
    const __nv_bfloat16* Bh, const __nv_bfloat16* Bl)
{
    int ldc = tid & 3;
    int r0 = tid >> 2;
    #pragma unroll
    for (int h = 0; h < 2; h++) {
        int row = r0 + h * 64;
        uint32_t doff = dbase + row * ROWB + ldc * 16;
        size_t ga = (size_t)(m0 + row) * 1024 + k0 + ldc * 8;
        size_t gb = (size_t)(n0 + row) * 1024 + k0 + ldc * 8;
        CP16(doff,             Ah + ga);
        CP16(doff + ARR_B,     Al + ga);
        CP16(doff + 2 * ARR_B, Bh + gb);
        CP16(doff + 3 * ARR_B, Bl + gb);
    }
}

template <bool OUT_16>
__device__ __forceinline__ void gemm_body(
    const __nv_bfloat16* __restrict__ Ah, const __nv_bfloat16* __restrict__ Al,
    const __nv_bfloat16* __restrict__ Bh, const __nv_bfloat16* __restrict__ Bl,
    const float* __restrict__ bias, float* __restrict__ C,
    __nv_bfloat16* __restrict__ Ch, __nv_bfloat16* __restrict__ Cl,
    float scale, int m0, int n0, char* sm, bool v_fp16)
{
    const uint32_t sb = smem_u32(sm);
    const int tid = threadIdx.x;
    const int lid = tid & 31, wid = tid >> 5;
    const int wm = wid >> 1, wn = wid & 1;

    float acc[2][8][4];
    #pragma unroll
    for (int f = 0; f < 2; f++)
        #pragma unroll
        for (int n = 0; n < 8; n++)
            #pragma unroll
            for (int j = 0; j < 4; j++) acc[f][n][j] = 0.0f;

    const uint32_t a_rel = (uint32_t)(wm * 32 + (lid & 15)) * ROWB + ((lid >> 4) << 4);
    const uint32_t b_rel = (uint32_t)(wn * 64 + (lid & 7) + ((lid >> 4) << 3)) * ROWB
                           + (((lid >> 3) & 1) << 4);

    gemm_load_stage(sb, m0, n0, 0, tid, Ah, Al, Bh, Bl);
    CP_COMMIT();

    for (int c = 0; c < 32; c++) {
        const int s = c & 1;
        if (c < 31) {
            gemm_load_stage(sb + (s ^ 1) * STAGE_B, m0, n0, (c + 1) * 32, tid,
                            Ah, Al, Bh, Bl);
            CP_COMMIT();
            CP_WAIT1();
        } else {
            CP_WAIT0();
        }
        __syncthreads();

        const uint32_t base = sb + s * STAGE_B;
        #pragma unroll
        for (int ks = 0; ks < 2; ks++) {
            const uint32_t koff = ks * 32;
            uint32_t ah[2][4], al[2][4];
            #pragma unroll
            for (int f = 0; f < 2; f++) {
                ldsm_x4(ah[f], base + a_rel + f * 16 * ROWB + koff);
                ldsm_x4(al[f], base + ARR_B + a_rel + f * 16 * ROWB + koff);
            }
            #pragma unroll
            for (int nfp = 0; nfp < 4; nfp++) {
                uint32_t bh[4], bl[4];
                ldsm_x4(bh, base + 2 * ARR_B + b_rel + nfp * 16 * ROWB + koff);
                ldsm_x4(bl, base + 3 * ARR_B + b_rel + nfp * 16 * ROWB + koff);
                #pragma unroll
                for (int f = 0; f < 2; f++) {
                    mma16816(acc[f][nfp * 2 + 0], ah[f], bh + 0);
                    mma16816(acc[f][nfp * 2 + 0], ah[f], bl + 0);
                    mma16816(acc[f][nfp * 2 + 0], al[f], bh + 0);
                    mma16816(acc[f][nfp * 2 + 1], ah[f], bh + 2);
                    mma16816(acc[f][nfp * 2 + 1], ah[f], bl + 2);
                    mma16816(acc[f][nfp * 2 + 1], al[f], bh + 2);
                }
            }
        }
        __syncthreads();
    }

    const int r_base = m0 + wm * 32 + (lid >> 2);
    const int c_lane = (lid & 3) * 2;
    #pragma unroll
    for (int f = 0; f < 2; f++) {
        #pragma unroll
        for (int nf = 0; nf < 8; nf++) {
            int col = n0 + wn * 64 + nf * 8 + c_lane;
            float2 bb = *(const float2*)(bias + col);
            int r0 = r_base + f * 16;
            float* a = acc[f][nf];
            float v0 = (a[0] + bb.x) * scale, v1 = (a[1] + bb.y) * scale;
            float v2 = (a[2] + bb.x) * scale, v3 = (a[3] + bb.y) * scale;
            if (OUT_16) {
                uint32_t h0, l0, h1, l1;
                if (v_fp16) {
                    split2h(v0, v1, h0, l0);
                    split2h(v2, v3, h1, l1);
                } else {
                    split2(v0, v1, h0, l0);
                    split2(v2, v3, h1, l1);
                }
                *(uint32_t*)(Ch + (size_t)r0 * 1024 + col) = h0;
                *(uint32_t*)(Cl + (size_t)r0 * 1024 + col) = l0;
                *(uint32_t*)(Ch + (size_t)(r0 + 8) * 1024 + col) = h1;
                *(uint32_t*)(Cl + (size_t)(r0 + 8) * 1024 + col) = l1;
            } else {
                *(float2*)(C + (size_t)r0 * 1024 + col) = make_float2(v0, v1);
                *(float2*)(C + (size_t)(r0 + 8) * 1024 + col) = make_float2(v2, v3);
            }
        }
    }
}

// Fused QKV projection: grid (8, 32, 3). Q scaled by D_KEY^-0.5 * log2(e).
__global__ __launch_bounds__(256, 2) void qkv_gemm(
    const float* __restrict__ bq, const float* __restrict__ bk,
    const float* __restrict__ bv)
{
    extern __shared__ __align__(16) char sm[];
    const int z = blockIdx.z;
    const float* bias = z == 0 ? bq : (z == 1 ? bk : bv);
    gemm_body<true>(g_ah + (size_t)z * ACT_ELEMS, g_al + (size_t)z * ACT_ELEMS,
                    g_wh + (size_t)z * W_ELEMS,  g_wl + (size_t)z * W_ELEMS,
                    bias, nullptr,
                    g_qkvh + (size_t)z * ACT_ELEMS, g_qkvl + (size_t)z * ACT_ELEMS,
                    z == 0 ? 0.125f * LOG2E : 1.0f,
                    blockIdx.y * 128, blockIdx.x * 128, sm,
                    z == 2 /* V as fp16 hi/lo */);
}

// Output projection: grid (8, 32)
__global__ __launch_bounds__(256, 2) void out_gemm(
    const float* __restrict__ bo, float* __restrict__ out)
{
    extern __shared__ __align__(16) char sm[];
    gemm_body<false>(g_ch, g_cl, g_wh + 3ull * W_ELEMS, g_wl + 3ull * W_ELEMS,
                     bo, out, nullptr, nullptr, 1.0f,
                     blockIdx.y * 128, blockIdx.x * 128, sm, false);
}

// ---------------------------------------------------------------------------
// Tensor-core flash attention (exp2 domain).
// Q/K bf16 hi/lo 3-term; V fp16 hi/lo + P fp16 -> 2-term PV.
// Q tile 128 rows, 256 threads, bias via direct LDG, 2 CTAs/SM.
// ---------------------------------------------------------------------------
#define KROWB 144
#define TILE9K (64 * KROWB)            // 9216
#define QTILE (128 * KROWB)            // 18432
#define STAGE_A (4 * TILE9K)           // 36864: Kh,Kl,Vh,Vl
#define Q_OFF (2 * STAGE_A)            // 73728
#define ATTN_SMEM (Q_OFF + 2 * QTILE)  // 110592

__device__ __forceinline__ void attn_load_stage(
    uint32_t dst, int b, int h, int kt, int tid)
{
    const __nv_bfloat16* kh = g_qkvh + 1ull * ACT_ELEMS;
    const __nv_bfloat16* kl = g_qkvl + 1ull * ACT_ELEMS;
    const __nv_bfloat16* vh = g_qkvh + 2ull * ACT_ELEMS;  // fp16 bits
    const __nv_bfloat16* vl = g_qkvl + 2ull * ACT_ELEMS;  // fp16 bits
    const size_t krow = (size_t)(b * NN + kt * 64);
    #pragma unroll
    for (int t = 0; t < 2; t++) {
        int chunk = tid + t * 256;
        int r = chunk >> 3, c = chunk & 7;
        size_t g = (krow + r) * DM + h * 64 + c * 8;
        uint32_t d = dst + r * KROWB + c * 16;
        CP16(d,              kh + g);
        CP16(d + TILE9K,     kl + g);
        CP16(d + 2 * TILE9K, vh + g);
        CP16(d + 3 * TILE9K, vl + g);
    }
}

__global__ __launch_bounds__(256, 2) void attn_mma(const float* __restrict__ bias)
{
    extern __shared__ __align__(16) char sm[];
    const uint32_t sb = smem_u32(sm);
    const int tid = threadIdx.x, lid = tid & 31, wid = tid >> 5;
    const int bh = blockIdx.x;
    const int qt = blockIdx.y;
    const int b = bh >> 4, h = bh & 15;
    const size_t qrow0 = (size_t)(b * NN + qt * 128);

    #pragma unroll
    for (int t = 0; t < 4; t++) {
        int chunk = tid + t * 256;
        int r = chunk >> 3, c = chunk & 7;
        size_t g = (qrow0 + r) * DM + h * 64 + c * 8;
        CP16(sb + Q_OFF + r * KROWB + c * 16, g_qkvh + g);
        CP16(sb + Q_OFF + QTILE + r * KROWB + c * 16, g_qkvl + g);
    }
    attn_load_stage(sb, b, h, 0, tid);
    CP_COMMIT();
    attn_load_stage(sb + STAGE_A, b, h, 1, tid);
    CP_COMMIT();
    CP_WAIT1();
    __syncthreads();

    float o[8][4];
    #pragma unroll
    for (int j = 0; j < 8; j++)
        #pragma unroll
        for (int e = 0; e < 4; e++) o[j][e] = 0.0f;
    float m0 = -1e30f, m1 = -1e30f, l0 = 0.0f, l1 = 0.0f;

    const int rrow = (lid >> 2);
    const uint32_t qrel = sb + Q_OFF + (uint32_t)(wid * 16 + (lid & 15)) * KROWB
                          + ((lid >> 4) << 4);
    const uint32_t krel_lane = (uint32_t)((lid & 7) + ((lid >> 4) << 3)) * KROWB
                               + (((lid >> 3) & 1) << 4);
    const uint32_t vcol_lane = ((lid >> 4) << 4);
    const uint32_t vrow_lane = (uint32_t)(lid & 15) * KROWB;

    const float* bias_pt = bias
        + (((size_t)(b * NH + h)) * NN + qt * 128 + wid * 16 + rrow) * NN
        + (lid & 3) * 2;

    for (int kt = 0; kt < 16; kt++) {
        const uint32_t st = sb + (kt & 1) * STAGE_A;

        // ---- bias LDG for this tile ----
        const float* bg = bias_pt + kt * 64;
        float2 bb0[8], bb1[8];
        #pragma unroll
        for (int j = 0; j < 8; j++) {
            bb0[j] = *(const float2*)(bg + j * 8);
            bb1[j] = *(const float2*)(bg + 8 * NN + j * 8);
        }

        // ---- S = Q K^T (bf16 3-term; S already in log2 domain via Q scale) ----
        float s[8][4];
        #pragma unroll
        for (int j = 0; j < 8; j++)
            #pragma unroll
            for (int e = 0; e < 4; e++) s[j][e] = 0.0f;

        #pragma unroll
        for (int ks = 0; ks < 4; ks++) {
            uint32_t aqh[4], aql[4];
            ldsm_x4(aqh, qrel + ks * 32);
            ldsm_x4(aql, qrel + QTILE + ks * 32);
            const uint32_t kbase = st + krel_lane + ks * 32;
            #pragma unroll
            for (int np = 0; np < 4; np++) {
                uint32_t bkh[4], bkl[4];
                ldsm_x4(bkh, kbase + np * 16 * KROWB);
                ldsm_x4(bkl, kbase + TILE9K + np * 16 * KROWB);
                mma16816(s[2 * np + 0], aqh, bkh + 0);
                mma16816(s[2 * np + 0], aqh, bkl + 0);
                mma16816(s[2 * np + 0], aql, bkh + 0);
                mma16816(s[2 * np + 1], aqh, bkh + 2);
                mma16816(s[2 * np + 1], aqh, bkl + 2);
                mma16816(s[2 * np + 1], aql, bkh + 2);
            }
        }

        // ---- + bias * log2(e) ----
        #pragma unroll
        for (int j = 0; j < 8; j++) {
            s[j][0] = fmaf(bb0[j].x, LOG2E, s[j][0]);
            s[j][1] = fmaf(bb0[j].y, LOG2E, s[j][1]);
            s[j][2] = fmaf(bb1[j].x, LOG2E, s[j][2]);
            s[j][3] = fmaf(bb1[j].y, LOG2E, s[j][3]);
        }

        // ---- online softmax (base-2) ----
        float mx0 = -1e30f, mx1 = -1e30f;
        #pragma unroll
        for (int j = 0; j < 8; j++) {
            mx0 = fmaxf(mx0, fmaxf(s[j][0], s[j][1]));
            mx1 = fmaxf(mx1, fmaxf(s[j][2], s[j][3]));
        }
        mx0 = fmaxf(mx0, __shfl_xor_sync(0xffffffffu, mx0, 1));
        mx0 = fmaxf(mx0, __shfl_xor_sync(0xffffffffu, mx0, 2));
        mx1 = fmaxf(mx1, __shfl_xor_sync(0xffffffffu, mx1, 1));
        mx1 = fmaxf(mx1, __shfl_xor_sync(0xffffffffu, mx1, 2));

        float mn0 = fmaxf(m0, mx0), mn1 = fmaxf(m1, mx1);
        float sc0 = ex2(m0 - mn0), sc1 = ex2(m1 - mn1);
        m0 = mn0; m1 = mn1;

        float rs0 = 0.0f, rs1 = 0.0f;
        #pragma unroll
        for (int j = 0; j < 8; j++) {
            s[j][0] = ex2(s[j][0] - m0);
            s[j][1] = ex2(s[j][1] - m0);
            s[j][2] = ex2(s[j][2] - m1);
            s[j][3] = ex2(s[j][3] - m1);
            rs0 += s[j][0] + s[j][1];
            rs1 += s[j][2] + s[j][3];
        }
        rs0 += __shfl_xor_sync(0xffffffffu, rs0, 1);
        rs0 += __shfl_xor_sync(0xffffffffu, rs0, 2);
        rs1 += __shfl_xor_sync(0xffffffffu, rs1, 1);
        rs1 += __shfl_xor_sync(0xffffffffu, rs1, 2);
        l0 = l0 * sc0 + rs0;
        l1 = l1 * sc1 + rs1;

        #pragma unroll
        for (int j = 0; j < 8; j++) {
            o[j][0] *= sc0; o[j][1] *= sc0;
            o[j][2] *= sc1; o[j][3] *= sc1;
        }

        // ---- pack P -> single fp16 A-fragments ----
        uint32_t pf[4][4];
        #pragma unroll
        for (int ks = 0; ks < 4; ks++) {
            asm("cvt.rn.f16x2.f32 %0, %1, %2;" : "=r"(pf[ks][0])
                : "f"(s[2 * ks][1]), "f"(s[2 * ks][0]));
            asm("cvt.rn.f16x2.f32 %0, %1, %2;" : "=r"(pf[ks][1])
                : "f"(s[2 * ks][3]), "f"(s[2 * ks][2]));
            asm("cvt.rn.f16x2.f32 %0, %1, %2;" : "=r"(pf[ks][2])
                : "f"(s[2 * ks + 1][1]), "f"(s[2 * ks + 1][0]));
            asm("cvt.rn.f16x2.f32 %0, %1, %2;" : "=r"(pf[ks][3])
                : "f"(s[2 * ks + 1][3]), "f"(s[2 * ks + 1][2]));
        }

        // ---- O += P V (fp16, 2-term: P*Vh + P*Vl) ----
        #pragma unroll
        for (int ks = 0; ks < 4; ks++) {
            const uint32_t vbase = st + 2 * TILE9K + ks * 16 * KROWB
                                   + vrow_lane + vcol_lane;
            #pragma unroll
            for (int np = 0; np < 4; np++) {
                uint32_t bvh[4], bvl[4];
                ldsm_x4_t(bvh, vbase + np * 32);
                ldsm_x4_t(bvl, vbase + TILE9K + np * 32);
                mma16816h(o[2 * np + 0], pf[ks], bvh + 0);
                mma16816h(o[2 * np + 1], pf[ks], bvh + 2);
                mma16816h(o[2 * np + 0], pf[ks], bvl + 0);
                mma16816h(o[2 * np + 1], pf[ks], bvl + 2);
            }
        }

        __syncthreads();
        if (kt < 15) {
            if (kt + 2 < 16) {
                attn_load_stage(sb + (kt & 1) * STAGE_A, b, h, kt + 2, tid);
                CP_COMMIT();
                CP_WAIT1();
            } else {
                CP_WAIT0();
            }
            __syncthreads();
        }
    }

    // ---- epilogue -> ctx bf16 hi/lo ----
    const float inv0 = 1.0f / l0, inv1 = 1.0f / l1;
    const size_t grow0 = qrow0 + wid * 16 + rrow;
    #pragma unroll
    for (int j = 0; j < 8; j++) {
        int col = h * 64 + j * 8 + (lid & 3) * 2;
        uint32_t h0, lo0, h1, lo1;
        split2(o[j][0] * inv0, o[j][1] * inv0, h0, lo0);
        split2(o[j][2] * inv1, o[j][3] * inv1, h1, lo1);
        *(uint32_t*)(g_ch + grow0 * DM + col) = h0;
        *(uint32_t*)(g_cl + grow0 * DM + col) = lo0;
        *(uint32_t*)(g_ch + (grow0 + 8) * DM + col) = h1;
        *(uint32_t*)(g_cl + (grow0 + 8) * DM + col) = lo1;
    }
}

// ---------------------------------------------------------------------------
// Launch
// ---------------------------------------------------------------------------
extern "C" void kernel_launch(void* const* d_in, const int* in_sizes, int n_in,
                              void* d_out, int out_size)
{
    const float* queries   = (const float*)d_in[0];
    const float* keys      = (const float*)d_in[1];
    const float* values    = (const float*)d_in[2];
    const float* attn_bias = (const float*)d_in[3];
    const float* Wq = (const float*)d_in[4];
    const float* bq = (const float*)d_in[5];
    const float* Wk = (const float*)d_in[6];
    const float* bk = (const float*)d_in[7];
    const float* Wv = (const float*)d_in[8];
    const float* bv = (const float*)d_in[9];
    const float* Wo = (const float*)d_in[10];
    const float* bo = (const float*)d_in[11];
    float* out = (float*)d_out;

    cudaFuncSetAttribute(attn_mma,
                         cudaFuncAttributeMaxDynamicSharedMemorySize, ATTN_SMEM);
    cudaFuncSetAttribute(qkv_gemm,
                         cudaFuncAttributeMaxDynamicSharedMemorySize, GEMM_SMEM);
    cudaFuncSetAttribute(out_gemm,
                         cudaFuncAttributeMaxDynamicSharedMemorySize, GEMM_SMEM);

    conv_act3<<<dim3(4096, 3), 256>>>(queries, keys, values);
    conv_wt4<<<dim3(32, 32, 4), dim3(32, 8)>>>(Wq, Wk, Wv, Wo);

    qkv_gemm<<<dim3(8, 32, 3), 256, GEMM_SMEM>>>(bq, bk, bv);

    attn_mma<<<dim3(64, 8), 256, ATTN_SMEM>>>(attn_bias);

    out_gemm<<<dim3(8, 32), 256, GEMM_SMEM>>>(bo, out);
}

// round 9
// speedup vs baseline: 1.2460x; 1.1610x over previous
#include <cuda_runtime.h>
#include <cuda_bf16.h>
#include <cuda_fp16.h>
#include <math.h>
#include <stdint.h>

// Problem constants
#define BB 4
#define NN 1024
#define DM 1024
#define NH 16
#define DK 64
#define LOG2E 1.4426950408889634f

// ---------------------------------------------------------------------------
// Scratch (__device__ globals; allocation-free rule)
// ---------------------------------------------------------------------------
#define ACT_ELEMS (4096 * 1024)
#define W_ELEMS   (1024 * 1024)
__device__ __align__(16) __nv_bfloat16 g_ah[3ull * ACT_ELEMS];
__device__ __align__(16) __nv_bfloat16 g_al[3ull * ACT_ELEMS];
__device__ __align__(16) __nv_bfloat16 g_wh[4ull * W_ELEMS];   // Wo slot = fp16 bits
__device__ __align__(16) __nv_bfloat16 g_wl[4ull * W_ELEMS];
// slot 0=Q bf16 hi/lo, 1=K bf16 hi/lo, 2=V single fp16 (hi slot only)
__device__ __align__(16) __nv_bfloat16 g_qkvh[3ull * ACT_ELEMS];
__device__ __align__(16) __nv_bfloat16 g_qkvl[3ull * ACT_ELEMS];
__device__ __align__(16) __nv_bfloat16 g_ch[ACT_ELEMS];        // ctx single fp16

// ---------------------------------------------------------------------------
// PTX helpers (compute_103-safe)
// ---------------------------------------------------------------------------
__device__ __forceinline__ uint32_t smem_u32(const void* p) {
    uint32_t a;
    asm("{ .reg .u64 t; cvta.to.shared.u64 t, %1; cvt.u32.u64 %0, t; }"
        : "=r"(a) : "l"(p));
    return a;
}

#define CP16(dst, src) \
    asm volatile("cp.async.cg.shared.global [%0], [%1], 16;" \
        :: "r"(dst), "l"(src) : "memory")
#define CP_COMMIT() asm volatile("cp.async.commit_group;" ::: "memory")
#define CP_WAIT1()  asm volatile("cp.async.wait_group 1;" ::: "memory")
#define CP_WAIT0()  asm volatile("cp.async.wait_group 0;" ::: "memory")

__device__ __forceinline__ void ldsm_x4(uint32_t* r, uint32_t addr) {
    asm volatile("ldmatrix.sync.aligned.m8n8.x4.shared.b16 {%0,%1,%2,%3}, [%4];"
        : "=r"(r[0]), "=r"(r[1]), "=r"(r[2]), "=r"(r[3]) : "r"(addr));
}
__device__ __forceinline__ void ldsm_x4_t(uint32_t* r, uint32_t addr) {
    asm volatile("ldmatrix.sync.aligned.m8n8.x4.trans.shared.b16 {%0,%1,%2,%3}, [%4];"
        : "=r"(r[0]), "=r"(r[1]), "=r"(r[2]), "=r"(r[3]) : "r"(addr));
}

__device__ __forceinline__ void mma16816(float* c, const uint32_t* a,
                                         const uint32_t* b) {
    asm volatile(
        "mma.sync.aligned.m16n8k16.row.col.f32.bf16.bf16.f32 "
        "{%0,%1,%2,%3}, {%4,%5,%6,%7}, {%8,%9}, {%0,%1,%2,%3};"
        : "+f"(c[0]), "+f"(c[1]), "+f"(c[2]), "+f"(c[3])
        : "r"(a[0]), "r"(a[1]), "r"(a[2]), "r"(a[3]), "r"(b[0]), "r"(b[1]));
}
__device__ __forceinline__ void mma16816h(float* c, const uint32_t* a,
                                          const uint32_t* b) {
    asm volatile(
        "mma.sync.aligned.m16n8k16.row.col.f32.f16.f16.f32 "
        "{%0,%1,%2,%3}, {%4,%5,%6,%7}, {%8,%9}, {%0,%1,%2,%3};"
        : "+f"(c[0]), "+f"(c[1]), "+f"(c[2]), "+f"(c[3])
        : "r"(a[0]), "r"(a[1]), "r"(a[2]), "r"(a[3]), "r"(b[0]), "r"(b[1]));
}

__device__ __forceinline__ float ex2(float x) {
    float r; asm("ex2.approx.f32 %0, %1;" : "=f"(r) : "f"(x)); return r;
}
__device__ __forceinline__ uint32_t packf16(float x, float y) {
    uint32_t r;
    asm("cvt.rn.f16x2.f32 %0, %1, %2;" : "=r"(r) : "f"(y), "f"(x));
    return r;
}

// fast bf16 hi/lo split of a float pair
__device__ __forceinline__ void split2(float x, float y, uint32_t& h, uint32_t& l) {
    asm("cvt.rn.bf16x2.f32 %0, %1, %2;" : "=r"(h) : "f"(y), "f"(x));
    float hx = __uint_as_float(h << 16);
    float hy = __uint_as_float(h & 0xFFFF0000u);
    float lx = x - hx, ly = y - hy;
    asm("cvt.rn.bf16x2.f32 %0, %1, %2;" : "=r"(l) : "f"(ly), "f"(lx));
}
// fp16 hi/lo split of a float pair
__device__ __forceinline__ void split2h(float x, float y, uint32_t& h, uint32_t& l) {
    h = packf16(x, y);
    __half2 hh = *(__half2*)&h;
    float hx = __half2float(__low2half(hh)), hy = __half2float(__high2half(hh));
    l = packf16(x - hx, y - hy);
}

// ---------------------------------------------------------------------------
// Conversions
// ---------------------------------------------------------------------------
__global__ __launch_bounds__(256) void conv_act3(
    const float* __restrict__ q, const float* __restrict__ k,
    const float* __restrict__ v)
{
    const float* X = blockIdx.y == 0 ? q : (blockIdx.y == 1 ? k : v);
    __nv_bfloat16* hi = g_ah + (size_t)blockIdx.y * ACT_ELEMS;
    __nv_bfloat16* lo = g_al + (size_t)blockIdx.y * ACT_ELEMS;
    int e = (blockIdx.x * 256 + threadIdx.x) * 4;
    float4 x = *(const float4*)(X + e);
    uint32_t h0, l0, h1, l1;
    split2(x.x, x.y, h0, l0);
    split2(x.z, x.w, h1, l1);
    *(uint2*)(hi + e) = make_uint2(h0, h1);
    *(uint2*)(lo + e) = make_uint2(l0, l1);
}

// Wq/Wk/Wv -> bf16 hi/lo ; Wo -> fp16 hi/lo
__global__ void conv_wt4(const float* __restrict__ Wq, const float* __restrict__ Wk,
                         const float* __restrict__ Wv, const float* __restrict__ Wo)
{
    __shared__ float t[32][33];
    const int z = blockIdx.z;
    const float* W = z == 0 ? Wq : (z == 1 ? Wk : (z == 2 ? Wv : Wo));
    __nv_bfloat16* hi = g_wh + (size_t)z * W_ELEMS;
    __nv_bfloat16* lo = g_wl + (size_t)z * W_ELEMS;
    int n0 = blockIdx.x * 32, k0 = blockIdx.y * 32;
    int tx = threadIdx.x, ty = threadIdx.y;  // 32 x 8

    #pragma unroll
    for (int j = 0; j < 32; j += 8)
        t[ty + j][tx] = W[(size_t)(k0 + ty + j) * 1024 + n0 + tx];
    __syncthreads();

    #pragma unroll
    for (int j = 0; j < 32; j += 8) {
        int n = n0 + ty + j, k = k0 + tx;
        float x = t[tx][ty + j];
        if (z == 3) {
            __half h = __float2half_rn(x);
            __half l = __float2half_rn(x - __half2float(h));
            *(__half*)(hi + (size_t)n * 1024 + k) = h;
            *(__half*)(lo + (size_t)n * 1024 + k) = l;
        } else {
            __nv_bfloat16 h = __float2bfloat16(x);
            __nv_bfloat16 l = __float2bfloat16(x - __bfloat162float(h));
            hi[(size_t)n * 1024 + k] = h;
            lo[(size_t)n * 1024 + k] = l;
        }
    }
}

// ---------------------------------------------------------------------------
// QKV GEMM body, bf16 hi/lo 3-term; epilogue bf16 hi/lo (Q,K) or fp16 single (V)
// ---------------------------------------------------------------------------
#define ROWB 80
#define ARR_B (128 * ROWB)
#define STAGE_B (4 * ARR_B)
#define GEMM_SMEM (2 * STAGE_B)

__device__ __forceinline__ void gemm_load_stage(
    uint32_t dbase, int m0, int n0, int k0, int tid,
    const __nv_bfloat16* Ah, const __nv_bfloat16* Al,
    const __nv_bfloat16* Bh, const __nv_bfloat16* Bl)
{
    int ldc = tid & 3;
    int r0 = tid >> 2;
    #pragma unroll
    for (int h = 0; h < 2; h++) {
        int row = r0 + h * 64;
        uint32_t doff = dbase + row * ROWB + ldc * 16;
        size_t ga = (size_t)(m0 + row) * 1024 + k0 + ldc * 8;
        size_t gb = (size_t)(n0 + row) * 1024 + k0 + ldc * 8;
        CP16(doff,             Ah + ga);
        CP16(doff + ARR_B,     Al + ga);
        CP16(doff + 2 * ARR_B, Bh + gb);
        CP16(doff + 3 * ARR_B, Bl + gb);
    }
}

__global__ __launch_bounds__(256, 2) void qkv_gemm(
    const float* __restrict__ bq, const float* __restrict__ bk,
    const float* __restrict__ bv)
{
    extern __shared__ __align__(16) char sm[];
    const int z = blockIdx.z;
    const float* bias = z == 0 ? bq : (z == 1 ? bk : bv);
    const float scale = z == 0 ? 0.125f * LOG2E : 1.0f;
    const __nv_bfloat16* Ah = g_ah + (size_t)z * ACT_ELEMS;
    const __nv_bfloat16* Al = g_al + (size_t)z * ACT_ELEMS;
    const __nv_bfloat16* Bh = g_wh + (size_t)z * W_ELEMS;
    const __nv_bfloat16* Bl = g_wl + (size_t)z * W_ELEMS;
    __nv_bfloat16* Ch = g_qkvh + (size_t)z * ACT_ELEMS;
    __nv_bfloat16* Cl = g_qkvl + (size_t)z * ACT_ELEMS;
    const int m0 = blockIdx.y * 128, n0 = blockIdx.x * 128;

    const uint32_t sb = smem_u32(sm);
    const int tid = threadIdx.x;
    const int lid = tid & 31, wid = tid >> 5;
    const int wm = wid >> 1, wn = wid & 1;

    float acc[2][8][4];
    #pragma unroll
    for (int f = 0; f < 2; f++)
        #pragma unroll
        for (int n = 0; n < 8; n++)
            #pragma unroll
            for (int j = 0; j < 4; j++) acc[f][n][j] = 0.0f;

    const uint32_t a_rel = (uint32_t)(wm * 32 + (lid & 15)) * ROWB + ((lid >> 4) << 4);
    const uint32_t b_rel = (uint32_t)(wn * 64 + (lid & 7) + ((lid >> 4) << 3)) * ROWB
                           + (((lid >> 3) & 1) << 4);

    gemm_load_stage(sb, m0, n0, 0, tid, Ah, Al, Bh, Bl);
    CP_COMMIT();

    for (int c = 0; c < 32; c++) {
        const int s = c & 1;
        if (c < 31) {
            gemm_load_stage(sb + (s ^ 1) * STAGE_B, m0, n0, (c + 1) * 32, tid,
                            Ah, Al, Bh, Bl);
            CP_COMMIT();
            CP_WAIT1();
        } else {
            CP_WAIT0();
        }
        __syncthreads();

        const uint32_t base = sb + s * STAGE_B;
        #pragma unroll
        for (int ks = 0; ks < 2; ks++) {
            const uint32_t koff = ks * 32;
            uint32_t ah[2][4], al[2][4];
            #pragma unroll
            for (int f = 0; f < 2; f++) {
                ldsm_x4(ah[f], base + a_rel + f * 16 * ROWB + koff);
                ldsm_x4(al[f], base + ARR_B + a_rel + f * 16 * ROWB + koff);
            }
            #pragma unroll
            for (int nfp = 0; nfp < 4; nfp++) {
                uint32_t bh[4], bl[4];
                ldsm_x4(bh, base + 2 * ARR_B + b_rel + nfp * 16 * ROWB + koff);
                ldsm_x4(bl, base + 3 * ARR_B + b_rel + nfp * 16 * ROWB + koff);
                #pragma unroll
                for (int f = 0; f < 2; f++) {
                    mma16816(acc[f][nfp * 2 + 0], ah[f], bh + 0);
                    mma16816(acc[f][nfp * 2 + 0], ah[f], bl + 0);
                    mma16816(acc[f][nfp * 2 + 0], al[f], bh + 0);
                    mma16816(acc[f][nfp * 2 + 1], ah[f], bh + 2);
                    mma16816(acc[f][nfp * 2 + 1], ah[f], bl + 2);
                    mma16816(acc[f][nfp * 2 + 1], al[f], bh + 2);
                }
            }
        }
        __syncthreads();
    }

    const int r_base = m0 + wm * 32 + (lid >> 2);
    const int c_lane = (lid & 3) * 2;
    #pragma unroll
    for (int f = 0; f < 2; f++) {
        #pragma unroll
        for (int nf = 0; nf < 8; nf++) {
            int col = n0 + wn * 64 + nf * 8 + c_lane;
            float2 bb = *(const float2*)(bias + col);
            int r0 = r_base + f * 16;
            float* a = acc[f][nf];
            float v0 = (a[0] + bb.x) * scale, v1 = (a[1] + bb.y) * scale;
            float v2 = (a[2] + bb.x) * scale, v3 = (a[3] + bb.y) * scale;
            if (z == 2) {
                // V: single fp16
                *(uint32_t*)(Ch + (size_t)r0 * 1024 + col) = packf16(v0, v1);
                *(uint32_t*)(Ch + (size_t)(r0 + 8) * 1024 + col) = packf16(v2, v3);
            } else {
                uint32_t h0, l0, h1, l1;
                split2(v0, v1, h0, l0);
                split2(v2, v3, h1, l1);
                *(uint32_t*)(Ch + (size_t)r0 * 1024 + col) = h0;
                *(uint32_t*)(Cl + (size_t)r0 * 1024 + col) = l0;
                *(uint32_t*)(Ch + (size_t)(r0 + 8) * 1024 + col) = h1;
                *(uint32_t*)(Cl + (size_t)(r0 + 8) * 1024 + col) = l1;
            }
        }
    }
}

// ---------------------------------------------------------------------------
// Output projection: A = ctx single fp16, B = Wo fp16 hi/lo, 2-term fp16 MMA.
// ---------------------------------------------------------------------------
#define OSTAGE_B (3 * ARR_B)
#define OGEMM_SMEM (2 * OSTAGE_B)   // 61440

__device__ __forceinline__ void ogemm_load_stage(
    uint32_t dbase, int m0, int n0, int k0, int tid,
    const __nv_bfloat16* A, const __nv_bfloat16* Bh, const __nv_bfloat16* Bl)
{
    int ldc = tid & 3;
    int r0 = tid >> 2;
    #pragma unroll
    for (int h = 0; h < 2; h++) {
        int row = r0 + h * 64;
        uint32_t doff = dbase + row * ROWB + ldc * 16;
        size_t ga = (size_t)(m0 + row) * 1024 + k0 + ldc * 8;
        size_t gb = (size_t)(n0 + row) * 1024 + k0 + ldc * 8;
        CP16(doff,             A + ga);
        CP16(doff + ARR_B,     Bh + gb);
        CP16(doff + 2 * ARR_B, Bl + gb);
    }
}

__global__ __launch_bounds__(256, 2) void out_gemm(
    const float* __restrict__ bo, float* __restrict__ out)
{
    extern __shared__ __align__(16) char sm[];
    const __nv_bfloat16* A  = g_ch;
    const __nv_bfloat16* Bh = g_wh + 3ull * W_ELEMS;
    const __nv_bfloat16* Bl = g_wl + 3ull * W_ELEMS;
    const int m0 = blockIdx.y * 128, n0 = blockIdx.x * 128;

    const uint32_t sb = smem_u32(sm);
    const int tid = threadIdx.x;
    const int lid = tid & 31, wid = tid >> 5;
    const int wm = wid >> 1, wn = wid & 1;

    float acc[2][8][4];
    #pragma unroll
    for (int f = 0; f < 2; f++)
        #pragma unroll
        for (int n = 0; n < 8; n++)
            #pragma unroll
            for (int j = 0; j < 4; j++) acc[f][n][j] = 0.0f;

    const uint32_t a_rel = (uint32_t)(wm * 32 + (lid & 15)) * ROWB + ((lid >> 4) << 4);
    const uint32_t b_rel = (uint32_t)(wn * 64 + (lid & 7) + ((lid >> 4) << 3)) * ROWB
                           + (((lid >> 3) & 1) << 4);

    ogemm_load_stage(sb, m0, n0, 0, tid, A, Bh, Bl);
    CP_COMMIT();

    for (int c = 0; c < 32; c++) {
        const int s = c & 1;
        if (c < 31) {
            ogemm_load_stage(sb + (s ^ 1) * OSTAGE_B, m0, n0, (c + 1) * 32, tid,
                             A, Bh, Bl);
            CP_COMMIT();
            CP_WAIT1();
        } else {
            CP_WAIT0();
        }
        __syncthreads();

        const uint32_t base = sb + s * OSTAGE_B;
        #pragma unroll
        for (int ks = 0; ks < 2; ks++) {
            const uint32_t koff = ks * 32;
            uint32_t a[2][4];
            #pragma unroll
            for (int f = 0; f < 2; f++)
                ldsm_x4(a[f], base + a_rel + f * 16 * ROWB + koff);
            #pragma unroll
            for (int nfp = 0; nfp < 4; nfp++) {
                uint32_t bh[4], bl[4];
                ldsm_x4(bh, base + ARR_B + b_rel + nfp * 16 * ROWB + koff);
                ldsm_x4(bl, base + 2 * ARR_B + b_rel + nfp * 16 * ROWB + koff);
                #pragma unroll
                for (int f = 0; f < 2; f++) {
                    mma16816h(acc[f][nfp * 2 + 0], a[f], bh + 0);
                    mma16816h(acc[f][nfp * 2 + 0], a[f], bl + 0);
                    mma16816h(acc[f][nfp * 2 + 1], a[f], bh + 2);
                    mma16816h(acc[f][nfp * 2 + 1], a[f], bl + 2);
                }
            }
        }
        __syncthreads();
    }

    const int r_base = m0 + wm * 32 + (lid >> 2);
    const int c_lane = (lid & 3) * 2;
    #pragma unroll
    for (int f = 0; f < 2; f++) {
        #pragma unroll
        for (int nf = 0; nf < 8; nf++) {
            int col = n0 + wn * 64 + nf * 8 + c_lane;
            float2 bb = *(const float2*)(bo + col);
            int r0 = r_base + f * 16;
            float* a = acc[f][nf];
            *(float2*)(out + (size_t)r0 * 1024 + col) =
                make_float2(a[0] + bb.x, a[1] + bb.y);
            *(float2*)(out + (size_t)(r0 + 8) * 1024 + col) =
                make_float2(a[2] + bb.x, a[3] + bb.y);
        }
    }
}

// ---------------------------------------------------------------------------
// Tensor-core flash attention (exp2 domain).
// Q/K bf16 hi/lo 3-term; V single fp16, P fp16 -> 1-term PV.
// Q tile 128 rows, 256 threads, bias direct LDG, 2 CTAs/SM (92KB smem).
// ---------------------------------------------------------------------------
#define KROWB 144
#define TILE9K (64 * KROWB)            // 9216
#define QTILE (128 * KROWB)            // 18432
#define STAGE_A (3 * TILE9K)           // 27648: Kh,Kl,V
#define Q_OFF (2 * STAGE_A)            // 55296
#define ATTN_SMEM (Q_OFF + 2 * QTILE)  // 92160

__device__ __forceinline__ void attn_load_stage(
    uint32_t dst, int b, int h, int kt, int tid)
{
    const __nv_bfloat16* kh = g_qkvh + 1ull * ACT_ELEMS;
    const __nv_bfloat16* kl = g_qkvl + 1ull * ACT_ELEMS;
    const __nv_bfloat16* vv = g_qkvh + 2ull * ACT_ELEMS;  // fp16 bits
    const size_t krow = (size_t)(b * NN + kt * 64);
    #pragma unroll
    for (int t = 0; t < 2; t++) {
        int chunk = tid + t * 256;
        int r = chunk >> 3, c = chunk & 7;
        size_t g = (krow + r) * DM + h * 64 + c * 8;
        uint32_t d = dst + r * KROWB + c * 16;
        CP16(d,              kh + g);
        CP16(d + TILE9K,     kl + g);
        CP16(d + 2 * TILE9K, vv + g);
    }
}

__global__ __launch_bounds__(256, 2) void attn_mma(const float* __restrict__ bias)
{
    extern __shared__ __align__(16) char sm[];
    const uint32_t sb = smem_u32(sm);
    const int tid = threadIdx.x, lid = tid & 31, wid = tid >> 5;
    const int bh = blockIdx.x;
    const int qt = blockIdx.y;
    const int b = bh >> 4, h = bh & 15;
    const size_t qrow0 = (size_t)(b * NN + qt * 128);

    #pragma unroll
    for (int t = 0; t < 4; t++) {
        int chunk = tid + t * 256;
        int r = chunk >> 3, c = chunk & 7;
        size_t g = (qrow0 + r) * DM + h * 64 + c * 8;
        CP16(sb + Q_OFF + r * KROWB + c * 16, g_qkvh + g);
        CP16(sb + Q_OFF + QTILE + r * KROWB + c * 16, g_qkvl + g);
    }
    attn_load_stage(sb, b, h, 0, tid);
    CP_COMMIT();
    attn_load_stage(sb + STAGE_A, b, h, 1, tid);
    CP_COMMIT();
    CP_WAIT1();
    __syncthreads();

    float o[8][4];
    #pragma unroll
    for (int j = 0; j < 8; j++)
        #pragma unroll
        for (int e = 0; e < 4; e++) o[j][e] = 0.0f;
    float m0 = -1e30f, m1 = -1e30f, l0 = 0.0f, l1 = 0.0f;

    const int rrow = (lid >> 2);
    const uint32_t qrel = sb + Q_OFF + (uint32_t)(wid * 16 + (lid & 15)) * KROWB
                          + ((lid >> 4) << 4);
    const uint32_t krel_lane = (uint32_t)((lid & 7) + ((lid >> 4) << 3)) * KROWB
                               + (((lid >> 3) & 1) << 4);
    const uint32_t vcol_lane = ((lid >> 4) << 4);
    const uint32_t vrow_lane = (uint32_t)(lid & 15) * KROWB;

    const float* bias_pt = bias
        + (((size_t)(b * NH + h)) * NN + qt * 128 + wid * 16 + rrow) * NN
        + (lid & 3) * 2;

    for (int kt = 0; kt < 16; kt++) {
        const uint32_t st = sb + (kt & 1) * STAGE_A;

        // ---- bias LDG ----
        const float* bg = bias_pt + kt * 64;
        float2 bb0[8], bb1[8];
        #pragma unroll
        for (int j = 0; j < 8; j++) {
            bb0[j] = *(const float2*)(bg + j * 8);
            bb1[j] = *(const float2*)(bg + 8 * NN + j * 8);
        }

        // ---- S = Q K^T (bf16 3-term, log2 domain) ----
        float s[8][4];
        #pragma unroll
        for (int j = 0; j < 8; j++)
            #pragma unroll
            for (int e = 0; e < 4; e++) s[j][e] = 0.0f;

        #pragma unroll
        for (int ks = 0; ks < 4; ks++) {
            uint32_t aqh[4], aql[4];
            ldsm_x4(aqh, qrel + ks * 32);
            ldsm_x4(aql, qrel + QTILE + ks * 32);
            const uint32_t kbase = st + krel_lane + ks * 32;
            #pragma unroll
            for (int np = 0; np < 4; np++) {
                uint32_t bkh[4], bkl[4];
                ldsm_x4(bkh, kbase + np * 16 * KROWB);
                ldsm_x4(bkl, kbase + TILE9K + np * 16 * KROWB);
                mma16816(s[2 * np + 0], aqh, bkh + 0);
                mma16816(s[2 * np + 0], aqh, bkl + 0);
                mma16816(s[2 * np + 0], aql, bkh + 0);
                mma16816(s[2 * np + 1], aqh, bkh + 2);
                mma16816(s[2 * np + 1], aqh, bkl + 2);
                mma16816(s[2 * np + 1], aql, bkh + 2);
            }
        }

        // ---- + bias * log2(e) ----
        #pragma unroll
        for (int j = 0; j < 8; j++) {
            s[j][0] = fmaf(bb0[j].x, LOG2E, s[j][0]);
            s[j][1] = fmaf(bb0[j].y, LOG2E, s[j][1]);
            s[j][2] = fmaf(bb1[j].x, LOG2E, s[j][2]);
            s[j][3] = fmaf(bb1[j].y, LOG2E, s[j][3]);
        }

        // ---- online softmax (base-2) ----
        float mx0 = -1e30f, mx1 = -1e30f;
        #pragma unroll
        for (int j = 0; j < 8; j++) {
            mx0 = fmaxf(mx0, fmaxf(s[j][0], s[j][1]));
            mx1 = fmaxf(mx1, fmaxf(s[j][2], s[j][3]));
        }
        mx0 = fmaxf(mx0, __shfl_xor_sync(0xffffffffu, mx0, 1));
        mx0 = fmaxf(mx0, __shfl_xor_sync(0xffffffffu, mx0, 2));
        mx1 = fmaxf(mx1, __shfl_xor_sync(0xffffffffu, mx1, 1));
        mx1 = fmaxf(mx1, __shfl_xor_sync(0xffffffffu, mx1, 2));

        float mn0 = fmaxf(m0, mx0), mn1 = fmaxf(m1, mx1);
        float sc0 = ex2(m0 - mn0), sc1 = ex2(m1 - mn1);
        m0 = mn0; m1 = mn1;

        float rs0 = 0.0f, rs1 = 0.0f;
        #pragma unroll
        for (int j = 0; j < 8; j++) {
            s[j][0] = ex2(s[j][0] - m0);
            s[j][1] = ex2(s[j][1] - m0);
            s[j][2] = ex2(s[j][2] - m1);
            s[j][3] = ex2(s[j][3] - m1);
            rs0 += s[j][0] + s[j][1];
            rs1 += s[j][2] + s[j][3];
        }
        rs0 += __shfl_xor_sync(0xffffffffu, rs0, 1);
        rs0 += __shfl_xor_sync(0xffffffffu, rs0, 2);
        rs1 += __shfl_xor_sync(0xffffffffu, rs1, 1);
        rs1 += __shfl_xor_sync(0xffffffffu, rs1, 2);
        l0 = l0 * sc0 + rs0;
        l1 = l1 * sc1 + rs1;

        #pragma unroll
        for (int j = 0; j < 8; j++) {
            o[j][0] *= sc0; o[j][1] *= sc0;
            o[j][2] *= sc1; o[j][3] *= sc1;
        }

        // ---- pack P -> fp16 A-fragments ----
        uint32_t pf[4][4];
        #pragma unroll
        for (int ks = 0; ks < 4; ks++) {
            pf[ks][0] = packf16(s[2 * ks][0], s[2 * ks][1]);
            pf[ks][1] = packf16(s[2 * ks][2], s[2 * ks][3]);
            pf[ks][2] = packf16(s[2 * ks + 1][0], s[2 * ks + 1][1]);
            pf[ks][3] = packf16(s[2 * ks + 1][2], s[2 * ks + 1][3]);
        }

        // ---- O += P V (fp16, 1-term) ----
        #pragma unroll
        for (int ks = 0; ks < 4; ks++) {
            const uint32_t vbase = st + 2 * TILE9K + ks * 16 * KROWB
                                   + vrow_lane + vcol_lane;
            #pragma unroll
            for (int np = 0; np < 4; np++) {
                uint32_t bv[4];
                ldsm_x4_t(bv, vbase + np * 32);
                mma16816h(o[2 * np + 0], pf[ks], bv + 0);
                mma16816h(o[2 * np + 1], pf[ks], bv + 2);
            }
        }

        __syncthreads();
        if (kt < 15) {
            if (kt + 2 < 16) {
                attn_load_stage(sb + (kt & 1) * STAGE_A, b, h, kt + 2, tid);
                CP_COMMIT();
                CP_WAIT1();
            } else {
                CP_WAIT0();
            }
            __syncthreads();
        }
    }

    // ---- epilogue -> ctx single fp16 ----
    const float inv0 = 1.0f / l0, inv1 = 1.0f / l1;
    const size_t grow0 = qrow0 + wid * 16 + rrow;
    #pragma unroll
    for (int j = 0; j < 8; j++) {
        int col = h * 64 + j * 8 + (lid & 3) * 2;
        *(uint32_t*)(g_ch + grow0 * DM + col) =
            packf16(o[j][0] * inv0, o[j][1] * inv0);
        *(uint32_t*)(g_ch + (grow0 + 8) * DM + col) =
            packf16(o[j][2] * inv1, o[j][3] * inv1);
    }
}

// ---------------------------------------------------------------------------
// Launch
// ---------------------------------------------------------------------------
extern "C" void kernel_launch(void* const* d_in, const int* in_sizes, int n_in,
                              void* d_out, int out_size)
{
    const float* queries   = (const float*)d_in[0];
    const float* keys      = (const float*)d_in[1];
    const float* values    = (const float*)d_in[2];
    const float* attn_bias = (const float*)d_in[3];
    const float* Wq = (const float*)d_in[4];
    const float* bq = (const float*)d_in[5];
    const float* Wk = (const float*)d_in[6];
    const float* bk = (const float*)d_in[7];
    const float* Wv = (const float*)d_in[8];
    const float* bv = (const float*)d_in[9];
    const float* Wo = (const float*)d_in[10];
    const float* bo = (const float*)d_in[11];
    float* out = (float*)d_out;

    cudaFuncSetAttribute(attn_mma,
                         cudaFuncAttributeMaxDynamicSharedMemorySize, ATTN_SMEM);
    cudaFuncSetAttribute(qkv_gemm,
                         cudaFuncAttributeMaxDynamicSharedMemorySize, GEMM_SMEM);
    cudaFuncSetAttribute(out_gemm,
                         cudaFuncAttributeMaxDynamicSharedMemorySize, OGEMM_SMEM);

    conv_act3<<<dim3(4096, 3), 256>>>(queries, keys, values);
    conv_wt4<<<dim3(32, 32, 4), dim3(32, 8)>>>(Wq, Wk, Wv, Wo);

    qkv_gemm<<<dim3(8, 32, 3), 256, GEMM_SMEM>>>(bq, bk, bv);

    attn_mma<<<dim3(64, 8), 256, ATTN_SMEM>>>(attn_bias);

    out_gemm<<<dim3(8, 32), 256, OGEMM_SMEM>>>(bo, out);
}

// round 10
// speedup vs baseline: 1.2534x; 1.0059x over previous
#include <cuda_runtime.h>
#include <cuda_bf16.h>
#include <cuda_fp16.h>
#include <math.h>
#include <stdint.h>

// Problem constants
#define BB 4
#define NN 1024
#define DM 1024
#define NH 16
#define DK 64
#define LOG2E 1.4426950408889634f

// ---------------------------------------------------------------------------
// Scratch (__device__ globals; allocation-free rule)
// ---------------------------------------------------------------------------
#define ACT_ELEMS (4096 * 1024)
#define W_ELEMS   (1024 * 1024)
__device__ __align__(16) __nv_bfloat16 g_ah[3ull * ACT_ELEMS];  // slot2 = fp16 bits
__device__ __align__(16) __nv_bfloat16 g_al[3ull * ACT_ELEMS];
__device__ __align__(16) __nv_bfloat16 g_wh[4ull * W_ELEMS];    // slots 2,3 = fp16 bits
__device__ __align__(16) __nv_bfloat16 g_wl[4ull * W_ELEMS];
// slot 0=Q bf16 hi/lo, 1=K bf16 hi/lo, 2=V single fp16 (hi slot only)
__device__ __align__(16) __nv_bfloat16 g_qkvh[3ull * ACT_ELEMS];
__device__ __align__(16) __nv_bfloat16 g_qkvl[3ull * ACT_ELEMS];
__device__ __align__(16) __nv_bfloat16 g_ch[ACT_ELEMS];         // ctx single fp16

// ---------------------------------------------------------------------------
// PTX helpers (compute_103-safe)
// ---------------------------------------------------------------------------
__device__ __forceinline__ uint32_t smem_u32(const void* p) {
    uint32_t a;
    asm("{ .reg .u64 t; cvta.to.shared.u64 t, %1; cvt.u32.u64 %0, t; }"
        : "=r"(a) : "l"(p));
    return a;
}

#define CP16(dst, src) \
    asm volatile("cp.async.cg.shared.global [%0], [%1], 16;" \
        :: "r"(dst), "l"(src) : "memory")
#define CP_COMMIT() asm volatile("cp.async.commit_group;" ::: "memory")
#define CP_WAIT1()  asm volatile("cp.async.wait_group 1;" ::: "memory")
#define CP_WAIT0()  asm volatile("cp.async.wait_group 0;" ::: "memory")

__device__ __forceinline__ void ldsm_x4(uint32_t* r, uint32_t addr) {
    asm volatile("ldmatrix.sync.aligned.m8n8.x4.shared.b16 {%0,%1,%2,%3}, [%4];"
        : "=r"(r[0]), "=r"(r[1]), "=r"(r[2]), "=r"(r[3]) : "r"(addr));
}
__device__ __forceinline__ void ldsm_x4_t(uint32_t* r, uint32_t addr) {
    asm volatile("ldmatrix.sync.aligned.m8n8.x4.trans.shared.b16 {%0,%1,%2,%3}, [%4];"
        : "=r"(r[0]), "=r"(r[1]), "=r"(r[2]), "=r"(r[3]) : "r"(addr));
}

__device__ __forceinline__ void mma16816(float* c, const uint32_t* a,
                                         const uint32_t* b) {
    asm volatile(
        "mma.sync.aligned.m16n8k16.row.col.f32.bf16.bf16.f32 "
        "{%0,%1,%2,%3}, {%4,%5,%6,%7}, {%8,%9}, {%0,%1,%2,%3};"
        : "+f"(c[0]), "+f"(c[1]), "+f"(c[2]), "+f"(c[3])
        : "r"(a[0]), "r"(a[1]), "r"(a[2]), "r"(a[3]), "r"(b[0]), "r"(b[1]));
}
__device__ __forceinline__ void mma16816h(float* c, const uint32_t* a,
                                          const uint32_t* b) {
    asm volatile(
        "mma.sync.aligned.m16n8k16.row.col.f32.f16.f16.f32 "
        "{%0,%1,%2,%3}, {%4,%5,%6,%7}, {%8,%9}, {%0,%1,%2,%3};"
        : "+f"(c[0]), "+f"(c[1]), "+f"(c[2]), "+f"(c[3])
        : "r"(a[0]), "r"(a[1]), "r"(a[2]), "r"(a[3]), "r"(b[0]), "r"(b[1]));
}

__device__ __forceinline__ float ex2(float x) {
    float r; asm("ex2.approx.f32 %0, %1;" : "=f"(r) : "f"(x)); return r;
}
__device__ __forceinline__ uint32_t packf16(float x, float y) {
    uint32_t r;
    asm("cvt.rn.f16x2.f32 %0, %1, %2;" : "=r"(r) : "f"(y), "f"(x));
    return r;
}

// fast bf16 hi/lo split of a float pair
__device__ __forceinline__ void split2(float x, float y, uint32_t& h, uint32_t& l) {
    asm("cvt.rn.bf16x2.f32 %0, %1, %2;" : "=r"(h) : "f"(y), "f"(x));
    float hx = __uint_as_float(h << 16);
    float hy = __uint_as_float(h & 0xFFFF0000u);
    float lx = x - hx, ly = y - hy;
    asm("cvt.rn.bf16x2.f32 %0, %1, %2;" : "=r"(l) : "f"(ly), "f"(lx));
}

// ---------------------------------------------------------------------------
// Conversions
// ---------------------------------------------------------------------------
__global__ __launch_bounds__(256) void conv_act3(
    const float* __restrict__ q, const float* __restrict__ k,
    const float* __restrict__ v)
{
    const int z = blockIdx.y;
    const float* X = z == 0 ? q : (z == 1 ? k : v);
    __nv_bfloat16* hi = g_ah + (size_t)z * ACT_ELEMS;
    __nv_bfloat16* lo = g_al + (size_t)z * ACT_ELEMS;
    int e = (blockIdx.x * 256 + threadIdx.x) * 4;
    float4 x = *(const float4*)(X + e);
    if (z == 2) {
        // values -> single fp16
        *(uint2*)(hi + e) = make_uint2(packf16(x.x, x.y), packf16(x.z, x.w));
    } else {
        uint32_t h0, l0, h1, l1;
        split2(x.x, x.y, h0, l0);
        split2(x.z, x.w, h1, l1);
        *(uint2*)(hi + e) = make_uint2(h0, h1);
        *(uint2*)(lo + e) = make_uint2(l0, l1);
    }
}

// Wq/Wk -> bf16 hi/lo ; Wv/Wo -> fp16 hi/lo
__global__ void conv_wt4(const float* __restrict__ Wq, const float* __restrict__ Wk,
                         const float* __restrict__ Wv, const float* __restrict__ Wo)
{
    __shared__ float t[32][33];
    const int z = blockIdx.z;
    const float* W = z == 0 ? Wq : (z == 1 ? Wk : (z == 2 ? Wv : Wo));
    __nv_bfloat16* hi = g_wh + (size_t)z * W_ELEMS;
    __nv_bfloat16* lo = g_wl + (size_t)z * W_ELEMS;
    int n0 = blockIdx.x * 32, k0 = blockIdx.y * 32;
    int tx = threadIdx.x, ty = threadIdx.y;  // 32 x 8

    #pragma unroll
    for (int j = 0; j < 32; j += 8)
        t[ty + j][tx] = W[(size_t)(k0 + ty + j) * 1024 + n0 + tx];
    __syncthreads();

    #pragma unroll
    for (int j = 0; j < 32; j += 8) {
        int n = n0 + ty + j, k = k0 + tx;
        float x = t[tx][ty + j];
        if (z >= 2) {
            __half h = __float2half_rn(x);
            __half l = __float2half_rn(x - __half2float(h));
            *(__half*)(hi + (size_t)n * 1024 + k) = h;
            *(__half*)(lo + (size_t)n * 1024 + k) = l;
        } else {
            __nv_bfloat16 h = __float2bfloat16(x);
            __nv_bfloat16 l = __float2bfloat16(x - __bfloat162float(h));
            hi[(size_t)n * 1024 + k] = h;
            lo[(size_t)n * 1024 + k] = l;
        }
    }
}

// ---------------------------------------------------------------------------
// Q/K projection GEMM, bf16 hi/lo 3-term; epilogue bf16 hi/lo.
// ---------------------------------------------------------------------------
#define ROWB 80
#define ARR_B (128 * ROWB)
#define STAGE_B (4 * ARR_B)
#define GEMM_SMEM (2 * STAGE_B)

__device__ __forceinline__ void gemm_load_stage(
    uint32_t dbase, int m0, int n0, int k0, int tid,
    const __nv_bfloat16* Ah, const __nv_bfloat16* Al,
    const __nv_bfloat16* Bh, const __nv_bfloat16* Bl)
{
    int ldc = tid & 3;
    int r0 = tid >> 2;
    #pragma unroll
    for (int h = 0; h < 2; h++) {
        int row = r0 + h * 64;
        uint32_t doff = dbase + row * ROWB + ldc * 16;
        size_t ga = (size_t)(m0 + row) * 1024 + k0 + ldc * 8;
        size_t gb = (size_t)(n0 + row) * 1024 + k0 + ldc * 8;
        CP16(doff,             Ah + ga);
        CP16(doff + ARR_B,     Al + ga);
        CP16(doff + 2 * ARR_B, Bh + gb);
        CP16(doff + 3 * ARR_B, Bl + gb);
    }
}

__global__ __launch_bounds__(256, 2) void qk_gemm(
    const float* __restrict__ bq, const float* __restrict__ bk)
{
    extern __shared__ __align__(16) char sm[];
    const int z = blockIdx.z;           // 0=Q, 1=K
    const float* bias = z == 0 ? bq : bk;
    const float scale = z == 0 ? 0.125f * LOG2E : 1.0f;
    const __nv_bfloat16* Ah = g_ah + (size_t)z * ACT_ELEMS;
    const __nv_bfloat16* Al = g_al + (size_t)z * ACT_ELEMS;
    const __nv_bfloat16* Bh = g_wh + (size_t)z * W_ELEMS;
    const __nv_bfloat16* Bl = g_wl + (size_t)z * W_ELEMS;
    __nv_bfloat16* Ch = g_qkvh + (size_t)z * ACT_ELEMS;
    __nv_bfloat16* Cl = g_qkvl + (size_t)z * ACT_ELEMS;
    const int m0 = blockIdx.y * 128, n0 = blockIdx.x * 128;

    const uint32_t sb = smem_u32(sm);
    const int tid = threadIdx.x;
    const int lid = tid & 31, wid = tid >> 5;
    const int wm = wid >> 1, wn = wid & 1;

    float acc[2][8][4];
    #pragma unroll
    for (int f = 0; f < 2; f++)
        #pragma unroll
        for (int n = 0; n < 8; n++)
            #pragma unroll
            for (int j = 0; j < 4; j++) acc[f][n][j] = 0.0f;

    const uint32_t a_rel = (uint32_t)(wm * 32 + (lid & 15)) * ROWB + ((lid >> 4) << 4);
    const uint32_t b_rel = (uint32_t)(wn * 64 + (lid & 7) + ((lid >> 4) << 3)) * ROWB
                           + (((lid >> 3) & 1) << 4);

    gemm_load_stage(sb, m0, n0, 0, tid, Ah, Al, Bh, Bl);
    CP_COMMIT();

    for (int c = 0; c < 32; c++) {
        const int s = c & 1;
        if (c < 31) {
            gemm_load_stage(sb + (s ^ 1) * STAGE_B, m0, n0, (c + 1) * 32, tid,
                            Ah, Al, Bh, Bl);
            CP_COMMIT();
            CP_WAIT1();
        } else {
            CP_WAIT0();
        }
        __syncthreads();

        const uint32_t base = sb + s * STAGE_B;
        #pragma unroll
        for (int ks = 0; ks < 2; ks++) {
            const uint32_t koff = ks * 32;
            uint32_t ah[2][4], al[2][4];
            #pragma unroll
            for (int f = 0; f < 2; f++) {
                ldsm_x4(ah[f], base + a_rel + f * 16 * ROWB + koff);
                ldsm_x4(al[f], base + ARR_B + a_rel + f * 16 * ROWB + koff);
            }
            #pragma unroll
            for (int nfp = 0; nfp < 4; nfp++) {
                uint32_t bh[4], bl[4];
                ldsm_x4(bh, base + 2 * ARR_B + b_rel + nfp * 16 * ROWB + koff);
                ldsm_x4(bl, base + 3 * ARR_B + b_rel + nfp * 16 * ROWB + koff);
                #pragma unroll
                for (int f = 0; f < 2; f++) {
                    mma16816(acc[f][nfp * 2 + 0], ah[f], bh + 0);
                    mma16816(acc[f][nfp * 2 + 0], ah[f], bl + 0);
                    mma16816(acc[f][nfp * 2 + 0], al[f], bh + 0);
                    mma16816(acc[f][nfp * 2 + 1], ah[f], bh + 2);
                    mma16816(acc[f][nfp * 2 + 1], ah[f], bl + 2);
                    mma16816(acc[f][nfp * 2 + 1], al[f], bh + 2);
                }
            }
        }
        __syncthreads();
    }

    const int r_base = m0 + wm * 32 + (lid >> 2);
    const int c_lane = (lid & 3) * 2;
    #pragma unroll
    for (int f = 0; f < 2; f++) {
        #pragma unroll
        for (int nf = 0; nf < 8; nf++) {
            int col = n0 + wn * 64 + nf * 8 + c_lane;
            float2 bb = *(const float2*)(bias + col);
            int r0 = r_base + f * 16;
            float* a = acc[f][nf];
            float v0 = (a[0] + bb.x) * scale, v1 = (a[1] + bb.y) * scale;
            float v2 = (a[2] + bb.x) * scale, v3 = (a[3] + bb.y) * scale;
            uint32_t h0, l0, h1, l1;
            split2(v0, v1, h0, l0);
            split2(v2, v3, h1, l1);
            *(uint32_t*)(Ch + (size_t)r0 * 1024 + col) = h0;
            *(uint32_t*)(Cl + (size_t)r0 * 1024 + col) = l0;
            *(uint32_t*)(Ch + (size_t)(r0 + 8) * 1024 + col) = h1;
            *(uint32_t*)(Cl + (size_t)(r0 + 8) * 1024 + col) = l1;
        }
    }
}

// ---------------------------------------------------------------------------
// fp16 2-term GEMM: A single fp16, B fp16 hi/lo. Used for V-projection
// (fp16 out) and output projection (fp32 out + bias).
// ---------------------------------------------------------------------------
#define OSTAGE_B (3 * ARR_B)
#define OGEMM_SMEM (2 * OSTAGE_B)   // 61440

__device__ __forceinline__ void ogemm_load_stage(
    uint32_t dbase, int m0, int n0, int k0, int tid,
    const __nv_bfloat16* A, const __nv_bfloat16* Bh, const __nv_bfloat16* Bl)
{
    int ldc = tid & 3;
    int r0 = tid >> 2;
    #pragma unroll
    for (int h = 0; h < 2; h++) {
        int row = r0 + h * 64;
        uint32_t doff = dbase + row * ROWB + ldc * 16;
        size_t ga = (size_t)(m0 + row) * 1024 + k0 + ldc * 8;
        size_t gb = (size_t)(n0 + row) * 1024 + k0 + ldc * 8;
        CP16(doff,             A + ga);
        CP16(doff + ARR_B,     Bh + gb);
        CP16(doff + 2 * ARR_B, Bl + gb);
    }
}

template <bool OUT_F32>
__global__ __launch_bounds__(256, 2) void h2_gemm(
    const __nv_bfloat16* __restrict__ A,
    const __nv_bfloat16* __restrict__ Bh, const __nv_bfloat16* __restrict__ Bl,
    const float* __restrict__ bias, float* __restrict__ outF,
    __nv_bfloat16* __restrict__ outH)
{
    extern __shared__ __align__(16) char sm[];
    const int m0 = blockIdx.y * 128, n0 = blockIdx.x * 128;

    const uint32_t sb = smem_u32(sm);
    const int tid = threadIdx.x;
    const int lid = tid & 31, wid = tid >> 5;
    const int wm = wid >> 1, wn = wid & 1;

    float acc[2][8][4];
    #pragma unroll
    for (int f = 0; f < 2; f++)
        #pragma unroll
        for (int n = 0; n < 8; n++)
            #pragma unroll
            for (int j = 0; j < 4; j++) acc[f][n][j] = 0.0f;

    const uint32_t a_rel = (uint32_t)(wm * 32 + (lid & 15)) * ROWB + ((lid >> 4) << 4);
    const uint32_t b_rel = (uint32_t)(wn * 64 + (lid & 7) + ((lid >> 4) << 3)) * ROWB
                           + (((lid >> 3) & 1) << 4);

    ogemm_load_stage(sb, m0, n0, 0, tid, A, Bh, Bl);
    CP_COMMIT();

    for (int c = 0; c < 32; c++) {
        const int s = c & 1;
        if (c < 31) {
            ogemm_load_stage(sb + (s ^ 1) * OSTAGE_B, m0, n0, (c + 1) * 32, tid,
                             A, Bh, Bl);
            CP_COMMIT();
            CP_WAIT1();
        } else {
            CP_WAIT0();
        }
        __syncthreads();

        const uint32_t base = sb + s * OSTAGE_B;
        #pragma unroll
        for (int ks = 0; ks < 2; ks++) {
            const uint32_t koff = ks * 32;
            uint32_t a[2][4];
            #pragma unroll
            for (int f = 0; f < 2; f++)
                ldsm_x4(a[f], base + a_rel + f * 16 * ROWB + koff);
            #pragma unroll
            for (int nfp = 0; nfp < 4; nfp++) {
                uint32_t bh[4], bl[4];
                ldsm_x4(bh, base + ARR_B + b_rel + nfp * 16 * ROWB + koff);
                ldsm_x4(bl, base + 2 * ARR_B + b_rel + nfp * 16 * ROWB + koff);
                #pragma unroll
                for (int f = 0; f < 2; f++) {
                    mma16816h(acc[f][nfp * 2 + 0], a[f], bh + 0);
                    mma16816h(acc[f][nfp * 2 + 0], a[f], bl + 0);
                    mma16816h(acc[f][nfp * 2 + 1], a[f], bh + 2);
                    mma16816h(acc[f][nfp * 2 + 1], a[f], bl + 2);
                }
            }
        }
        __syncthreads();
    }

    const int r_base = m0 + wm * 32 + (lid >> 2);
    const int c_lane = (lid & 3) * 2;
    #pragma unroll
    for (int f = 0; f < 2; f++) {
        #pragma unroll
        for (int nf = 0; nf < 8; nf++) {
            int col = n0 + wn * 64 + nf * 8 + c_lane;
            float2 bb = *(const float2*)(bias + col);
            int r0 = r_base + f * 16;
            float* a = acc[f][nf];
            float v0 = a[0] + bb.x, v1 = a[1] + bb.y;
            float v2 = a[2] + bb.x, v3 = a[3] + bb.y;
            if (OUT_F32) {
                *(float2*)(outF + (size_t)r0 * 1024 + col) = make_float2(v0, v1);
                *(float2*)(outF + (size_t)(r0 + 8) * 1024 + col) = make_float2(v2, v3);
            } else {
                *(uint32_t*)(outH + (size_t)r0 * 1024 + col) = packf16(v0, v1);
                *(uint32_t*)(outH + (size_t)(r0 + 8) * 1024 + col) = packf16(v2, v3);
            }
        }
    }
}

// ---------------------------------------------------------------------------
// Tensor-core flash attention (exp2 domain), 32 q-rows per warp.
// Q tile 256 rows, 8 warps x 2 A-fragment groups; K/V fragments register-
// shared across the 2 groups (halves K/V ldsm per output).
// Q/K bf16 hi/lo 3-term; V single fp16, P fp16 1-term PV.
// ---------------------------------------------------------------------------
#define KROWB 144
#define TILE9K (64 * KROWB)            // 9216
#define QTILE (256 * KROWB)            // 36864
#define STAGE_A (3 * TILE9K)           // 27648: Kh,Kl,V
#define Q_OFF (2 * STAGE_A)            // 55296
#define ATTN_SMEM (Q_OFF + 2 * QTILE)  // 129024

__device__ __forceinline__ void attn_load_stage(
    uint32_t dst, int b, int h, int kt, int tid)
{
    const __nv_bfloat16* kh = g_qkvh + 1ull * ACT_ELEMS;
    const __nv_bfloat16* kl = g_qkvl + 1ull * ACT_ELEMS;
    const __nv_bfloat16* vv = g_qkvh + 2ull * ACT_ELEMS;  // fp16 bits
    const size_t krow = (size_t)(b * NN + kt * 64);
    #pragma unroll
    for (int t = 0; t < 2; t++) {
        int chunk = tid + t * 256;
        int r = chunk >> 3, c = chunk & 7;
        size_t g = (krow + r) * DM + h * 64 + c * 8;
        uint32_t d = dst + r * KROWB + c * 16;
        CP16(d,              kh + g);
        CP16(d + TILE9K,     kl + g);
        CP16(d + 2 * TILE9K, vv + g);
    }
}

__global__ __launch_bounds__(256, 1) void attn_mma(const float* __restrict__ bias)
{
    extern __shared__ __align__(16) char sm[];
    const uint32_t sb = smem_u32(sm);
    const int tid = threadIdx.x, lid = tid & 31, wid = tid >> 5;
    const int bh = blockIdx.x;
    const int qt = blockIdx.y;            // 0..3 (256-row q tiles)
    const int b = bh >> 4, h = bh & 15;
    const size_t qrow0 = (size_t)(b * NN + qt * 256);
    const int wq = wid * 32;              // warp's 32 q rows

    // Q tile hi/lo (256x64) + stage0/stage1 prefetch
    #pragma unroll
    for (int t = 0; t < 8; t++) {
        int chunk = tid + t * 256;
        int r = chunk >> 3, c = chunk & 7;
        size_t g = (qrow0 + r) * DM + h * 64 + c * 8;
        CP16(sb + Q_OFF + r * KROWB + c * 16, g_qkvh + g);
        CP16(sb + Q_OFF + QTILE + r * KROWB + c * 16, g_qkvl + g);
    }
    attn_load_stage(sb, b, h, 0, tid);
    CP_COMMIT();
    attn_load_stage(sb + STAGE_A, b, h, 1, tid);
    CP_COMMIT();
    CP_WAIT1();
    __syncthreads();

    float o0[8][4], o1[8][4];
    #pragma unroll
    for (int j = 0; j < 8; j++)
        #pragma unroll
        for (int e = 0; e < 4; e++) { o0[j][e] = 0.0f; o1[j][e] = 0.0f; }
    float m00 = -1e30f, m01 = -1e30f, l00 = 0.0f, l01 = 0.0f;  // group 0
    float m10 = -1e30f, m11 = -1e30f, l10 = 0.0f, l11 = 0.0f;  // group 1

    const int rrow = (lid >> 2);
    const uint32_t qrel0 = sb + Q_OFF + (uint32_t)(wq + (lid & 15)) * KROWB
                           + ((lid >> 4) << 4);
    const uint32_t qrel1 = qrel0 + 16 * KROWB;
    const uint32_t krel_lane = (uint32_t)((lid & 7) + ((lid >> 4) << 3)) * KROWB
                               + (((lid >> 3) & 1) << 4);
    const uint32_t vcol_lane = ((lid >> 4) << 4);
    const uint32_t vrow_lane = (uint32_t)(lid & 15) * KROWB;

    const float* bias_pt0 = bias
        + (((size_t)(b * NH + h)) * NN + qt * 256 + wq + rrow) * NN
        + (lid & 3) * 2;
    const float* bias_pt1 = bias_pt0 + (size_t)16 * NN;

    for (int kt = 0; kt < 16; kt++) {
        const uint32_t st = sb + (kt & 1) * STAGE_A;

        // ---- bias LDG group 0 (early) ----
        const float* bg0 = bias_pt0 + kt * 64;
        float2 ba0[8], bb0[8];
        #pragma unroll
        for (int j = 0; j < 8; j++) {
            ba0[j] = *(const float2*)(bg0 + j * 8);
            bb0[j] = *(const float2*)(bg0 + 8 * NN + j * 8);
        }

        // ---- S = Q K^T for both groups (K frags shared) ----
        float s0[8][4], s1[8][4];
        #pragma unroll
        for (int j = 0; j < 8; j++)
            #pragma unroll
            for (int e = 0; e < 4; e++) { s0[j][e] = 0.0f; s1[j][e] = 0.0f; }

        #pragma unroll
        for (int ks = 0; ks < 4; ks++) {
            uint32_t aqh0[4], aql0[4], aqh1[4], aql1[4];
            ldsm_x4(aqh0, qrel0 + ks * 32);
            ldsm_x4(aql0, qrel0 + QTILE + ks * 32);
            ldsm_x4(aqh1, qrel1 + ks * 32);
            ldsm_x4(aql1, qrel1 + QTILE + ks * 32);
            const uint32_t kbase = st + krel_lane + ks * 32;
            #pragma unroll
            for (int np = 0; np < 4; np++) {
                uint32_t bkh[4], bkl[4];
                ldsm_x4(bkh, kbase + np * 16 * KROWB);
                ldsm_x4(bkl, kbase + TILE9K + np * 16 * KROWB);
                mma16816(s0[2 * np + 0], aqh0, bkh + 0);
                mma16816(s0[2 * np + 0], aqh0, bkl + 0);
                mma16816(s0[2 * np + 0], aql0, bkh + 0);
                mma16816(s0[2 * np + 1], aqh0, bkh + 2);
                mma16816(s0[2 * np + 1], aqh0, bkl + 2);
                mma16816(s0[2 * np + 1], aql0, bkh + 2);
                mma16816(s1[2 * np + 0], aqh1, bkh + 0);
                mma16816(s1[2 * np + 0], aqh1, bkl + 0);
                mma16816(s1[2 * np + 0], aql1, bkh + 0);
                mma16816(s1[2 * np + 1], aqh1, bkh + 2);
                mma16816(s1[2 * np + 1], aqh1, bkl + 2);
                mma16816(s1[2 * np + 1], aql1, bkh + 2);
            }
        }

        // ---- bias LDG group 1 (hidden under group-0 softmax) ----
        const float* bg1 = bias_pt1 + kt * 64;
        float2 ba1[8], bb1[8];
        #pragma unroll
        for (int j = 0; j < 8; j++) {
            ba1[j] = *(const float2*)(bg1 + j * 8);
            bb1[j] = *(const float2*)(bg1 + 8 * NN + j * 8);
        }

        uint32_t pf0[4][4], pf1[4][4];

        // ---- group 0: bias + softmax + pack ----
        {
            #pragma unroll
            for (int j = 0; j < 8; j++) {
                s0[j][0] = fmaf(ba0[j].x, LOG2E, s0[j][0]);
                s0[j][1] = fmaf(ba0[j].y, LOG2E, s0[j][1]);
                s0[j][2] = fmaf(bb0[j].x, LOG2E, s0[j][2]);
                s0[j][3] = fmaf(bb0[j].y, LOG2E, s0[j][3]);
            }
            float mx0 = -1e30f, mx1 = -1e30f;
            #pragma unroll
            for (int j = 0; j < 8; j++) {
                mx0 = fmaxf(mx0, fmaxf(s0[j][0], s0[j][1]));
                mx1 = fmaxf(mx1, fmaxf(s0[j][2], s0[j][3]));
            }
            mx0 = fmaxf(mx0, __shfl_xor_sync(0xffffffffu, mx0, 1));
            mx0 = fmaxf(mx0, __shfl_xor_sync(0xffffffffu, mx0, 2));
            mx1 = fmaxf(mx1, __shfl_xor_sync(0xffffffffu, mx1, 1));
            mx1 = fmaxf(mx1, __shfl_xor_sync(0xffffffffu, mx1, 2));
            float mn0 = fmaxf(m00, mx0), mn1 = fmaxf(m01, mx1);
            float sc0 = ex2(m00 - mn0), sc1 = ex2(m01 - mn1);
            m00 = mn0; m01 = mn1;
            float rs0 = 0.0f, rs1 = 0.0f;
            #pragma unroll
            for (int j = 0; j < 8; j++) {
                s0[j][0] = ex2(s0[j][0] - m00);
                s0[j][1] = ex2(s0[j][1] - m00);
                s0[j][2] = ex2(s0[j][2] - m01);
                s0[j][3] = ex2(s0[j][3] - m01);
                rs0 += s0[j][0] + s0[j][1];
                rs1 += s0[j][2] + s0[j][3];
            }
            rs0 += __shfl_xor_sync(0xffffffffu, rs0, 1);
            rs0 += __shfl_xor_sync(0xffffffffu, rs0, 2);
            rs1 += __shfl_xor_sync(0xffffffffu, rs1, 1);
            rs1 += __shfl_xor_sync(0xffffffffu, rs1, 2);
            l00 = l00 * sc0 + rs0;
            l01 = l01 * sc1 + rs1;
            #pragma unroll
            for (int j = 0; j < 8; j++) {
                o0[j][0] *= sc0; o0[j][1] *= sc0;
                o0[j][2] *= sc1; o0[j][3] *= sc1;
            }
            #pragma unroll
            for (int ks = 0; ks < 4; ks++) {
                pf0[ks][0] = packf16(s0[2 * ks][0], s0[2 * ks][1]);
                pf0[ks][1] = packf16(s0[2 * ks][2], s0[2 * ks][3]);
                pf0[ks][2] = packf16(s0[2 * ks + 1][0], s0[2 * ks + 1][1]);
                pf0[ks][3] = packf16(s0[2 * ks + 1][2], s0[2 * ks + 1][3]);
            }
        }

        // ---- group 1: bias + softmax + pack ----
        {
            #pragma unroll
            for (int j = 0; j < 8; j++) {
                s1[j][0] = fmaf(ba1[j].x, LOG2E, s1[j][0]);
                s1[j][1] = fmaf(ba1[j].y, LOG2E, s1[j][1]);
                s1[j][2] = fmaf(bb1[j].x, LOG2E, s1[j][2]);
                s1[j][3] = fmaf(bb1[j].y, LOG2E, s1[j][3]);
            }
            float mx0 = -1e30f, mx1 = -1e30f;
            #pragma unroll
            for (int j = 0; j < 8; j++) {
                mx0 = fmaxf(mx0, fmaxf(s1[j][0], s1[j][1]));
                mx1 = fmaxf(mx1, fmaxf(s1[j][2], s1[j][3]));
            }
            mx0 = fmaxf(mx0, __shfl_xor_sync(0xffffffffu, mx0, 1));
            mx0 = fmaxf(mx0, __shfl_xor_sync(0xffffffffu, mx0, 2));
            mx1 = fmaxf(mx1, __shfl_xor_sync(0xffffffffu, mx1, 1));
            mx1 = fmaxf(mx1, __shfl_xor_sync(0xffffffffu, mx1, 2));
            float mn0 = fmaxf(m10, mx0), mn1 = fmaxf(m11, mx1);
            float sc0 = ex2(m10 - mn0), sc1 = ex2(m11 - mn1);
            m10 = mn0; m11 = mn1;
            float rs0 = 0.0f, rs1 = 0.0f;
            #pragma unroll
            for (int j = 0; j < 8; j++) {
                s1[j][0] = ex2(s1[j][0] - m10);
                s1[j][1] = ex2(s1[j][1] - m10);
                s1[j][2] = ex2(s1[j][2] - m11);
                s1[j][3] = ex2(s1[j][3] - m11);
                rs0 += s1[j][0] + s1[j][1];
                rs1 += s1[j][2] + s1[j][3];
            }
            rs0 += __shfl_xor_sync(0xffffffffu, rs0, 1);
            rs0 += __shfl_xor_sync(0xffffffffu, rs0, 2);
            rs1 += __shfl_xor_sync(0xffffffffu, rs1, 1);
            rs1 += __shfl_xor_sync(0xffffffffu, rs1, 2);
            l10 = l10 * sc0 + rs0;
            l11 = l11 * sc1 + rs1;
            #pragma unroll
            for (int j = 0; j < 8; j++) {
                o1[j][0] *= sc0; o1[j][1] *= sc0;
                o1[j][2] *= sc1; o1[j][3] *= sc1;
            }
            #pragma unroll
            for (int ks = 0; ks < 4; ks++) {
                pf1[ks][0] = packf16(s1[2 * ks][0], s1[2 * ks][1]);
                pf1[ks][1] = packf16(s1[2 * ks][2], s1[2 * ks][3]);
                pf1[ks][2] = packf16(s1[2 * ks + 1][0], s1[2 * ks + 1][1]);
                pf1[ks][3] = packf16(s1[2 * ks + 1][2], s1[2 * ks + 1][3]);
            }
        }

        // ---- O += P V (V frags shared across groups) ----
        #pragma unroll
        for (int ks = 0; ks < 4; ks++) {
            const uint32_t vbase = st + 2 * TILE9K + ks * 16 * KROWB
                                   + vrow_lane + vcol_lane;
            #pragma unroll
            for (int np = 0; np < 4; np++) {
                uint32_t bv[4];
                ldsm_x4_t(bv, vbase + np * 32);
                mma16816h(o0[2 * np + 0], pf0[ks], bv + 0);
                mma16816h(o0[2 * np + 1], pf0[ks], bv + 2);
                mma16816h(o1[2 * np + 0], pf1[ks], bv + 0);
                mma16816h(o1[2 * np + 1], pf1[ks], bv + 2);
            }
        }

        __syncthreads();
        if (kt < 15) {
            if (kt + 2 < 16) {
                attn_load_stage(sb + (kt & 1) * STAGE_A, b, h, kt + 2, tid);
                CP_COMMIT();
                CP_WAIT1();
            } else {
                CP_WAIT0();
            }
            __syncthreads();
        }
    }

    // ---- epilogue -> ctx single fp16 ----
    {
        const float i00 = 1.0f / l00, i01 = 1.0f / l01;
        const size_t grow = qrow0 + wq + rrow;
        #pragma unroll
        for (int j = 0; j < 8; j++) {
            int col = h * 64 + j * 8 + (lid & 3) * 2;
            *(uint32_t*)(g_ch + grow * DM + col) =
                packf16(o0[j][0] * i00, o0[j][1] * i00);
            *(uint32_t*)(g_ch + (grow + 8) * DM + col) =
                packf16(o0[j][2] * i01, o0[j][3] * i01);
        }
        const float i10 = 1.0f / l10, i11 = 1.0f / l11;
        const size_t grow1 = grow + 16;
        #pragma unroll
        for (int j = 0; j < 8; j++) {
            int col = h * 64 + j * 8 + (lid & 3) * 2;
            *(uint32_t*)(g_ch + grow1 * DM + col) =
                packf16(o1[j][0] * i10, o1[j][1] * i10);
            *(uint32_t*)(g_ch + (grow1 + 8) * DM + col) =
                packf16(o1[j][2] * i11, o1[j][3] * i11);
        }
    }
}

// ---------------------------------------------------------------------------
// Launch
// ---------------------------------------------------------------------------
extern "C" void kernel_launch(void* const* d_in, const int* in_sizes, int n_in,
                              void* d_out, int out_size)
{
    const float* queries   = (const float*)d_in[0];
    const float* keys      = (const float*)d_in[1];
    const float* values    = (const float*)d_in[2];
    const float* attn_bias = (const float*)d_in[3];
    const float* Wq = (const float*)d_in[4];
    const float* bq = (const float*)d_in[5];
    const float* Wk = (const float*)d_in[6];
    const float* bk = (const float*)d_in[7];
    const float* Wv = (const float*)d_in[8];
    const float* bv = (const float*)d_in[9];
    const float* Wo = (const float*)d_in[10];
    const float* bo = (const float*)d_in[11];
    float* out = (float*)d_out;

    __nv_bfloat16 *ah, *wh, *wl, *qkvh, *ch;
    cudaGetSymbolAddress((void**)&ah,   g_ah);
    cudaGetSymbolAddress((void**)&wh,   g_wh);
    cudaGetSymbolAddress((void**)&wl,   g_wl);
    cudaGetSymbolAddress((void**)&qkvh, g_qkvh);
    cudaGetSymbolAddress((void**)&ch,   g_ch);

    cudaFuncSetAttribute(attn_mma,
                         cudaFuncAttributeMaxDynamicSharedMemorySize, ATTN_SMEM);
    cudaFuncSetAttribute(qk_gemm,
                         cudaFuncAttributeMaxDynamicSharedMemorySize, GEMM_SMEM);
    cudaFuncSetAttribute(h2_gemm<false>,
                         cudaFuncAttributeMaxDynamicSharedMemorySize, OGEMM_SMEM);
    cudaFuncSetAttribute(h2_gemm<true>,
                         cudaFuncAttributeMaxDynamicSharedMemorySize, OGEMM_SMEM);

    conv_act3<<<dim3(4096, 3), 256>>>(queries, keys, values);
    conv_wt4<<<dim3(32, 32, 4), dim3(32, 8)>>>(Wq, Wk, Wv, Wo);

    // Q and K projections (bf16 3-term)
    qk_gemm<<<dim3(8, 32, 2), 256, GEMM_SMEM>>>(bq, bk);
    // V projection (fp16 2-term) -> single fp16
    h2_gemm<false><<<dim3(8, 32), 256, OGEMM_SMEM>>>(
        ah + 2ull * ACT_ELEMS, wh + 2ull * W_ELEMS, wl + 2ull * W_ELEMS,
        bv, nullptr, qkvh + 2ull * ACT_ELEMS);

    attn_mma<<<dim3(64, 4), 256, ATTN_SMEM>>>(attn_bias);

    // Output projection (fp16 2-term) -> fp32
    h2_gemm<true><<<dim3(8, 32), 256, OGEMM_SMEM>>>(
        ch, wh + 3ull * W_ELEMS, wl + 3ull * W_ELEMS, bo, out, nullptr);
}

// round 11
// speedup vs baseline: 1.3414x; 1.0702x over previous
#include <cuda_runtime.h>
#include <cuda_bf16.h>
#include <cuda_fp16.h>
#include <math.h>
#include <stdint.h>

// Problem constants
#define BB 4
#define NN 1024
#define DM 1024
#define NH 16
#define DK 64
#define LOG2E 1.4426950408889634f

// ---------------------------------------------------------------------------
// Scratch (__device__ globals; allocation-free rule)
// ---------------------------------------------------------------------------
#define ACT_ELEMS (4096 * 1024)
#define W_ELEMS   (1024 * 1024)
__device__ __align__(16) __nv_bfloat16 g_ah[3ull * ACT_ELEMS];  // slot2 = fp16 bits
__device__ __align__(16) __nv_bfloat16 g_al[3ull * ACT_ELEMS];
__device__ __align__(16) __nv_bfloat16 g_wh[4ull * W_ELEMS];    // slots 2,3 = fp16 bits
__device__ __align__(16) __nv_bfloat16 g_wl[4ull * W_ELEMS];
// slot 0=Q bf16 hi/lo, 1=K bf16 hi/lo, 2=V single fp16 (hi slot only)
__device__ __align__(16) __nv_bfloat16 g_qkvh[3ull * ACT_ELEMS];
__device__ __align__(16) __nv_bfloat16 g_qkvl[3ull * ACT_ELEMS];
__device__ __align__(16) __nv_bfloat16 g_ch[ACT_ELEMS];         // ctx single fp16

// ---------------------------------------------------------------------------
// PTX helpers (compute_103-safe)
// ---------------------------------------------------------------------------
__device__ __forceinline__ uint32_t smem_u32(const void* p) {
    uint32_t a;
    asm("{ .reg .u64 t; cvta.to.shared.u64 t, %1; cvt.u32.u64 %0, t; }"
        : "=r"(a) : "l"(p));
    return a;
}

#define CP16(dst, src) \
    asm volatile("cp.async.cg.shared.global [%0], [%1], 16;" \
        :: "r"(dst), "l"(src) : "memory")
#define CP_COMMIT() asm volatile("cp.async.commit_group;" ::: "memory")
#define CP_WAIT1()  asm volatile("cp.async.wait_group 1;" ::: "memory")
#define CP_WAIT0()  asm volatile("cp.async.wait_group 0;" ::: "memory")

__device__ __forceinline__ void ldsm_x4(uint32_t* r, uint32_t addr) {
    asm volatile("ldmatrix.sync.aligned.m8n8.x4.shared.b16 {%0,%1,%2,%3}, [%4];"
        : "=r"(r[0]), "=r"(r[1]), "=r"(r[2]), "=r"(r[3]) : "r"(addr));
}
__device__ __forceinline__ void ldsm_x4_t(uint32_t* r, uint32_t addr) {
    asm volatile("ldmatrix.sync.aligned.m8n8.x4.trans.shared.b16 {%0,%1,%2,%3}, [%4];"
        : "=r"(r[0]), "=r"(r[1]), "=r"(r[2]), "=r"(r[3]) : "r"(addr));
}

__device__ __forceinline__ void mma16816(float* c, const uint32_t* a,
                                         const uint32_t* b) {
    asm volatile(
        "mma.sync.aligned.m16n8k16.row.col.f32.bf16.bf16.f32 "
        "{%0,%1,%2,%3}, {%4,%5,%6,%7}, {%8,%9}, {%0,%1,%2,%3};"
        : "+f"(c[0]), "+f"(c[1]), "+f"(c[2]), "+f"(c[3])
        : "r"(a[0]), "r"(a[1]), "r"(a[2]), "r"(a[3]), "r"(b[0]), "r"(b[1]));
}
__device__ __forceinline__ void mma16816h(float* c, const uint32_t* a,
                                          const uint32_t* b) {
    asm volatile(
        "mma.sync.aligned.m16n8k16.row.col.f32.f16.f16.f32 "
        "{%0,%1,%2,%3}, {%4,%5,%6,%7}, {%8,%9}, {%0,%1,%2,%3};"
        : "+f"(c[0]), "+f"(c[1]), "+f"(c[2]), "+f"(c[3])
        : "r"(a[0]), "r"(a[1]), "r"(a[2]), "r"(a[3]), "r"(b[0]), "r"(b[1]));
}

__device__ __forceinline__ float ex2(float x) {
    float r; asm("ex2.approx.f32 %0, %1;" : "=f"(r) : "f"(x)); return r;
}
__device__ __forceinline__ uint32_t packf16(float x, float y) {
    uint32_t r;
    asm("cvt.rn.f16x2.f32 %0, %1, %2;" : "=r"(r) : "f"(y), "f"(x));
    return r;
}

// fast bf16 hi/lo split of a float pair
__device__ __forceinline__ void split2(float x, float y, uint32_t& h, uint32_t& l) {
    asm("cvt.rn.bf16x2.f32 %0, %1, %2;" : "=r"(h) : "f"(y), "f"(x));
    float hx = __uint_as_float(h << 16);
    float hy = __uint_as_float(h & 0xFFFF0000u);
    float lx = x - hx, ly = y - hy;
    asm("cvt.rn.bf16x2.f32 %0, %1, %2;" : "=r"(l) : "f"(ly), "f"(lx));
}

// ---------------------------------------------------------------------------
// Conversions
// ---------------------------------------------------------------------------
__global__ __launch_bounds__(256) void conv_act3(
    const float* __restrict__ q, const float* __restrict__ k,
    const float* __restrict__ v)
{
    const int z = blockIdx.y;
    const float* X = z == 0 ? q : (z == 1 ? k : v);
    __nv_bfloat16* hi = g_ah + (size_t)z * ACT_ELEMS;
    __nv_bfloat16* lo = g_al + (size_t)z * ACT_ELEMS;
    int e = (blockIdx.x * 256 + threadIdx.x) * 4;
    float4 x = *(const float4*)(X + e);
    if (z == 2) {
        *(uint2*)(hi + e) = make_uint2(packf16(x.x, x.y), packf16(x.z, x.w));
    } else {
        uint32_t h0, l0, h1, l1;
        split2(x.x, x.y, h0, l0);
        split2(x.z, x.w, h1, l1);
        *(uint2*)(hi + e) = make_uint2(h0, h1);
        *(uint2*)(lo + e) = make_uint2(l0, l1);
    }
}

// Wq/Wk -> bf16 hi/lo ; Wv -> fp16 single ; Wo -> fp16 hi/lo
__global__ void conv_wt4(const float* __restrict__ Wq, const float* __restrict__ Wk,
                         const float* __restrict__ Wv, const float* __restrict__ Wo)
{
    __shared__ float t[32][33];
    const int z = blockIdx.z;
    const float* W = z == 0 ? Wq : (z == 1 ? Wk : (z == 2 ? Wv : Wo));
    __nv_bfloat16* hi = g_wh + (size_t)z * W_ELEMS;
    __nv_bfloat16* lo = g_wl + (size_t)z * W_ELEMS;
    int n0 = blockIdx.x * 32, k0 = blockIdx.y * 32;
    int tx = threadIdx.x, ty = threadIdx.y;  // 32 x 8

    #pragma unroll
    for (int j = 0; j < 32; j += 8)
        t[ty + j][tx] = W[(size_t)(k0 + ty + j) * 1024 + n0 + tx];
    __syncthreads();

    #pragma unroll
    for (int j = 0; j < 32; j += 8) {
        int n = n0 + ty + j, k = k0 + tx;
        float x = t[tx][ty + j];
        if (z == 2) {
            *(__half*)(hi + (size_t)n * 1024 + k) = __float2half_rn(x);
        } else if (z == 3) {
            __half h = __float2half_rn(x);
            __half l = __float2half_rn(x - __half2float(h));
            *(__half*)(hi + (size_t)n * 1024 + k) = h;
            *(__half*)(lo + (size_t)n * 1024 + k) = l;
        } else {
            __nv_bfloat16 h = __float2bfloat16(x);
            __nv_bfloat16 l = __float2bfloat16(x - __bfloat162float(h));
            hi[(size_t)n * 1024 + k] = h;
            lo[(size_t)n * 1024 + k] = l;
        }
    }
}

// ---------------------------------------------------------------------------
// Q/K projection GEMM, bf16 hi/lo 3-term (unchanged 2-stage baseline).
// ---------------------------------------------------------------------------
#define ROWB 80
#define ARR_B (128 * ROWB)
#define STAGE_B (4 * ARR_B)
#define GEMM_SMEM (2 * STAGE_B)

__device__ __forceinline__ void gemm_load_stage(
    uint32_t dbase, int m0, int n0, int k0, int tid,
    const __nv_bfloat16* Ah, const __nv_bfloat16* Al,
    const __nv_bfloat16* Bh, const __nv_bfloat16* Bl)
{
    int ldc = tid & 3;
    int r0 = tid >> 2;
    #pragma unroll
    for (int h = 0; h < 2; h++) {
        int row = r0 + h * 64;
        uint32_t doff = dbase + row * ROWB + ldc * 16;
        size_t ga = (size_t)(m0 + row) * 1024 + k0 + ldc * 8;
        size_t gb = (size_t)(n0 + row) * 1024 + k0 + ldc * 8;
        CP16(doff,             Ah + ga);
        CP16(doff + ARR_B,     Al + ga);
        CP16(doff + 2 * ARR_B, Bh + gb);
        CP16(doff + 3 * ARR_B, Bl + gb);
    }
}

__global__ __launch_bounds__(256, 2) void qk_gemm(
    const float* __restrict__ bq, const float* __restrict__ bk)
{
    extern __shared__ __align__(16) char sm[];
    const int z = blockIdx.z;           // 0=Q, 1=K
    const float* bias = z == 0 ? bq : bk;
    const float scale = z == 0 ? 0.125f * LOG2E : 1.0f;
    const __nv_bfloat16* Ah = g_ah + (size_t)z * ACT_ELEMS;
    const __nv_bfloat16* Al = g_al + (size_t)z * ACT_ELEMS;
    const __nv_bfloat16* Bh = g_wh + (size_t)z * W_ELEMS;
    const __nv_bfloat16* Bl = g_wl + (size_t)z * W_ELEMS;
    __nv_bfloat16* Ch = g_qkvh + (size_t)z * ACT_ELEMS;
    __nv_bfloat16* Cl = g_qkvl + (size_t)z * ACT_ELEMS;
    const int m0 = blockIdx.y * 128, n0 = blockIdx.x * 128;

    const uint32_t sb = smem_u32(sm);
    const int tid = threadIdx.x;
    const int lid = tid & 31, wid = tid >> 5;
    const int wm = wid >> 1, wn = wid & 1;

    float acc[2][8][4];
    #pragma unroll
    for (int f = 0; f < 2; f++)
        #pragma unroll
        for (int n = 0; n < 8; n++)
            #pragma unroll
            for (int j = 0; j < 4; j++) acc[f][n][j] = 0.0f;

    const uint32_t a_rel = (uint32_t)(wm * 32 + (lid & 15)) * ROWB + ((lid >> 4) << 4);
    const uint32_t b_rel = (uint32_t)(wn * 64 + (lid & 7) + ((lid >> 4) << 3)) * ROWB
                           + (((lid >> 3) & 1) << 4);

    gemm_load_stage(sb, m0, n0, 0, tid, Ah, Al, Bh, Bl);
    CP_COMMIT();

    for (int c = 0; c < 32; c++) {
        const int s = c & 1;
        if (c < 31) {
            gemm_load_stage(sb + (s ^ 1) * STAGE_B, m0, n0, (c + 1) * 32, tid,
                            Ah, Al, Bh, Bl);
            CP_COMMIT();
            CP_WAIT1();
        } else {
            CP_WAIT0();
        }
        __syncthreads();

        const uint32_t base = sb + s * STAGE_B;
        #pragma unroll
        for (int ks = 0; ks < 2; ks++) {
            const uint32_t koff = ks * 32;
            uint32_t ah[2][4], al[2][4];
            #pragma unroll
            for (int f = 0; f < 2; f++) {
                ldsm_x4(ah[f], base + a_rel + f * 16 * ROWB + koff);
                ldsm_x4(al[f], base + ARR_B + a_rel + f * 16 * ROWB + koff);
            }
            #pragma unroll
            for (int nfp = 0; nfp < 4; nfp++) {
                uint32_t bh[4], bl[4];
                ldsm_x4(bh, base + 2 * ARR_B + b_rel + nfp * 16 * ROWB + koff);
                ldsm_x4(bl, base + 3 * ARR_B + b_rel + nfp * 16 * ROWB + koff);
                #pragma unroll
                for (int f = 0; f < 2; f++) {
                    mma16816(acc[f][nfp * 2 + 0], ah[f], bh + 0);
                    mma16816(acc[f][nfp * 2 + 0], ah[f], bl + 0);
                    mma16816(acc[f][nfp * 2 + 0], al[f], bh + 0);
                    mma16816(acc[f][nfp * 2 + 1], ah[f], bh + 2);
                    mma16816(acc[f][nfp * 2 + 1], ah[f], bl + 2);
                    mma16816(acc[f][nfp * 2 + 1], al[f], bh + 2);
                }
            }
        }
        __syncthreads();
    }

    const int r_base = m0 + wm * 32 + (lid >> 2);
    const int c_lane = (lid & 3) * 2;
    #pragma unroll
    for (int f = 0; f < 2; f++) {
        #pragma unroll
        for (int nf = 0; nf < 8; nf++) {
            int col = n0 + wn * 64 + nf * 8 + c_lane;
            float2 bb = *(const float2*)(bias + col);
            int r0 = r_base + f * 16;
            float* a = acc[f][nf];
            float v0 = (a[0] + bb.x) * scale, v1 = (a[1] + bb.y) * scale;
            float v2 = (a[2] + bb.x) * scale, v3 = (a[3] + bb.y) * scale;
            uint32_t h0, l0, h1, l1;
            split2(v0, v1, h0, l0);
            split2(v2, v3, h1, l1);
            *(uint32_t*)(Ch + (size_t)r0 * 1024 + col) = h0;
            *(uint32_t*)(Cl + (size_t)r0 * 1024 + col) = l0;
            *(uint32_t*)(Ch + (size_t)(r0 + 8) * 1024 + col) = h1;
            *(uint32_t*)(Cl + (size_t)(r0 + 8) * 1024 + col) = l1;
        }
    }
}

// ---------------------------------------------------------------------------
// fp16 GEMM, NTERMS B-arrays (1 = single, 2 = hi/lo), 3-stage ring with
// a single __syncthreads per k-chunk (anti-convoy structure).
// ---------------------------------------------------------------------------
template <int NTERMS>
__device__ __forceinline__ void h_load_stage(
    uint32_t dbase, int m0, int n0, int k0, int tid,
    const __nv_bfloat16* A, const __nv_bfloat16* Bh, const __nv_bfloat16* Bl)
{
    int ldc = tid & 3;
    int r0 = tid >> 2;
    #pragma unroll
    for (int h = 0; h < 2; h++) {
        int row = r0 + h * 64;
        uint32_t doff = dbase + row * ROWB + ldc * 16;
        size_t ga = (size_t)(m0 + row) * 1024 + k0 + ldc * 8;
        size_t gb = (size_t)(n0 + row) * 1024 + k0 + ldc * 8;
        CP16(doff,         A + ga);
        CP16(doff + ARR_B, Bh + gb);
        if (NTERMS == 2) CP16(doff + 2 * ARR_B, Bl + gb);
    }
}

#define H_STAGE(NT) ((1 + NT) * ARR_B)

template <int NTERMS, bool OUT_F32>
__global__ __launch_bounds__(256, 2) void h_gemm(
    const __nv_bfloat16* __restrict__ A,
    const __nv_bfloat16* __restrict__ Bh, const __nv_bfloat16* __restrict__ Bl,
    const float* __restrict__ bias, float* __restrict__ outF,
    __nv_bfloat16* __restrict__ outH)
{
    extern __shared__ __align__(16) char sm[];
    const int m0 = blockIdx.y * 128, n0 = blockIdx.x * 128;
    const uint32_t stage_b = H_STAGE(NTERMS);

    const uint32_t sb = smem_u32(sm);
    const int tid = threadIdx.x;
    const int lid = tid & 31, wid = tid >> 5;
    const int wm = wid >> 1, wn = wid & 1;

    float acc[2][8][4];
    #pragma unroll
    for (int f = 0; f < 2; f++)
        #pragma unroll
        for (int n = 0; n < 8; n++)
            #pragma unroll
            for (int j = 0; j < 4; j++) acc[f][n][j] = 0.0f;

    const uint32_t a_rel = (uint32_t)(wm * 32 + (lid & 15)) * ROWB + ((lid >> 4) << 4);
    const uint32_t b_rel = (uint32_t)(wn * 64 + (lid & 7) + ((lid >> 4) << 3)) * ROWB
                           + (((lid >> 3) & 1) << 4);

    h_load_stage<NTERMS>(sb, m0, n0, 0, tid, A, Bh, Bl);
    CP_COMMIT();
    h_load_stage<NTERMS>(sb + stage_b, m0, n0, 32, tid, A, Bh, Bl);
    CP_COMMIT();

    for (int c = 0; c < 32; c++) {
        if (c < 31) CP_WAIT1(); else CP_WAIT0();
        __syncthreads();
        if (c + 2 < 32) {
            h_load_stage<NTERMS>(sb + ((c + 2) % 3) * stage_b, m0, n0,
                                 (c + 2) * 32, tid, A, Bh, Bl);
            CP_COMMIT();
        }

        const uint32_t base = sb + (c % 3) * stage_b;
        #pragma unroll
        for (int ks = 0; ks < 2; ks++) {
            const uint32_t koff = ks * 32;
            uint32_t a[2][4];
            #pragma unroll
            for (int f = 0; f < 2; f++)
                ldsm_x4(a[f], base + a_rel + f * 16 * ROWB + koff);
            #pragma unroll
            for (int nfp = 0; nfp < 4; nfp++) {
                uint32_t bh[4];
                ldsm_x4(bh, base + ARR_B + b_rel + nfp * 16 * ROWB + koff);
                #pragma unroll
                for (int f = 0; f < 2; f++) {
                    mma16816h(acc[f][nfp * 2 + 0], a[f], bh + 0);
                    mma16816h(acc[f][nfp * 2 + 1], a[f], bh + 2);
                }
                if (NTERMS == 2) {
                    uint32_t bl[4];
                    ldsm_x4(bl, base + 2 * ARR_B + b_rel + nfp * 16 * ROWB + koff);
                    #pragma unroll
                    for (int f = 0; f < 2; f++) {
                        mma16816h(acc[f][nfp * 2 + 0], a[f], bl + 0);
                        mma16816h(acc[f][nfp * 2 + 1], a[f], bl + 2);
                    }
                }
            }
        }
    }

    const int r_base = m0 + wm * 32 + (lid >> 2);
    const int c_lane = (lid & 3) * 2;
    #pragma unroll
    for (int f = 0; f < 2; f++) {
        #pragma unroll
        for (int nf = 0; nf < 8; nf++) {
            int col = n0 + wn * 64 + nf * 8 + c_lane;
            float2 bb = *(const float2*)(bias + col);
            int r0 = r_base + f * 16;
            float* a = acc[f][nf];
            float v0 = a[0] + bb.x, v1 = a[1] + bb.y;
            float v2 = a[2] + bb.x, v3 = a[3] + bb.y;
            if (OUT_F32) {
                *(float2*)(outF + (size_t)r0 * 1024 + col) = make_float2(v0, v1);
                *(float2*)(outF + (size_t)(r0 + 8) * 1024 + col) = make_float2(v2, v3);
            } else {
                *(uint32_t*)(outH + (size_t)r0 * 1024 + col) = packf16(v0, v1);
                *(uint32_t*)(outH + (size_t)(r0 + 8) * 1024 + col) = packf16(v2, v3);
            }
        }
    }
}

// ---------------------------------------------------------------------------
// Tensor-core flash attention (exp2 domain), 32 q-rows per warp,
// 3-stage K/V ring, ONE __syncthreads per key tile.
// Q/K bf16 hi/lo 3-term; V single fp16, P fp16 1-term PV.
// ---------------------------------------------------------------------------
#define KROWB 144
#define TILE9K (64 * KROWB)            // 9216
#define QTILE (256 * KROWB)            // 36864
#define STAGE_A (3 * TILE9K)           // 27648: Kh,Kl,V
#define Q_OFF (3 * STAGE_A)            // 82944
#define ATTN_SMEM (Q_OFF + 2 * QTILE)  // 156672

__device__ __forceinline__ void attn_load_stage(
    uint32_t dst, int b, int h, int kt, int tid)
{
    const __nv_bfloat16* kh = g_qkvh + 1ull * ACT_ELEMS;
    const __nv_bfloat16* kl = g_qkvl + 1ull * ACT_ELEMS;
    const __nv_bfloat16* vv = g_qkvh + 2ull * ACT_ELEMS;  // fp16 bits
    const size_t krow = (size_t)(b * NN + kt * 64);
    #pragma unroll
    for (int t = 0; t < 2; t++) {
        int chunk = tid + t * 256;
        int r = chunk >> 3, c = chunk & 7;
        size_t g = (krow + r) * DM + h * 64 + c * 8;
        uint32_t d = dst + r * KROWB + c * 16;
        CP16(d,              kh + g);
        CP16(d + TILE9K,     kl + g);
        CP16(d + 2 * TILE9K, vv + g);
    }
}

__global__ __launch_bounds__(256, 1) void attn_mma(const float* __restrict__ bias)
{
    extern __shared__ __align__(16) char sm[];
    const uint32_t sb = smem_u32(sm);
    const int tid = threadIdx.x, lid = tid & 31, wid = tid >> 5;
    const int bh = blockIdx.x;
    const int qt = blockIdx.y;            // 0..3 (256-row q tiles)
    const int b = bh >> 4, h = bh & 15;
    const size_t qrow0 = (size_t)(b * NN + qt * 256);
    const int wq = wid * 32;

    // Q tile hi/lo (256x64) + stage0/stage1 prefetch
    #pragma unroll
    for (int t = 0; t < 8; t++) {
        int chunk = tid + t * 256;
        int r = chunk >> 3, c = chunk & 7;
        size_t g = (qrow0 + r) * DM + h * 64 + c * 8;
        CP16(sb + Q_OFF + r * KROWB + c * 16, g_qkvh + g);
        CP16(sb + Q_OFF + QTILE + r * KROWB + c * 16, g_qkvl + g);
    }
    attn_load_stage(sb, b, h, 0, tid);
    CP_COMMIT();
    attn_load_stage(sb + STAGE_A, b, h, 1, tid);
    CP_COMMIT();

    float o0[8][4], o1[8][4];
    #pragma unroll
    for (int j = 0; j < 8; j++)
        #pragma unroll
        for (int e = 0; e < 4; e++) { o0[j][e] = 0.0f; o1[j][e] = 0.0f; }
    float m00 = -1e30f, m01 = -1e30f, l00 = 0.0f, l01 = 0.0f;
    float m10 = -1e30f, m11 = -1e30f, l10 = 0.0f, l11 = 0.0f;

    const int rrow = (lid >> 2);
    const uint32_t qrel0 = sb + Q_OFF + (uint32_t)(wq + (lid & 15)) * KROWB
                           + ((lid >> 4) << 4);
    const uint32_t qrel1 = qrel0 + 16 * KROWB;
    const uint32_t krel_lane = (uint32_t)((lid & 7) + ((lid >> 4) << 3)) * KROWB
                               + (((lid >> 3) & 1) << 4);
    const uint32_t vcol_lane = ((lid >> 4) << 4);
    const uint32_t vrow_lane = (uint32_t)(lid & 15) * KROWB;

    const float* bias_pt0 = bias
        + (((size_t)(b * NH + h)) * NN + qt * 256 + wq + rrow) * NN
        + (lid & 3) * 2;
    const float* bias_pt1 = bias_pt0 + (size_t)16 * NN;

    for (int kt = 0; kt < 16; kt++) {
        if (kt < 15) CP_WAIT1(); else CP_WAIT0();
        __syncthreads();
        if (kt + 2 < 16) {
            attn_load_stage(sb + ((kt + 2) % 3) * STAGE_A, b, h, kt + 2, tid);
            CP_COMMIT();
        }
        const uint32_t st = sb + (kt % 3) * STAGE_A;

        // ---- bias LDG group 0 ----
        const float* bg0 = bias_pt0 + kt * 64;
        float2 ba0[8], bb0[8];
        #pragma unroll
        for (int j = 0; j < 8; j++) {
            ba0[j] = *(const float2*)(bg0 + j * 8);
            bb0[j] = *(const float2*)(bg0 + 8 * NN + j * 8);
        }

        // ---- S = Q K^T for both groups (K frags shared) ----
        float s0[8][4], s1[8][4];
        #pragma unroll
        for (int j = 0; j < 8; j++)
            #pragma unroll
            for (int e = 0; e < 4; e++) { s0[j][e] = 0.0f; s1[j][e] = 0.0f; }

        #pragma unroll
        for (int ks = 0; ks < 4; ks++) {
            uint32_t aqh0[4], aql0[4], aqh1[4], aql1[4];
            ldsm_x4(aqh0, qrel0 + ks * 32);
            ldsm_x4(aql0, qrel0 + QTILE + ks * 32);
            ldsm_x4(aqh1, qrel1 + ks * 32);
            ldsm_x4(aql1, qrel1 + QTILE + ks * 32);
            const uint32_t kbase = st + krel_lane + ks * 32;
            #pragma unroll
            for (int np = 0; np < 4; np++) {
                uint32_t bkh[4], bkl[4];
                ldsm_x4(bkh, kbase + np * 16 * KROWB);
                ldsm_x4(bkl, kbase + TILE9K + np * 16 * KROWB);
                mma16816(s0[2 * np + 0], aqh0, bkh + 0);
                mma16816(s0[2 * np + 0], aqh0, bkl + 0);
                mma16816(s0[2 * np + 0], aql0, bkh + 0);
                mma16816(s0[2 * np + 1], aqh0, bkh + 2);
                mma16816(s0[2 * np + 1], aqh0, bkl + 2);
                mma16816(s0[2 * np + 1], aql0, bkh + 2);
                mma16816(s1[2 * np + 0], aqh1, bkh + 0);
                mma16816(s1[2 * np + 0], aqh1, bkl + 0);
                mma16816(s1[2 * np + 0], aql1, bkh + 0);
                mma16816(s1[2 * np + 1], aqh1, bkh + 2);
                mma16816(s1[2 * np + 1], aqh1, bkl + 2);
                mma16816(s1[2 * np + 1], aql1, bkh + 2);
            }
        }

        // ---- bias LDG group 1 ----
        const float* bg1 = bias_pt1 + kt * 64;
        float2 ba1[8], bb1[8];
        #pragma unroll
        for (int j = 0; j < 8; j++) {
            ba1[j] = *(const float2*)(bg1 + j * 8);
            bb1[j] = *(const float2*)(bg1 + 8 * NN + j * 8);
        }

        uint32_t pf0[4][4], pf1[4][4];

        // ---- group 0: bias + softmax + pack ----
        {
            #pragma unroll
            for (int j = 0; j < 8; j++) {
                s0[j][0] = fmaf(ba0[j].x, LOG2E, s0[j][0]);
                s0[j][1] = fmaf(ba0[j].y, LOG2E, s0[j][1]);
                s0[j][2] = fmaf(bb0[j].x, LOG2E, s0[j][2]);
                s0[j][3] = fmaf(bb0[j].y, LOG2E, s0[j][3]);
            }
            float mx0 = -1e30f, mx1 = -1e30f;
            #pragma unroll
            for (int j = 0; j < 8; j++) {
                mx0 = fmaxf(mx0, fmaxf(s0[j][0], s0[j][1]));
                mx1 = fmaxf(mx1, fmaxf(s0[j][2], s0[j][3]));
            }
            mx0 = fmaxf(mx0, __shfl_xor_sync(0xffffffffu, mx0, 1));
            mx0 = fmaxf(mx0, __shfl_xor_sync(0xffffffffu, mx0, 2));
            mx1 = fmaxf(mx1, __shfl_xor_sync(0xffffffffu, mx1, 1));
            mx1 = fmaxf(mx1, __shfl_xor_sync(0xffffffffu, mx1, 2));
            float mn0 = fmaxf(m00, mx0), mn1 = fmaxf(m01, mx1);
            float sc0 = ex2(m00 - mn0), sc1 = ex2(m01 - mn1);
            m00 = mn0; m01 = mn1;
            float rs0 = 0.0f, rs1 = 0.0f;
            #pragma unroll
            for (int j = 0; j < 8; j++) {
                s0[j][0] = ex2(s0[j][0] - m00);
                s0[j][1] = ex2(s0[j][1] - m00);
                s0[j][2] = ex2(s0[j][2] - m01);
                s0[j][3] = ex2(s0[j][3] - m01);
                rs0 += s0[j][0] + s0[j][1];
                rs1 += s0[j][2] + s0[j][3];
            }
            rs0 += __shfl_xor_sync(0xffffffffu, rs0, 1);
            rs0 += __shfl_xor_sync(0xffffffffu, rs0, 2);
            rs1 += __shfl_xor_sync(0xffffffffu, rs1, 1);
            rs1 += __shfl_xor_sync(0xffffffffu, rs1, 2);
            l00 = l00 * sc0 + rs0;
            l01 = l01 * sc1 + rs1;
            #pragma unroll
            for (int j = 0; j < 8; j++) {
                o0[j][0] *= sc0; o0[j][1] *= sc0;
                o0[j][2] *= sc1; o0[j][3] *= sc1;
            }
            #pragma unroll
            for (int ks = 0; ks < 4; ks++) {
                pf0[ks][0] = packf16(s0[2 * ks][0], s0[2 * ks][1]);
                pf0[ks][1] = packf16(s0[2 * ks][2], s0[2 * ks][3]);
                pf0[ks][2] = packf16(s0[2 * ks + 1][0], s0[2 * ks + 1][1]);
                pf0[ks][3] = packf16(s0[2 * ks + 1][2], s0[2 * ks + 1][3]);
            }
        }

        // ---- group 1: bias + softmax + pack ----
        {
            #pragma unroll
            for (int j = 0; j < 8; j++) {
                s1[j][0] = fmaf(ba1[j].x, LOG2E, s1[j][0]);
                s1[j][1] = fmaf(ba1[j].y, LOG2E, s1[j][1]);
                s1[j][2] = fmaf(bb1[j].x, LOG2E, s1[j][2]);
                s1[j][3] = fmaf(bb1[j].y, LOG2E, s1[j][3]);
            }
            float mx0 = -1e30f, mx1 = -1e30f;
            #pragma unroll
            for (int j = 0; j < 8; j++) {
                mx0 = fmaxf(mx0, fmaxf(s1[j][0], s1[j][1]));
                mx1 = fmaxf(mx1, fmaxf(s1[j][2], s1[j][3]));
            }
            mx0 = fmaxf(mx0, __shfl_xor_sync(0xffffffffu, mx0, 1));
            mx0 = fmaxf(mx0, __shfl_xor_sync(0xffffffffu, mx0, 2));
            mx1 = fmaxf(mx1, __shfl_xor_sync(0xffffffffu, mx1, 1));
            mx1 = fmaxf(mx1, __shfl_xor_sync(0xffffffffu, mx1, 2));
            float mn0 = fmaxf(m10, mx0), mn1 = fmaxf(m11, mx1);
            float sc0 = ex2(m10 - mn0), sc1 = ex2(m11 - mn1);
            m10 = mn0; m11 = mn1;
            float rs0 = 0.0f, rs1 = 0.0f;
            #pragma unroll
            for (int j = 0; j < 8; j++) {
                s1[j][0] = ex2(s1[j][0] - m10);
                s1[j][1] = ex2(s1[j][1] - m10);
                s1[j][2] = ex2(s1[j][2] - m11);
                s1[j][3] = ex2(s1[j][3] - m11);
                rs0 += s1[j][0] + s1[j][1];
                rs1 += s1[j][2] + s1[j][3];
            }
            rs0 += __shfl_xor_sync(0xffffffffu, rs0, 1);
            rs0 += __shfl_xor_sync(0xffffffffu, rs0, 2);
            rs1 += __shfl_xor_sync(0xffffffffu, rs1, 1);
            rs1 += __shfl_xor_sync(0xffffffffu, rs1, 2);
            l10 = l10 * sc0 + rs0;
            l11 = l11 * sc1 + rs1;
            #pragma unroll
            for (int j = 0; j < 8; j++) {
                o1[j][0] *= sc0; o1[j][1] *= sc0;
                o1[j][2] *= sc1; o1[j][3] *= sc1;
            }
            #pragma unroll
            for (int ks = 0; ks < 4; ks++) {
                pf1[ks][0] = packf16(s1[2 * ks][0], s1[2 * ks][1]);
                pf1[ks][1] = packf16(s1[2 * ks][2], s1[2 * ks][3]);
                pf1[ks][2] = packf16(s1[2 * ks + 1][0], s1[2 * ks + 1][1]);
                pf1[ks][3] = packf16(s1[2 * ks + 1][2], s1[2 * ks + 1][3]);
            }
        }

        // ---- O += P V (V frags shared across groups) ----
        #pragma unroll
        for (int ks = 0; ks < 4; ks++) {
            const uint32_t vbase = st + 2 * TILE9K + ks * 16 * KROWB
                                   + vrow_lane + vcol_lane;
            #pragma unroll
            for (int np = 0; np < 4; np++) {
                uint32_t bv[4];
                ldsm_x4_t(bv, vbase + np * 32);
                mma16816h(o0[2 * np + 0], pf0[ks], bv + 0);
                mma16816h(o0[2 * np + 1], pf0[ks], bv + 2);
                mma16816h(o1[2 * np + 0], pf1[ks], bv + 0);
                mma16816h(o1[2 * np + 1], pf1[ks], bv + 2);
            }
        }
    }

    // ---- epilogue -> ctx single fp16 ----
    {
        const float i00 = 1.0f / l00, i01 = 1.0f / l01;
        const size_t grow = qrow0 + wq + rrow;
        #pragma unroll
        for (int j = 0; j < 8; j++) {
            int col = h * 64 + j * 8 + (lid & 3) * 2;
            *(uint32_t*)(g_ch + grow * DM + col) =
                packf16(o0[j][0] * i00, o0[j][1] * i00);
            *(uint32_t*)(g_ch + (grow + 8) * DM + col) =
                packf16(o0[j][2] * i01, o0[j][3] * i01);
        }
        const float i10 = 1.0f / l10, i11 = 1.0f / l11;
        const size_t grow1 = grow + 16;
        #pragma unroll
        for (int j = 0; j < 8; j++) {
            int col = h * 64 + j * 8 + (lid & 3) * 2;
            *(uint32_t*)(g_ch + grow1 * DM + col) =
                packf16(o1[j][0] * i10, o1[j][1] * i10);
            *(uint32_t*)(g_ch + (grow1 + 8) * DM + col) =
                packf16(o1[j][2] * i11, o1[j][3] * i11);
        }
    }
}

// ---------------------------------------------------------------------------
// Launch
// ---------------------------------------------------------------------------
extern "C" void kernel_launch(void* const* d_in, const int* in_sizes, int n_in,
                              void* d_out, int out_size)
{
    const float* queries   = (const float*)d_in[0];
    const float* keys      = (const float*)d_in[1];
    const float* values    = (const float*)d_in[2];
    const float* attn_bias = (const float*)d_in[3];
    const float* Wq = (const float*)d_in[4];
    const float* bq = (const float*)d_in[5];
    const float* Wk = (const float*)d_in[6];
    const float* bk = (const float*)d_in[7];
    const float* Wv = (const float*)d_in[8];
    const float* bv = (const float*)d_in[9];
    const float* Wo = (const float*)d_in[10];
    const float* bo = (const float*)d_in[11];
    float* out = (float*)d_out;

    __nv_bfloat16 *ah, *wh, *wl, *qkvh, *ch;
    cudaGetSymbolAddress((void**)&ah,   g_ah);
    cudaGetSymbolAddress((void**)&wh,   g_wh);
    cudaGetSymbolAddress((void**)&wl,   g_wl);
    cudaGetSymbolAddress((void**)&qkvh, g_qkvh);
    cudaGetSymbolAddress((void**)&ch,   g_ch);

    cudaFuncSetAttribute(attn_mma,
                         cudaFuncAttributeMaxDynamicSharedMemorySize, ATTN_SMEM);
    cudaFuncSetAttribute(qk_gemm,
                         cudaFuncAttributeMaxDynamicSharedMemorySize, GEMM_SMEM);
    cudaFuncSetAttribute((const void*)h_gemm<1, false>,
                         cudaFuncAttributeMaxDynamicSharedMemorySize, 3 * H_STAGE(1));
    cudaFuncSetAttribute((const void*)h_gemm<2, true>,
                         cudaFuncAttributeMaxDynamicSharedMemorySize, 3 * H_STAGE(2));

    conv_act3<<<dim3(4096, 3), 256>>>(queries, keys, values);
    conv_wt4<<<dim3(32, 32, 4), dim3(32, 8)>>>(Wq, Wk, Wv, Wo);

    // Q and K projections (bf16 3-term)
    qk_gemm<<<dim3(8, 32, 2), 256, GEMM_SMEM>>>(bq, bk);
    // V projection (fp16 1-term) -> single fp16
    h_gemm<1, false><<<dim3(8, 32), 256, 3 * H_STAGE(1)>>>(
        ah + 2ull * ACT_ELEMS, wh + 2ull * W_ELEMS, nullptr,
        bv, nullptr, qkvh + 2ull * ACT_ELEMS);

    attn_mma<<<dim3(64, 4), 256, ATTN_SMEM>>>(attn_bias);

    // Output projection (fp16 2-term) -> fp32
    h_gemm<2, true><<<dim3(8, 32), 256, 3 * H_STAGE(2)>>>(
        ch, wh + 3ull * W_ELEMS, wl + 3ull * W_ELEMS, bo, out, nullptr);
}

// round 12
// speedup vs baseline: 1.3710x; 1.0221x over previous
#include <cuda_runtime.h>
#include <cuda_bf16.h>
#include <cuda_fp16.h>
#include <math.h>
#include <stdint.h>

// Problem constants
#define BB 4
#define NN 1024
#define DM 1024
#define NH 16
#define DK 64
#define LOG2E 1.4426950408889634f

// ---------------------------------------------------------------------------
// Scratch (__device__ globals; allocation-free rule)
// ---------------------------------------------------------------------------
#define ACT_ELEMS (4096 * 1024)
#define W_ELEMS   (1024 * 1024)
__device__ __align__(16) __nv_bfloat16 g_ah[3ull * ACT_ELEMS];  // slot2 = fp16 bits
__device__ __align__(16) __nv_bfloat16 g_al[3ull * ACT_ELEMS];
__device__ __align__(16) __nv_bfloat16 g_wh[4ull * W_ELEMS];    // slots 2,3 = fp16 bits
__device__ __align__(16) __nv_bfloat16 g_wl[4ull * W_ELEMS];
// slot 0=Q bf16 hi/lo, 1=K bf16 hi/lo, 2=V single fp16 (hi slot only)
__device__ __align__(16) __nv_bfloat16 g_qkvh[3ull * ACT_ELEMS];
__device__ __align__(16) __nv_bfloat16 g_qkvl[3ull * ACT_ELEMS];
__device__ __align__(16) __nv_bfloat16 g_ch[ACT_ELEMS];         // ctx single fp16

// ---------------------------------------------------------------------------
// PTX helpers (compute_103-safe)
// ---------------------------------------------------------------------------
__device__ __forceinline__ uint32_t smem_u32(const void* p) {
    uint32_t a;
    asm("{ .reg .u64 t; cvta.to.shared.u64 t, %1; cvt.u32.u64 %0, t; }"
        : "=r"(a) : "l"(p));
    return a;
}

#define CP16(dst, src) \
    asm volatile("cp.async.cg.shared.global [%0], [%1], 16;" \
        :: "r"(dst), "l"(src) : "memory")
#define CP_COMMIT() asm volatile("cp.async.commit_group;" ::: "memory")
#define CP_WAIT1()  asm volatile("cp.async.wait_group 1;" ::: "memory")
#define CP_WAIT0()  asm volatile("cp.async.wait_group 0;" ::: "memory")

__device__ __forceinline__ void ldsm_x4(uint32_t* r, uint32_t addr) {
    asm volatile("ldmatrix.sync.aligned.m8n8.x4.shared.b16 {%0,%1,%2,%3}, [%4];"
        : "=r"(r[0]), "=r"(r[1]), "=r"(r[2]), "=r"(r[3]) : "r"(addr));
}
__device__ __forceinline__ void ldsm_x4_t(uint32_t* r, uint32_t addr) {
    asm volatile("ldmatrix.sync.aligned.m8n8.x4.trans.shared.b16 {%0,%1,%2,%3}, [%4];"
        : "=r"(r[0]), "=r"(r[1]), "=r"(r[2]), "=r"(r[3]) : "r"(addr));
}

__device__ __forceinline__ void mma16816(float* c, const uint32_t* a,
                                         const uint32_t* b) {
    asm volatile(
        "mma.sync.aligned.m16n8k16.row.col.f32.bf16.bf16.f32 "
        "{%0,%1,%2,%3}, {%4,%5,%6,%7}, {%8,%9}, {%0,%1,%2,%3};"
        : "+f"(c[0]), "+f"(c[1]), "+f"(c[2]), "+f"(c[3])
        : "r"(a[0]), "r"(a[1]), "r"(a[2]), "r"(a[3]), "r"(b[0]), "r"(b[1]));
}
__device__ __forceinline__ void mma16816h(float* c, const uint32_t* a,
                                          const uint32_t* b) {
    asm volatile(
        "mma.sync.aligned.m16n8k16.row.col.f32.f16.f16.f32 "
        "{%0,%1,%2,%3}, {%4,%5,%6,%7}, {%8,%9}, {%0,%1,%2,%3};"
        : "+f"(c[0]), "+f"(c[1]), "+f"(c[2]), "+f"(c[3])
        : "r"(a[0]), "r"(a[1]), "r"(a[2]), "r"(a[3]), "r"(b[0]), "r"(b[1]));
}

__device__ __forceinline__ float ex2(float x) {
    float r; asm("ex2.approx.f32 %0, %1;" : "=f"(r) : "f"(x)); return r;
}
__device__ __forceinline__ uint32_t packf16(float x, float y) {
    uint32_t r;
    asm("cvt.rn.f16x2.f32 %0, %1, %2;" : "=r"(r) : "f"(y), "f"(x));
    return r;
}

// fast bf16 hi/lo split of a float pair
__device__ __forceinline__ void split2(float x, float y, uint32_t& h, uint32_t& l) {
    asm("cvt.rn.bf16x2.f32 %0, %1, %2;" : "=r"(h) : "f"(y), "f"(x));
    float hx = __uint_as_float(h << 16);
    float hy = __uint_as_float(h & 0xFFFF0000u);
    float lx = x - hx, ly = y - hy;
    asm("cvt.rn.bf16x2.f32 %0, %1, %2;" : "=r"(l) : "f"(ly), "f"(lx));
}

// ---------------------------------------------------------------------------
// Conversions
// ---------------------------------------------------------------------------
__global__ __launch_bounds__(256) void conv_act3(
    const float* __restrict__ q, const float* __restrict__ k,
    const float* __restrict__ v)
{
    const int z = blockIdx.y;
    const float* X = z == 0 ? q : (z == 1 ? k : v);
    __nv_bfloat16* hi = g_ah + (size_t)z * ACT_ELEMS;
    __nv_bfloat16* lo = g_al + (size_t)z * ACT_ELEMS;
    int e = (blockIdx.x * 256 + threadIdx.x) * 4;
    float4 x = *(const float4*)(X + e);
    if (z == 2) {
        *(uint2*)(hi + e) = make_uint2(packf16(x.x, x.y), packf16(x.z, x.w));
    } else {
        uint32_t h0, l0, h1, l1;
        split2(x.x, x.y, h0, l0);
        split2(x.z, x.w, h1, l1);
        *(uint2*)(hi + e) = make_uint2(h0, h1);
        *(uint2*)(lo + e) = make_uint2(l0, l1);
    }
}

// Wq/Wk -> bf16 hi/lo ; Wv/Wo -> fp16 single
__global__ void conv_wt4(const float* __restrict__ Wq, const float* __restrict__ Wk,
                         const float* __restrict__ Wv, const float* __restrict__ Wo)
{
    __shared__ float t[32][33];
    const int z = blockIdx.z;
    const float* W = z == 0 ? Wq : (z == 1 ? Wk : (z == 2 ? Wv : Wo));
    __nv_bfloat16* hi = g_wh + (size_t)z * W_ELEMS;
    __nv_bfloat16* lo = g_wl + (size_t)z * W_ELEMS;
    int n0 = blockIdx.x * 32, k0 = blockIdx.y * 32;
    int tx = threadIdx.x, ty = threadIdx.y;  // 32 x 8

    #pragma unroll
    for (int j = 0; j < 32; j += 8)
        t[ty + j][tx] = W[(size_t)(k0 + ty + j) * 1024 + n0 + tx];
    __syncthreads();

    #pragma unroll
    for (int j = 0; j < 32; j += 8) {
        int n = n0 + ty + j, k = k0 + tx;
        float x = t[tx][ty + j];
        if (z >= 2) {
            *(__half*)(hi + (size_t)n * 1024 + k) = __float2half_rn(x);
        } else {
            __nv_bfloat16 h = __float2bfloat16(x);
            __nv_bfloat16 l = __float2bfloat16(x - __bfloat162float(h));
            hi[(size_t)n * 1024 + k] = h;
            lo[(size_t)n * 1024 + k] = l;
        }
    }
}

// ---------------------------------------------------------------------------
// Q/K projection GEMM, bf16 hi/lo 3-term, 3-stage ring / 1 sync per chunk.
// ---------------------------------------------------------------------------
#define ROWB 80
#define ARR_B (128 * ROWB)
#define STAGE_B (4 * ARR_B)
#define QK_SMEM (3 * STAGE_B)   // 122880 -> 1 CTA/SM

__device__ __forceinline__ void gemm_load_stage(
    uint32_t dbase, int m0, int n0, int k0, int tid,
    const __nv_bfloat16* Ah, const __nv_bfloat16* Al,
    const __nv_bfloat16* Bh, const __nv_bfloat16* Bl)
{
    int ldc = tid & 3;
    int r0 = tid >> 2;
    #pragma unroll
    for (int h = 0; h < 2; h++) {
        int row = r0 + h * 64;
        uint32_t doff = dbase + row * ROWB + ldc * 16;
        size_t ga = (size_t)(m0 + row) * 1024 + k0 + ldc * 8;
        size_t gb = (size_t)(n0 + row) * 1024 + k0 + ldc * 8;
        CP16(doff,             Ah + ga);
        CP16(doff + ARR_B,     Al + ga);
        CP16(doff + 2 * ARR_B, Bh + gb);
        CP16(doff + 3 * ARR_B, Bl + gb);
    }
}

__global__ __launch_bounds__(256, 1) void qk_gemm(
    const float* __restrict__ bq, const float* __restrict__ bk)
{
    extern __shared__ __align__(16) char sm[];
    const int z = blockIdx.z;           // 0=Q, 1=K
    const float* bias = z == 0 ? bq : bk;
    const float scale = z == 0 ? 0.125f * LOG2E : 1.0f;
    const __nv_bfloat16* Ah = g_ah + (size_t)z * ACT_ELEMS;
    const __nv_bfloat16* Al = g_al + (size_t)z * ACT_ELEMS;
    const __nv_bfloat16* Bh = g_wh + (size_t)z * W_ELEMS;
    const __nv_bfloat16* Bl = g_wl + (size_t)z * W_ELEMS;
    __nv_bfloat16* Ch = g_qkvh + (size_t)z * ACT_ELEMS;
    __nv_bfloat16* Cl = g_qkvl + (size_t)z * ACT_ELEMS;
    const int m0 = blockIdx.y * 128, n0 = blockIdx.x * 128;

    const uint32_t sb = smem_u32(sm);
    const int tid = threadIdx.x;
    const int lid = tid & 31, wid = tid >> 5;
    const int wm = wid >> 1, wn = wid & 1;

    float acc[2][8][4];
    #pragma unroll
    for (int f = 0; f < 2; f++)
        #pragma unroll
        for (int n = 0; n < 8; n++)
            #pragma unroll
            for (int j = 0; j < 4; j++) acc[f][n][j] = 0.0f;

    const uint32_t a_rel = (uint32_t)(wm * 32 + (lid & 15)) * ROWB + ((lid >> 4) << 4);
    const uint32_t b_rel = (uint32_t)(wn * 64 + (lid & 7) + ((lid >> 4) << 3)) * ROWB
                           + (((lid >> 3) & 1) << 4);

    gemm_load_stage(sb, m0, n0, 0, tid, Ah, Al, Bh, Bl);
    CP_COMMIT();
    gemm_load_stage(sb + STAGE_B, m0, n0, 32, tid, Ah, Al, Bh, Bl);
    CP_COMMIT();

    for (int c = 0; c < 32; c++) {
        if (c < 31) CP_WAIT1(); else CP_WAIT0();
        __syncthreads();
        if (c + 2 < 32) {
            gemm_load_stage(sb + ((c + 2) % 3) * STAGE_B, m0, n0, (c + 2) * 32,
                            tid, Ah, Al, Bh, Bl);
            CP_COMMIT();
        }

        const uint32_t base = sb + (c % 3) * STAGE_B;
        #pragma unroll
        for (int ks = 0; ks < 2; ks++) {
            const uint32_t koff = ks * 32;
            uint32_t ah[2][4], al[2][4];
            #pragma unroll
            for (int f = 0; f < 2; f++) {
                ldsm_x4(ah[f], base + a_rel + f * 16 * ROWB + koff);
                ldsm_x4(al[f], base + ARR_B + a_rel + f * 16 * ROWB + koff);
            }
            #pragma unroll
            for (int nfp = 0; nfp < 4; nfp++) {
                uint32_t bh[4], bl[4];
                ldsm_x4(bh, base + 2 * ARR_B + b_rel + nfp * 16 * ROWB + koff);
                ldsm_x4(bl, base + 3 * ARR_B + b_rel + nfp * 16 * ROWB + koff);
                #pragma unroll
                for (int f = 0; f < 2; f++) {
                    mma16816(acc[f][nfp * 2 + 0], ah[f], bh + 0);
                    mma16816(acc[f][nfp * 2 + 0], ah[f], bl + 0);
                    mma16816(acc[f][nfp * 2 + 0], al[f], bh + 0);
                    mma16816(acc[f][nfp * 2 + 1], ah[f], bh + 2);
                    mma16816(acc[f][nfp * 2 + 1], ah[f], bl + 2);
                    mma16816(acc[f][nfp * 2 + 1], al[f], bh + 2);
                }
            }
        }
    }

    const int r_base = m0 + wm * 32 + (lid >> 2);
    const int c_lane = (lid & 3) * 2;
    #pragma unroll
    for (int f = 0; f < 2; f++) {
        #pragma unroll
        for (int nf = 0; nf < 8; nf++) {
            int col = n0 + wn * 64 + nf * 8 + c_lane;
            float2 bb = *(const float2*)(bias + col);
            int r0 = r_base + f * 16;
            float* a = acc[f][nf];
            float v0 = (a[0] + bb.x) * scale, v1 = (a[1] + bb.y) * scale;
            float v2 = (a[2] + bb.x) * scale, v3 = (a[3] + bb.y) * scale;
            uint32_t h0, l0, h1, l1;
            split2(v0, v1, h0, l0);
            split2(v2, v3, h1, l1);
            *(uint32_t*)(Ch + (size_t)r0 * 1024 + col) = h0;
            *(uint32_t*)(Cl + (size_t)r0 * 1024 + col) = l0;
            *(uint32_t*)(Ch + (size_t)(r0 + 8) * 1024 + col) = h1;
            *(uint32_t*)(Cl + (size_t)(r0 + 8) * 1024 + col) = l1;
        }
    }
}

// ---------------------------------------------------------------------------
// fp16 1-term GEMM (A single fp16 x B single fp16), 3-stage ring / 1 sync.
// Used for V-projection (fp16 out) and output projection (fp32 out).
// ---------------------------------------------------------------------------
#define H_STAGE (2 * ARR_B)
#define H_SMEM (3 * H_STAGE)   // 61440 -> 2 CTAs/SM

__device__ __forceinline__ void h_load_stage(
    uint32_t dbase, int m0, int n0, int k0, int tid,
    const __nv_bfloat16* A, const __nv_bfloat16* Bh)
{
    int ldc = tid & 3;
    int r0 = tid >> 2;
    #pragma unroll
    for (int h = 0; h < 2; h++) {
        int row = r0 + h * 64;
        uint32_t doff = dbase + row * ROWB + ldc * 16;
        size_t ga = (size_t)(m0 + row) * 1024 + k0 + ldc * 8;
        size_t gb = (size_t)(n0 + row) * 1024 + k0 + ldc * 8;
        CP16(doff,         A + ga);
        CP16(doff + ARR_B, Bh + gb);
    }
}

template <bool OUT_F32>
__global__ __launch_bounds__(256, 2) void h_gemm(
    const __nv_bfloat16* __restrict__ A, const __nv_bfloat16* __restrict__ Bh,
    const float* __restrict__ bias, float* __restrict__ outF,
    __nv_bfloat16* __restrict__ outH)
{
    extern __shared__ __align__(16) char sm[];
    const int m0 = blockIdx.y * 128, n0 = blockIdx.x * 128;

    const uint32_t sb = smem_u32(sm);
    const int tid = threadIdx.x;
    const int lid = tid & 31, wid = tid >> 5;
    const int wm = wid >> 1, wn = wid & 1;

    float acc[2][8][4];
    #pragma unroll
    for (int f = 0; f < 2; f++)
        #pragma unroll
        for (int n = 0; n < 8; n++)
            #pragma unroll
            for (int j = 0; j < 4; j++) acc[f][n][j] = 0.0f;

    const uint32_t a_rel = (uint32_t)(wm * 32 + (lid & 15)) * ROWB + ((lid >> 4) << 4);
    const uint32_t b_rel = (uint32_t)(wn * 64 + (lid & 7) + ((lid >> 4) << 3)) * ROWB
                           + (((lid >> 3) & 1) << 4);

    h_load_stage(sb, m0, n0, 0, tid, A, Bh);
    CP_COMMIT();
    h_load_stage(sb + H_STAGE, m0, n0, 32, tid, A, Bh);
    CP_COMMIT();

    for (int c = 0; c < 32; c++) {
        if (c < 31) CP_WAIT1(); else CP_WAIT0();
        __syncthreads();
        if (c + 2 < 32) {
            h_load_stage(sb + ((c + 2) % 3) * H_STAGE, m0, n0, (c + 2) * 32,
                         tid, A, Bh);
            CP_COMMIT();
        }

        const uint32_t base = sb + (c % 3) * H_STAGE;
        #pragma unroll
        for (int ks = 0; ks < 2; ks++) {
            const uint32_t koff = ks * 32;
            uint32_t a[2][4];
            #pragma unroll
            for (int f = 0; f < 2; f++)
                ldsm_x4(a[f], base + a_rel + f * 16 * ROWB + koff);
            #pragma unroll
            for (int nfp = 0; nfp < 4; nfp++) {
                uint32_t bh[4];
                ldsm_x4(bh, base + ARR_B + b_rel + nfp * 16 * ROWB + koff);
                #pragma unroll
                for (int f = 0; f < 2; f++) {
                    mma16816h(acc[f][nfp * 2 + 0], a[f], bh + 0);
                    mma16816h(acc[f][nfp * 2 + 1], a[f], bh + 2);
                }
            }
        }
    }

    const int r_base = m0 + wm * 32 + (lid >> 2);
    const int c_lane = (lid & 3) * 2;
    #pragma unroll
    for (int f = 0; f < 2; f++) {
        #pragma unroll
        for (int nf = 0; nf < 8; nf++) {
            int col = n0 + wn * 64 + nf * 8 + c_lane;
            float2 bb = *(const float2*)(bias + col);
            int r0 = r_base + f * 16;
            float* a = acc[f][nf];
            float v0 = a[0] + bb.x, v1 = a[1] + bb.y;
            float v2 = a[2] + bb.x, v3 = a[3] + bb.y;
            if (OUT_F32) {
                *(float2*)(outF + (size_t)r0 * 1024 + col) = make_float2(v0, v1);
                *(float2*)(outF + (size_t)(r0 + 8) * 1024 + col) = make_float2(v2, v3);
            } else {
                *(uint32_t*)(outH + (size_t)r0 * 1024 + col) = packf16(v0, v1);
                *(uint32_t*)(outH + (size_t)(r0 + 8) * 1024 + col) = packf16(v2, v3);
            }
        }
    }
}

// ---------------------------------------------------------------------------
// Tensor-core flash attention (exp2 domain), 32 q-rows per warp,
// 3-stage K/V ring, ONE __syncthreads per key tile.
// Q/K bf16 hi/lo 3-term; V single fp16, P fp16 1-term PV.
// ---------------------------------------------------------------------------
#define KROWB 144
#define TILE9K (64 * KROWB)            // 9216
#define QTILE (256 * KROWB)            // 36864
#define STAGE_A (3 * TILE9K)           // 27648: Kh,Kl,V
#define Q_OFF (3 * STAGE_A)            // 82944
#define ATTN_SMEM (Q_OFF + 2 * QTILE)  // 156672

__device__ __forceinline__ void attn_load_stage(
    uint32_t dst, int b, int h, int kt, int tid)
{
    const __nv_bfloat16* kh = g_qkvh + 1ull * ACT_ELEMS;
    const __nv_bfloat16* kl = g_qkvl + 1ull * ACT_ELEMS;
    const __nv_bfloat16* vv = g_qkvh + 2ull * ACT_ELEMS;  // fp16 bits
    const size_t krow = (size_t)(b * NN + kt * 64);
    #pragma unroll
    for (int t = 0; t < 2; t++) {
        int chunk = tid + t * 256;
        int r = chunk >> 3, c = chunk & 7;
        size_t g = (krow + r) * DM + h * 64 + c * 8;
        uint32_t d = dst + r * KROWB + c * 16;
        CP16(d,              kh + g);
        CP16(d + TILE9K,     kl + g);
        CP16(d + 2 * TILE9K, vv + g);
    }
}

__global__ __launch_bounds__(256, 1) void attn_mma(const float* __restrict__ bias)
{
    extern __shared__ __align__(16) char sm[];
    const uint32_t sb = smem_u32(sm);
    const int tid = threadIdx.x, lid = tid & 31, wid = tid >> 5;
    const int bh = blockIdx.x;
    const int qt = blockIdx.y;            // 0..3 (256-row q tiles)
    const int b = bh >> 4, h = bh & 15;
    const size_t qrow0 = (size_t)(b * NN + qt * 256);
    const int wq = wid * 32;

    #pragma unroll
    for (int t = 0; t < 8; t++) {
        int chunk = tid + t * 256;
        int r = chunk >> 3, c = chunk & 7;
        size_t g = (qrow0 + r) * DM + h * 64 + c * 8;
        CP16(sb + Q_OFF + r * KROWB + c * 16, g_qkvh + g);
        CP16(sb + Q_OFF + QTILE + r * KROWB + c * 16, g_qkvl + g);
    }
    attn_load_stage(sb, b, h, 0, tid);
    CP_COMMIT();
    attn_load_stage(sb + STAGE_A, b, h, 1, tid);
    CP_COMMIT();

    float o0[8][4], o1[8][4];
    #pragma unroll
    for (int j = 0; j < 8; j++)
        #pragma unroll
        for (int e = 0; e < 4; e++) { o0[j][e] = 0.0f; o1[j][e] = 0.0f; }
    float m00 = -1e30f, m01 = -1e30f, l00 = 0.0f, l01 = 0.0f;
    float m10 = -1e30f, m11 = -1e30f, l10 = 0.0f, l11 = 0.0f;

    const int rrow = (lid >> 2);
    const uint32_t qrel0 = sb + Q_OFF + (uint32_t)(wq + (lid & 15)) * KROWB
                           + ((lid >> 4) << 4);
    const uint32_t qrel1 = qrel0 + 16 * KROWB;
    const uint32_t krel_lane = (uint32_t)((lid & 7) + ((lid >> 4) << 3)) * KROWB
                               + (((lid >> 3) & 1) << 4);
    const uint32_t vcol_lane = ((lid >> 4) << 4);
    const uint32_t vrow_lane = (uint32_t)(lid & 15) * KROWB;

    const float* bias_pt0 = bias
        + (((size_t)(b * NH + h)) * NN + qt * 256 + wq + rrow) * NN
        + (lid & 3) * 2;
    const float* bias_pt1 = bias_pt0 + (size_t)16 * NN;

    for (int kt = 0; kt < 16; kt++) {
        if (kt < 15) CP_WAIT1(); else CP_WAIT0();
        __syncthreads();
        if (kt + 2 < 16) {
            attn_load_stage(sb + ((kt + 2) % 3) * STAGE_A, b, h, kt + 2, tid);
            CP_COMMIT();
        }
        const uint32_t st = sb + (kt % 3) * STAGE_A;

        // ---- bias LDG group 0 ----
        const float* bg0 = bias_pt0 + kt * 64;
        float2 ba0[8], bb0[8];
        #pragma unroll
        for (int j = 0; j < 8; j++) {
            ba0[j] = *(const float2*)(bg0 + j * 8);
            bb0[j] = *(const float2*)(bg0 + 8 * NN + j * 8);
        }

        // ---- S = Q K^T for both groups (K frags shared) ----
        float s0[8][4], s1[8][4];
        #pragma unroll
        for (int j = 0; j < 8; j++)
            #pragma unroll
            for (int e = 0; e < 4; e++) { s0[j][e] = 0.0f; s1[j][e] = 0.0f; }

        #pragma unroll
        for (int ks = 0; ks < 4; ks++) {
            uint32_t aqh0[4], aql0[4], aqh1[4], aql1[4];
            ldsm_x4(aqh0, qrel0 + ks * 32);
            ldsm_x4(aql0, qrel0 + QTILE + ks * 32);
            ldsm_x4(aqh1, qrel1 + ks * 32);
            ldsm_x4(aql1, qrel1 + QTILE + ks * 32);
            const uint32_t kbase = st + krel_lane + ks * 32;
            #pragma unroll
            for (int np = 0; np < 4; np++) {
                uint32_t bkh[4], bkl[4];
                ldsm_x4(bkh, kbase + np * 16 * KROWB);
                ldsm_x4(bkl, kbase + TILE9K + np * 16 * KROWB);
                mma16816(s0[2 * np + 0], aqh0, bkh + 0);
                mma16816(s0[2 * np + 0], aqh0, bkl + 0);
                mma16816(s0[2 * np + 0], aql0, bkh + 0);
                mma16816(s0[2 * np + 1], aqh0, bkh + 2);
                mma16816(s0[2 * np + 1], aqh0, bkl + 2);
                mma16816(s0[2 * np + 1], aql0, bkh + 2);
                mma16816(s1[2 * np + 0], aqh1, bkh + 0);
                mma16816(s1[2 * np + 0], aqh1, bkl + 0);
                mma16816(s1[2 * np + 0], aql1, bkh + 0);
                mma16816(s1[2 * np + 1], aqh1, bkh + 2);
                mma16816(s1[2 * np + 1], aqh1, bkl + 2);
                mma16816(s1[2 * np + 1], aql1, bkh + 2);
            }
        }

        // ---- bias LDG group 1 ----
        const float* bg1 = bias_pt1 + kt * 64;
        float2 ba1[8], bb1[8];
        #pragma unroll
        for (int j = 0; j < 8; j++) {
            ba1[j] = *(const float2*)(bg1 + j * 8);
            bb1[j] = *(const float2*)(bg1 + 8 * NN + j * 8);
        }

        uint32_t pf0[4][4], pf1[4][4];

        // ---- group 0: bias + softmax + pack ----
        {
            #pragma unroll
            for (int j = 0; j < 8; j++) {
                s0[j][0] = fmaf(ba0[j].x, LOG2E, s0[j][0]);
                s0[j][1] = fmaf(ba0[j].y, LOG2E, s0[j][1]);
                s0[j][2] = fmaf(bb0[j].x, LOG2E, s0[j][2]);
                s0[j][3] = fmaf(bb0[j].y, LOG2E, s0[j][3]);
            }
            float mx0 = -1e30f, mx1 = -1e30f;
            #pragma unroll
            for (int j = 0; j < 8; j++) {
                mx0 = fmaxf(mx0, fmaxf(s0[j][0], s0[j][1]));
                mx1 = fmaxf(mx1, fmaxf(s0[j][2], s0[j][3]));
            }
            mx0 = fmaxf(mx0, __shfl_xor_sync(0xffffffffu, mx0, 1));
            mx0 = fmaxf(mx0, __shfl_xor_sync(0xffffffffu, mx0, 2));
            mx1 = fmaxf(mx1, __shfl_xor_sync(0xffffffffu, mx1, 1));
            mx1 = fmaxf(mx1, __shfl_xor_sync(0xffffffffu, mx1, 2));
            float mn0 = fmaxf(m00, mx0), mn1 = fmaxf(m01, mx1);
            float sc0 = ex2(m00 - mn0), sc1 = ex2(m01 - mn1);
            m00 = mn0; m01 = mn1;
            float rs0 = 0.0f, rs1 = 0.0f;
            #pragma unroll
            for (int j = 0; j < 8; j++) {
                s0[j][0] = ex2(s0[j][0] - m00);
                s0[j][1] = ex2(s0[j][1] - m00);
                s0[j][2] = ex2(s0[j][2] - m01);
                s0[j][3] = ex2(s0[j][3] - m01);
                rs0 += s0[j][0] + s0[j][1];
                rs1 += s0[j][2] + s0[j][3];
            }
            rs0 += __shfl_xor_sync(0xffffffffu, rs0, 1);
            rs0 += __shfl_xor_sync(0xffffffffu, rs0, 2);
            rs1 += __shfl_xor_sync(0xffffffffu, rs1, 1);
            rs1 += __shfl_xor_sync(0xffffffffu, rs1, 2);
            l00 = l00 * sc0 + rs0;
            l01 = l01 * sc1 + rs1;
            #pragma unroll
            for (int j = 0; j < 8; j++) {
                o0[j][0] *= sc0; o0[j][1] *= sc0;
                o0[j][2] *= sc1; o0[j][3] *= sc1;
            }
            #pragma unroll
            for (int ks = 0; ks < 4; ks++) {
                pf0[ks][0] = packf16(s0[2 * ks][0], s0[2 * ks][1]);
                pf0[ks][1] = packf16(s0[2 * ks][2], s0[2 * ks][3]);
                pf0[ks][2] = packf16(s0[2 * ks + 1][0], s0[2 * ks + 1][1]);
                pf0[ks][3] = packf16(s0[2 * ks + 1][2], s0[2 * ks + 1][3]);
            }
        }

        // ---- group 1: bias + softmax + pack ----
        {
            #pragma unroll
            for (int j = 0; j < 8; j++) {
                s1[j][0] = fmaf(ba1[j].x, LOG2E, s1[j][0]);
                s1[j][1] = fmaf(ba1[j].y, LOG2E, s1[j][1]);
                s1[j][2] = fmaf(bb1[j].x, LOG2E, s1[j][2]);
                s1[j][3] = fmaf(bb1[j].y, LOG2E, s1[j][3]);
            }
            float mx0 = -1e30f, mx1 = -1e30f;
            #pragma unroll
            for (int j = 0; j < 8; j++) {
                mx0 = fmaxf(mx0, fmaxf(s1[j][0], s1[j][1]));
                mx1 = fmaxf(mx1, fmaxf(s1[j][2], s1[j][3]));
            }
            mx0 = fmaxf(mx0, __shfl_xor_sync(0xffffffffu, mx0, 1));
            mx0 = fmaxf(mx0, __shfl_xor_sync(0xffffffffu, mx0, 2));
            mx1 = fmaxf(mx1, __shfl_xor_sync(0xffffffffu, mx1, 1));
            mx1 = fmaxf(mx1, __shfl_xor_sync(0xffffffffu, mx1, 2));
            float mn0 = fmaxf(m10, mx0), mn1 = fmaxf(m11, mx1);
            float sc0 = ex2(m10 - mn0), sc1 = ex2(m11 - mn1);
            m10 = mn0; m11 = mn1;
            float rs0 = 0.0f, rs1 = 0.0f;
            #pragma unroll
            for (int j = 0; j < 8; j++) {
                s1[j][0] = ex2(s1[j][0] - m10);
                s1[j][1] = ex2(s1[j][1] - m10);
                s1[j][2] = ex2(s1[j][2] - m11);
                s1[j][3] = ex2(s1[j][3] - m11);
                rs0 += s1[j][0] + s1[j][1];
                rs1 += s1[j][2] + s1[j][3];
            }
            rs0 += __shfl_xor_sync(0xffffffffu, rs0, 1);
            rs0 += __shfl_xor_sync(0xffffffffu, rs0, 2);
            rs1 += __shfl_xor_sync(0xffffffffu, rs1, 1);
            rs1 += __shfl_xor_sync(0xffffffffu, rs1, 2);
            l10 = l10 * sc0 + rs0;
            l11 = l11 * sc1 + rs1;
            #pragma unroll
            for (int j = 0; j < 8; j++) {
                o1[j][0] *= sc0; o1[j][1] *= sc0;
                o1[j][2] *= sc1; o1[j][3] *= sc1;
            }
            #pragma unroll
            for (int ks = 0; ks < 4; ks++) {
                pf1[ks][0] = packf16(s1[2 * ks][0], s1[2 * ks][1]);
                pf1[ks][1] = packf16(s1[2 * ks][2], s1[2 * ks][3]);
                pf1[ks][2] = packf16(s1[2 * ks + 1][0], s1[2 * ks + 1][1]);
                pf1[ks][3] = packf16(s1[2 * ks + 1][2], s1[2 * ks + 1][3]);
            }
        }

        // ---- O += P V (V frags shared across groups) ----
        #pragma unroll
        for (int ks = 0; ks < 4; ks++) {
            const uint32_t vbase = st + 2 * TILE9K + ks * 16 * KROWB
                                   + vrow_lane + vcol_lane;
            #pragma unroll
            for (int np = 0; np < 4; np++) {
                uint32_t bv[4];
                ldsm_x4_t(bv, vbase + np * 32);
                mma16816h(o0[2 * np + 0], pf0[ks], bv + 0);
                mma16816h(o0[2 * np + 1], pf0[ks], bv + 2);
                mma16816h(o1[2 * np + 0], pf1[ks], bv + 0);
                mma16816h(o1[2 * np + 1], pf1[ks], bv + 2);
            }
        }
    }

    // ---- epilogue -> ctx single fp16 ----
    {
        const float i00 = 1.0f / l00, i01 = 1.0f / l01;
        const size_t grow = qrow0 + wq + rrow;
        #pragma unroll
        for (int j = 0; j < 8; j++) {
            int col = h * 64 + j * 8 + (lid & 3) * 2;
            *(uint32_t*)(g_ch + grow * DM + col) =
                packf16(o0[j][0] * i00, o0[j][1] * i00);
            *(uint32_t*)(g_ch + (grow + 8) * DM + col) =
                packf16(o0[j][2] * i01, o0[j][3] * i01);
        }
        const float i10 = 1.0f / l10, i11 = 1.0f / l11;
        const size_t grow1 = grow + 16;
        #pragma unroll
        for (int j = 0; j < 8; j++) {
            int col = h * 64 + j * 8 + (lid & 3) * 2;
            *(uint32_t*)(g_ch + grow1 * DM + col) =
                packf16(o1[j][0] * i10, o1[j][1] * i10);
            *(uint32_t*)(g_ch + (grow1 + 8) * DM + col) =
                packf16(o1[j][2] * i11, o1[j][3] * i11);
        }
    }
}

// ---------------------------------------------------------------------------
// Launch
// ---------------------------------------------------------------------------
extern "C" void kernel_launch(void* const* d_in, const int* in_sizes, int n_in,
                              void* d_out, int out_size)
{
    const float* queries   = (const float*)d_in[0];
    const float* keys      = (const float*)d_in[1];
    const float* values    = (const float*)d_in[2];
    const float* attn_bias = (const float*)d_in[3];
    const float* Wq = (const float*)d_in[4];
    const float* bq = (const float*)d_in[5];
    const float* Wk = (const float*)d_in[6];
    const float* bk = (const float*)d_in[7];
    const float* Wv = (const float*)d_in[8];
    const float* bv = (const float*)d_in[9];
    const float* Wo = (const float*)d_in[10];
    const float* bo = (const float*)d_in[11];
    float* out = (float*)d_out;

    __nv_bfloat16 *ah, *wh, *qkvh, *ch;
    cudaGetSymbolAddress((void**)&ah,   g_ah);
    cudaGetSymbolAddress((void**)&wh,   g_wh);
    cudaGetSymbolAddress((void**)&qkvh, g_qkvh);
    cudaGetSymbolAddress((void**)&ch,   g_ch);

    cudaFuncSetAttribute(attn_mma,
                         cudaFuncAttributeMaxDynamicSharedMemorySize, ATTN_SMEM);
    cudaFuncSetAttribute(qk_gemm,
                         cudaFuncAttributeMaxDynamicSharedMemorySize, QK_SMEM);
    cudaFuncSetAttribute((const void*)h_gemm<false>,
                         cudaFuncAttributeMaxDynamicSharedMemorySize, H_SMEM);
    cudaFuncSetAttribute((const void*)h_gemm<true>,
                         cudaFuncAttributeMaxDynamicSharedMemorySize, H_SMEM);

    conv_act3<<<dim3(4096, 3), 256>>>(queries, keys, values);
    conv_wt4<<<dim3(32, 32, 4), dim3(32, 8)>>>(Wq, Wk, Wv, Wo);

    // Q and K projections (bf16 3-term, 3-stage ring)
    qk_gemm<<<dim3(8, 32, 2), 256, QK_SMEM>>>(bq, bk);
    // V projection (fp16 1-term) -> single fp16
    h_gemm<false><<<dim3(8, 32), 256, H_SMEM>>>(
        ah + 2ull * ACT_ELEMS, wh + 2ull * W_ELEMS,
        bv, nullptr, qkvh + 2ull * ACT_ELEMS);

    attn_mma<<<dim3(64, 4), 256, ATTN_SMEM>>>(attn_bias);

    // Output projection (fp16 1-term) -> fp32
    h_gemm<true><<<dim3(8, 32), 256, H_SMEM>>>(
        ch, wh + 3ull * W_ELEMS, bo, out, nullptr);
}

// round 13
// speedup vs baseline: 1.7467x; 1.2740x over previous
#include <cuda_runtime.h>
#include <cuda_bf16.h>
#include <cuda_fp16.h>
#include <math.h>
#include <stdint.h>

// Problem constants
#define BB 4
#define NN 1024
#define DM 1024
#define NH 16
#define DK 64
#define LOG2E 1.4426950408889634f

// ---------------------------------------------------------------------------
// Scratch (__device__ globals; allocation-free rule). All fp16 bits now.
// ---------------------------------------------------------------------------
#define ACT_ELEMS (4096 * 1024)
#define W_ELEMS   (1024 * 1024)
__device__ __align__(16) __nv_bfloat16 g_ah[3ull * ACT_ELEMS];  // acts single fp16
__device__ __align__(16) __nv_bfloat16 g_wh[4ull * W_ELEMS];    // W hi (fp16)
__device__ __align__(16) __nv_bfloat16 g_wl[2ull * W_ELEMS];    // Wq/Wk lo (fp16)
// slot 0=Q fp16 hi/lo, 1=K single fp16, 2=V single fp16
__device__ __align__(16) __nv_bfloat16 g_qkvh[3ull * ACT_ELEMS];
__device__ __align__(16) __nv_bfloat16 g_qkvl[1ull * ACT_ELEMS];  // Q lo only
__device__ __align__(16) __nv_bfloat16 g_ch[ACT_ELEMS];           // ctx single fp16

// ---------------------------------------------------------------------------
// PTX helpers (compute_103-safe)
// ---------------------------------------------------------------------------
__device__ __forceinline__ uint32_t smem_u32(const void* p) {
    uint32_t a;
    asm("{ .reg .u64 t; cvta.to.shared.u64 t, %1; cvt.u32.u64 %0, t; }"
        : "=r"(a) : "l"(p));
    return a;
}

#define CP16(dst, src) \
    asm volatile("cp.async.cg.shared.global [%0], [%1], 16;" \
        :: "r"(dst), "l"(src) : "memory")
#define CP_COMMIT() asm volatile("cp.async.commit_group;" ::: "memory")
#define CP_WAIT1()  asm volatile("cp.async.wait_group 1;" ::: "memory")
#define CP_WAIT0()  asm volatile("cp.async.wait_group 0;" ::: "memory")

__device__ __forceinline__ void ldsm_x4(uint32_t* r, uint32_t addr) {
    asm volatile("ldmatrix.sync.aligned.m8n8.x4.shared.b16 {%0,%1,%2,%3}, [%4];"
        : "=r"(r[0]), "=r"(r[1]), "=r"(r[2]), "=r"(r[3]) : "r"(addr));
}
__device__ __forceinline__ void ldsm_x4_t(uint32_t* r, uint32_t addr) {
    asm volatile("ldmatrix.sync.aligned.m8n8.x4.trans.shared.b16 {%0,%1,%2,%3}, [%4];"
        : "=r"(r[0]), "=r"(r[1]), "=r"(r[2]), "=r"(r[3]) : "r"(addr));
}

__device__ __forceinline__ void mma16816h(float* c, const uint32_t* a,
                                          const uint32_t* b) {
    asm volatile(
        "mma.sync.aligned.m16n8k16.row.col.f32.f16.f16.f32 "
        "{%0,%1,%2,%3}, {%4,%5,%6,%7}, {%8,%9}, {%0,%1,%2,%3};"
        : "+f"(c[0]), "+f"(c[1]), "+f"(c[2]), "+f"(c[3])
        : "r"(a[0]), "r"(a[1]), "r"(a[2]), "r"(a[3]), "r"(b[0]), "r"(b[1]));
}

__device__ __forceinline__ float ex2(float x) {
    float r; asm("ex2.approx.f32 %0, %1;" : "=f"(r) : "f"(x)); return r;
}
__device__ __forceinline__ uint32_t packf16(float x, float y) {
    uint32_t r;
    asm("cvt.rn.f16x2.f32 %0, %1, %2;" : "=r"(r) : "f"(y), "f"(x));
    return r;
}
// fp16 hi/lo split of a float pair
__device__ __forceinline__ void split2h(float x, float y, uint32_t& h, uint32_t& l) {
    h = packf16(x, y);
    __half2 hh = *(__half2*)&h;
    float hx = __half2float(__low2half(hh)), hy = __half2float(__high2half(hh));
    l = packf16(x - hx, y - hy);
}

// ---------------------------------------------------------------------------
// Conversions: activations -> single fp16; Wq/Wk -> fp16 hi/lo; Wv/Wo -> fp16
// ---------------------------------------------------------------------------
__global__ __launch_bounds__(256) void conv_act3(
    const float* __restrict__ q, const float* __restrict__ k,
    const float* __restrict__ v)
{
    const int z = blockIdx.y;
    const float* X = z == 0 ? q : (z == 1 ? k : v);
    __nv_bfloat16* hi = g_ah + (size_t)z * ACT_ELEMS;
    int e = (blockIdx.x * 256 + threadIdx.x) * 4;
    float4 x = *(const float4*)(X + e);
    *(uint2*)(hi + e) = make_uint2(packf16(x.x, x.y), packf16(x.z, x.w));
}

__global__ void conv_wt4(const float* __restrict__ Wq, const float* __restrict__ Wk,
                         const float* __restrict__ Wv, const float* __restrict__ Wo)
{
    __shared__ float t[32][33];
    const int z = blockIdx.z;
    const float* W = z == 0 ? Wq : (z == 1 ? Wk : (z == 2 ? Wv : Wo));
    __nv_bfloat16* hi = g_wh + (size_t)z * W_ELEMS;
    int n0 = blockIdx.x * 32, k0 = blockIdx.y * 32;
    int tx = threadIdx.x, ty = threadIdx.y;  // 32 x 8

    #pragma unroll
    for (int j = 0; j < 32; j += 8)
        t[ty + j][tx] = W[(size_t)(k0 + ty + j) * 1024 + n0 + tx];
    __syncthreads();

    #pragma unroll
    for (int j = 0; j < 32; j += 8) {
        int n = n0 + ty + j, k = k0 + tx;
        float x = t[tx][ty + j];
        __half h = __float2half_rn(x);
        *(__half*)(hi + (size_t)n * 1024 + k) = h;
        if (z < 2) {
            __half l = __float2half_rn(x - __half2float(h));
            *(__half*)(g_wl + (size_t)z * W_ELEMS + (size_t)n * 1024 + k) = l;
        }
    }
}

// ---------------------------------------------------------------------------
// Q/K projection: A single fp16 x W fp16 hi/lo (2-term), 3-stage ring,
// 1 sync per chunk, 2 CTAs/SM.
// ---------------------------------------------------------------------------
#define ROWB 80
#define ARR_B (128 * ROWB)
#define QK_STAGE (3 * ARR_B)
#define QK_SMEM (3 * QK_STAGE)   // 92160 -> 2 CTAs/SM

__device__ __forceinline__ void qk_load_stage(
    uint32_t dbase, int m0, int n0, int k0, int tid,
    const __nv_bfloat16* A, const __nv_bfloat16* Bh, const __nv_bfloat16* Bl)
{
    int ldc = tid & 3;
    int r0 = tid >> 2;
    #pragma unroll
    for (int h = 0; h < 2; h++) {
        int row = r0 + h * 64;
        uint32_t doff = dbase + row * ROWB + ldc * 16;
        size_t ga = (size_t)(m0 + row) * 1024 + k0 + ldc * 8;
        size_t gb = (size_t)(n0 + row) * 1024 + k0 + ldc * 8;
        CP16(doff,             A + ga);
        CP16(doff + ARR_B,     Bh + gb);
        CP16(doff + 2 * ARR_B, Bl + gb);
    }
}

__global__ __launch_bounds__(256, 2) void qk_gemm(
    const float* __restrict__ bq, const float* __restrict__ bk)
{
    extern __shared__ __align__(16) char sm[];
    const int z = blockIdx.z;           // 0=Q, 1=K
    const float* bias = z == 0 ? bq : bk;
    const float scale = z == 0 ? 0.125f * LOG2E : 1.0f;
    const __nv_bfloat16* A  = g_ah + (size_t)z * ACT_ELEMS;
    const __nv_bfloat16* Bh = g_wh + (size_t)z * W_ELEMS;
    const __nv_bfloat16* Bl = g_wl + (size_t)z * W_ELEMS;
    __nv_bfloat16* Ch = g_qkvh + (size_t)z * ACT_ELEMS;
    const int m0 = blockIdx.y * 128, n0 = blockIdx.x * 128;

    const uint32_t sb = smem_u32(sm);
    const int tid = threadIdx.x;
    const int lid = tid & 31, wid = tid >> 5;
    const int wm = wid >> 1, wn = wid & 1;

    float acc[2][8][4];
    #pragma unroll
    for (int f = 0; f < 2; f++)
        #pragma unroll
        for (int n = 0; n < 8; n++)
            #pragma unroll
            for (int j = 0; j < 4; j++) acc[f][n][j] = 0.0f;

    const uint32_t a_rel = (uint32_t)(wm * 32 + (lid & 15)) * ROWB + ((lid >> 4) << 4);
    const uint32_t b_rel = (uint32_t)(wn * 64 + (lid & 7) + ((lid >> 4) << 3)) * ROWB
                           + (((lid >> 3) & 1) << 4);

    qk_load_stage(sb, m0, n0, 0, tid, A, Bh, Bl);
    CP_COMMIT();
    qk_load_stage(sb + QK_STAGE, m0, n0, 32, tid, A, Bh, Bl);
    CP_COMMIT();

    for (int c = 0; c < 32; c++) {
        if (c < 31) CP_WAIT1(); else CP_WAIT0();
        __syncthreads();
        if (c + 2 < 32) {
            qk_load_stage(sb + ((c + 2) % 3) * QK_STAGE, m0, n0, (c + 2) * 32,
                          tid, A, Bh, Bl);
            CP_COMMIT();
        }

        const uint32_t base = sb + (c % 3) * QK_STAGE;
        #pragma unroll
        for (int ks = 0; ks < 2; ks++) {
            const uint32_t koff = ks * 32;
            uint32_t a[2][4];
            #pragma unroll
            for (int f = 0; f < 2; f++)
                ldsm_x4(a[f], base + a_rel + f * 16 * ROWB + koff);
            #pragma unroll
            for (int nfp = 0; nfp < 4; nfp++) {
                uint32_t bh[4], bl[4];
                ldsm_x4(bh, base + ARR_B + b_rel + nfp * 16 * ROWB + koff);
                ldsm_x4(bl, base + 2 * ARR_B + b_rel + nfp * 16 * ROWB + koff);
                #pragma unroll
                for (int f = 0; f < 2; f++) {
                    mma16816h(acc[f][nfp * 2 + 0], a[f], bh + 0);
                    mma16816h(acc[f][nfp * 2 + 0], a[f], bl + 0);
                    mma16816h(acc[f][nfp * 2 + 1], a[f], bh + 2);
                    mma16816h(acc[f][nfp * 2 + 1], a[f], bl + 2);
                }
            }
        }
    }

    const int r_base = m0 + wm * 32 + (lid >> 2);
    const int c_lane = (lid & 3) * 2;
    #pragma unroll
    for (int f = 0; f < 2; f++) {
        #pragma unroll
        for (int nf = 0; nf < 8; nf++) {
            int col = n0 + wn * 64 + nf * 8 + c_lane;
            float2 bb = *(const float2*)(bias + col);
            int r0 = r_base + f * 16;
            float* a = acc[f][nf];
            float v0 = (a[0] + bb.x) * scale, v1 = (a[1] + bb.y) * scale;
            float v2 = (a[2] + bb.x) * scale, v3 = (a[3] + bb.y) * scale;
            if (z == 0) {
                uint32_t h0, l0, h1, l1;
                split2h(v0, v1, h0, l0);
                split2h(v2, v3, h1, l1);
                *(uint32_t*)(Ch + (size_t)r0 * 1024 + col) = h0;
                *(uint32_t*)(g_qkvl + (size_t)r0 * 1024 + col) = l0;
                *(uint32_t*)(Ch + (size_t)(r0 + 8) * 1024 + col) = h1;
                *(uint32_t*)(g_qkvl + (size_t)(r0 + 8) * 1024 + col) = l1;
            } else {
                *(uint32_t*)(Ch + (size_t)r0 * 1024 + col) = packf16(v0, v1);
                *(uint32_t*)(Ch + (size_t)(r0 + 8) * 1024 + col) = packf16(v2, v3);
            }
        }
    }
}

// ---------------------------------------------------------------------------
// fp16 1-term GEMM (V-projection, output projection), 3-stage ring.
// ---------------------------------------------------------------------------
#define H_STAGE (2 * ARR_B)
#define H_SMEM (3 * H_STAGE)   // 61440 -> 2 CTAs/SM

__device__ __forceinline__ void h_load_stage(
    uint32_t dbase, int m0, int n0, int k0, int tid,
    const __nv_bfloat16* A, const __nv_bfloat16* Bh)
{
    int ldc = tid & 3;
    int r0 = tid >> 2;
    #pragma unroll
    for (int h = 0; h < 2; h++) {
        int row = r0 + h * 64;
        uint32_t doff = dbase + row * ROWB + ldc * 16;
        size_t ga = (size_t)(m0 + row) * 1024 + k0 + ldc * 8;
        size_t gb = (size_t)(n0 + row) * 1024 + k0 + ldc * 8;
        CP16(doff,         A + ga);
        CP16(doff + ARR_B, Bh + gb);
    }
}

template <bool OUT_F32>
__global__ __launch_bounds__(256, 2) void h_gemm(
    const __nv_bfloat16* __restrict__ A, const __nv_bfloat16* __restrict__ Bh,
    const float* __restrict__ bias, float* __restrict__ outF,
    __nv_bfloat16* __restrict__ outH)
{
    extern __shared__ __align__(16) char sm[];
    const int m0 = blockIdx.y * 128, n0 = blockIdx.x * 128;

    const uint32_t sb = smem_u32(sm);
    const int tid = threadIdx.x;
    const int lid = tid & 31, wid = tid >> 5;
    const int wm = wid >> 1, wn = wid & 1;

    float acc[2][8][4];
    #pragma unroll
    for (int f = 0; f < 2; f++)
        #pragma unroll
        for (int n = 0; n < 8; n++)
            #pragma unroll
            for (int j = 0; j < 4; j++) acc[f][n][j] = 0.0f;

    const uint32_t a_rel = (uint32_t)(wm * 32 + (lid & 15)) * ROWB + ((lid >> 4) << 4);
    const uint32_t b_rel = (uint32_t)(wn * 64 + (lid & 7) + ((lid >> 4) << 3)) * ROWB
                           + (((lid >> 3) & 1) << 4);

    h_load_stage(sb, m0, n0, 0, tid, A, Bh);
    CP_COMMIT();
    h_load_stage(sb + H_STAGE, m0, n0, 32, tid, A, Bh);
    CP_COMMIT();

    for (int c = 0; c < 32; c++) {
        if (c < 31) CP_WAIT1(); else CP_WAIT0();
        __syncthreads();
        if (c + 2 < 32) {
            h_load_stage(sb + ((c + 2) % 3) * H_STAGE, m0, n0, (c + 2) * 32,
                         tid, A, Bh);
            CP_COMMIT();
        }

        const uint32_t base = sb + (c % 3) * H_STAGE;
        #pragma unroll
        for (int ks = 0; ks < 2; ks++) {
            const uint32_t koff = ks * 32;
            uint32_t a[2][4];
            #pragma unroll
            for (int f = 0; f < 2; f++)
                ldsm_x4(a[f], base + a_rel + f * 16 * ROWB + koff);
            #pragma unroll
            for (int nfp = 0; nfp < 4; nfp++) {
                uint32_t bh[4];
                ldsm_x4(bh, base + ARR_B + b_rel + nfp * 16 * ROWB + koff);
                #pragma unroll
                for (int f = 0; f < 2; f++) {
                    mma16816h(acc[f][nfp * 2 + 0], a[f], bh + 0);
                    mma16816h(acc[f][nfp * 2 + 1], a[f], bh + 2);
                }
            }
        }
    }

    const int r_base = m0 + wm * 32 + (lid >> 2);
    const int c_lane = (lid & 3) * 2;
    #pragma unroll
    for (int f = 0; f < 2; f++) {
        #pragma unroll
        for (int nf = 0; nf < 8; nf++) {
            int col = n0 + wn * 64 + nf * 8 + c_lane;
            float2 bb = *(const float2*)(bias + col);
            int r0 = r_base + f * 16;
            float* a = acc[f][nf];
            float v0 = a[0] + bb.x, v1 = a[1] + bb.y;
            float v2 = a[2] + bb.x, v3 = a[3] + bb.y;
            if (OUT_F32) {
                *(float2*)(outF + (size_t)r0 * 1024 + col) = make_float2(v0, v1);
                *(float2*)(outF + (size_t)(r0 + 8) * 1024 + col) = make_float2(v2, v3);
            } else {
                *(uint32_t*)(outH + (size_t)r0 * 1024 + col) = packf16(v0, v1);
                *(uint32_t*)(outH + (size_t)(r0 + 8) * 1024 + col) = packf16(v2, v3);
            }
        }
    }
}

// ---------------------------------------------------------------------------
// Tensor-core flash attention (exp2 domain), 32 q-rows per warp,
// 3-stage K/V ring, ONE sync per key tile.
// QK^T: Q fp16 hi/lo x K single fp16 (2-term); PV: P fp16 x V fp16 (1-term).
// ---------------------------------------------------------------------------
#define KROWB 144
#define TILE9K (64 * KROWB)            // 9216
#define QTILE (256 * KROWB)            // 36864
#define STAGE_A (2 * TILE9K)           // 18432: Kh, V
#define Q_OFF (3 * STAGE_A)            // 55296
#define ATTN_SMEM (Q_OFF + 2 * QTILE)  // 129024

__device__ __forceinline__ void attn_load_stage(
    uint32_t dst, int b, int h, int kt, int tid)
{
    const __nv_bfloat16* kh = g_qkvh + 1ull * ACT_ELEMS;  // fp16 bits
    const __nv_bfloat16* vv = g_qkvh + 2ull * ACT_ELEMS;  // fp16 bits
    const size_t krow = (size_t)(b * NN + kt * 64);
    #pragma unroll
    for (int t = 0; t < 2; t++) {
        int chunk = tid + t * 256;
        int r = chunk >> 3, c = chunk & 7;
        size_t g = (krow + r) * DM + h * 64 + c * 8;
        uint32_t d = dst + r * KROWB + c * 16;
        CP16(d,          kh + g);
        CP16(d + TILE9K, vv + g);
    }
}

__global__ __launch_bounds__(256, 1) void attn_mma(const float* __restrict__ bias)
{
    extern __shared__ __align__(16) char sm[];
    const uint32_t sb = smem_u32(sm);
    const int tid = threadIdx.x, lid = tid & 31, wid = tid >> 5;
    const int bh = blockIdx.x;
    const int qt = blockIdx.y;            // 0..3 (256-row q tiles)
    const int b = bh >> 4, h = bh & 15;
    const size_t qrow0 = (size_t)(b * NN + qt * 256);
    const int wq = wid * 32;

    #pragma unroll
    for (int t = 0; t < 8; t++) {
        int chunk = tid + t * 256;
        int r = chunk >> 3, c = chunk & 7;
        size_t g = (qrow0 + r) * DM + h * 64 + c * 8;
        CP16(sb + Q_OFF + r * KROWB + c * 16, g_qkvh + g);
        CP16(sb + Q_OFF + QTILE + r * KROWB + c * 16, g_qkvl + g);
    }
    attn_load_stage(sb, b, h, 0, tid);
    CP_COMMIT();
    attn_load_stage(sb + STAGE_A, b, h, 1, tid);
    CP_COMMIT();

    float o0[8][4], o1[8][4];
    #pragma unroll
    for (int j = 0; j < 8; j++)
        #pragma unroll
        for (int e = 0; e < 4; e++) { o0[j][e] = 0.0f; o1[j][e] = 0.0f; }
    float m00 = -1e30f, m01 = -1e30f, l00 = 0.0f, l01 = 0.0f;
    float m10 = -1e30f, m11 = -1e30f, l10 = 0.0f, l11 = 0.0f;

    const int rrow = (lid >> 2);
    const uint32_t qrel0 = sb + Q_OFF + (uint32_t)(wq + (lid & 15)) * KROWB
                           + ((lid >> 4) << 4);
    const uint32_t qrel1 = qrel0 + 16 * KROWB;
    const uint32_t krel_lane = (uint32_t)((lid & 7) + ((lid >> 4) << 3)) * KROWB
                               + (((lid >> 3) & 1) << 4);
    const uint32_t vcol_lane = ((lid >> 4) << 4);
    const uint32_t vrow_lane = (uint32_t)(lid & 15) * KROWB;

    const float* bias_pt0 = bias
        + (((size_t)(b * NH + h)) * NN + qt * 256 + wq + rrow) * NN
        + (lid & 3) * 2;
    const float* bias_pt1 = bias_pt0 + (size_t)16 * NN;

    for (int kt = 0; kt < 16; kt++) {
        if (kt < 15) CP_WAIT1(); else CP_WAIT0();
        __syncthreads();
        if (kt + 2 < 16) {
            attn_load_stage(sb + ((kt + 2) % 3) * STAGE_A, b, h, kt + 2, tid);
            CP_COMMIT();
        }
        const uint32_t st = sb + (kt % 3) * STAGE_A;

        // ---- bias LDG group 0 ----
        const float* bg0 = bias_pt0 + kt * 64;
        float2 ba0[8], bb0[8];
        #pragma unroll
        for (int j = 0; j < 8; j++) {
            ba0[j] = *(const float2*)(bg0 + j * 8);
            bb0[j] = *(const float2*)(bg0 + 8 * NN + j * 8);
        }

        // ---- S = Q K^T, 2-term fp16, both groups (K frags shared) ----
        float s0[8][4], s1[8][4];
        #pragma unroll
        for (int j = 0; j < 8; j++)
            #pragma unroll
            for (int e = 0; e < 4; e++) { s0[j][e] = 0.0f; s1[j][e] = 0.0f; }

        #pragma unroll
        for (int ks = 0; ks < 4; ks++) {
            uint32_t aqh0[4], aql0[4], aqh1[4], aql1[4];
            ldsm_x4(aqh0, qrel0 + ks * 32);
            ldsm_x4(aql0, qrel0 + QTILE + ks * 32);
            ldsm_x4(aqh1, qrel1 + ks * 32);
            ldsm_x4(aql1, qrel1 + QTILE + ks * 32);
            const uint32_t kbase = st + krel_lane + ks * 32;
            #pragma unroll
            for (int np = 0; np < 4; np++) {
                uint32_t bkh[4];
                ldsm_x4(bkh, kbase + np * 16 * KROWB);
                mma16816h(s0[2 * np + 0], aqh0, bkh + 0);
                mma16816h(s0[2 * np + 0], aql0, bkh + 0);
                mma16816h(s0[2 * np + 1], aqh0, bkh + 2);
                mma16816h(s0[2 * np + 1], aql0, bkh + 2);
                mma16816h(s1[2 * np + 0], aqh1, bkh + 0);
                mma16816h(s1[2 * np + 0], aql1, bkh + 0);
                mma16816h(s1[2 * np + 1], aqh1, bkh + 2);
                mma16816h(s1[2 * np + 1], aql1, bkh + 2);
            }
        }

        // ---- bias LDG group 1 ----
        const float* bg1 = bias_pt1 + kt * 64;
        float2 ba1[8], bb1[8];
        #pragma unroll
        for (int j = 0; j < 8; j++) {
            ba1[j] = *(const float2*)(bg1 + j * 8);
            bb1[j] = *(const float2*)(bg1 + 8 * NN + j * 8);
        }

        uint32_t pf0[4][4], pf1[4][4];

        // ---- group 0: bias + softmax + pack ----
        {
            #pragma unroll
            for (int j = 0; j < 8; j++) {
                s0[j][0] = fmaf(ba0[j].x, LOG2E, s0[j][0]);
                s0[j][1] = fmaf(ba0[j].y, LOG2E, s0[j][1]);
                s0[j][2] = fmaf(bb0[j].x, LOG2E, s0[j][2]);
                s0[j][3] = fmaf(bb0[j].y, LOG2E, s0[j][3]);
            }
            float mx0 = -1e30f, mx1 = -1e30f;
            #pragma unroll
            for (int j = 0; j < 8; j++) {
                mx0 = fmaxf(mx0, fmaxf(s0[j][0], s0[j][1]));
                mx1 = fmaxf(mx1, fmaxf(s0[j][2], s0[j][3]));
            }
            mx0 = fmaxf(mx0, __shfl_xor_sync(0xffffffffu, mx0, 1));
            mx0 = fmaxf(mx0, __shfl_xor_sync(0xffffffffu, mx0, 2));
            mx1 = fmaxf(mx1, __shfl_xor_sync(0xffffffffu, mx1, 1));
            mx1 = fmaxf(mx1, __shfl_xor_sync(0xffffffffu, mx1, 2));
            float mn0 = fmaxf(m00, mx0), mn1 = fmaxf(m01, mx1);
            float sc0 = ex2(m00 - mn0), sc1 = ex2(m01 - mn1);
            m00 = mn0; m01 = mn1;
            float rs0 = 0.0f, rs1 = 0.0f;
            #pragma unroll
            for (int j = 0; j < 8; j++) {
                s0[j][0] = ex2(s0[j][0] - m00);
                s0[j][1] = ex2(s0[j][1] - m00);
                s0[j][2] = ex2(s0[j][2] - m01);
                s0[j][3] = ex2(s0[j][3] - m01);
                rs0 += s0[j][0] + s0[j][1];
                rs1 += s0[j][2] + s0[j][3];
            }
            rs0 += __shfl_xor_sync(0xffffffffu, rs0, 1);
            rs0 += __shfl_xor_sync(0xffffffffu, rs0, 2);
            rs1 += __shfl_xor_sync(0xffffffffu, rs1, 1);
            rs1 += __shfl_xor_sync(0xffffffffu, rs1, 2);
            l00 = l00 * sc0 + rs0;
            l01 = l01 * sc1 + rs1;
            #pragma unroll
            for (int j = 0; j < 8; j++) {
                o0[j][0] *= sc0; o0[j][1] *= sc0;
                o0[j][2] *= sc1; o0[j][3] *= sc1;
            }
            #pragma unroll
            for (int ks = 0; ks < 4; ks++) {
                pf0[ks][0] = packf16(s0[2 * ks][0], s0[2 * ks][1]);
                pf0[ks][1] = packf16(s0[2 * ks][2], s0[2 * ks][3]);
                pf0[ks][2] = packf16(s0[2 * ks + 1][0], s0[2 * ks + 1][1]);
                pf0[ks][3] = packf16(s0[2 * ks + 1][2], s0[2 * ks + 1][3]);
            }
        }

        // ---- group 1: bias + softmax + pack ----
        {
            #pragma unroll
            for (int j = 0; j < 8; j++) {
                s1[j][0] = fmaf(ba1[j].x, LOG2E, s1[j][0]);
                s1[j][1] = fmaf(ba1[j].y, LOG2E, s1[j][1]);
                s1[j][2] = fmaf(bb1[j].x, LOG2E, s1[j][2]);
                s1[j][3] = fmaf(bb1[j].y, LOG2E, s1[j][3]);
            }
            float mx0 = -1e30f, mx1 = -1e30f;
            #pragma unroll
            for (int j = 0; j < 8; j++) {
                mx0 = fmaxf(mx0, fmaxf(s1[j][0], s1[j][1]));
                mx1 = fmaxf(mx1, fmaxf(s1[j][2], s1[j][3]));
            }
            mx0 = fmaxf(mx0, __shfl_xor_sync(0xffffffffu, mx0, 1));
            mx0 = fmaxf(mx0, __shfl_xor_sync(0xffffffffu, mx0, 2));
            mx1 = fmaxf(mx1, __shfl_xor_sync(0xffffffffu, mx1, 1));
            mx1 = fmaxf(mx1, __shfl_xor_sync(0xffffffffu, mx1, 2));
            float mn0 = fmaxf(m10, mx0), mn1 = fmaxf(m11, mx1);
            float sc0 = ex2(m10 - mn0), sc1 = ex2(m11 - mn1);
            m10 = mn0; m11 = mn1;
            float rs0 = 0.0f, rs1 = 0.0f;
            #pragma unroll
            for (int j = 0; j < 8; j++) {
                s1[j][0] = ex2(s1[j][0] - m10);
                s1[j][1] = ex2(s1[j][1] - m10);
                s1[j][2] = ex2(s1[j][2] - m11);
                s1[j][3] = ex2(s1[j][3] - m11);
                rs0 += s1[j][0] + s1[j][1];
                rs1 += s1[j][2] + s1[j][3];
            }
            rs0 += __shfl_xor_sync(0xffffffffu, rs0, 1);
            rs0 += __shfl_xor_sync(0xffffffffu, rs0, 2);
            rs1 += __shfl_xor_sync(0xffffffffu, rs1, 1);
            rs1 += __shfl_xor_sync(0xffffffffu, rs1, 2);
            l10 = l10 * sc0 + rs0;
            l11 = l11 * sc1 + rs1;
            #pragma unroll
            for (int j = 0; j < 8; j++) {
                o1[j][0] *= sc0; o1[j][1] *= sc0;
                o1[j][2] *= sc1; o1[j][3] *= sc1;
            }
            #pragma unroll
            for (int ks = 0; ks < 4; ks++) {
                pf1[ks][0] = packf16(s1[2 * ks][0], s1[2 * ks][1]);
                pf1[ks][1] = packf16(s1[2 * ks][2], s1[2 * ks][3]);
                pf1[ks][2] = packf16(s1[2 * ks + 1][0], s1[2 * ks + 1][1]);
                pf1[ks][3] = packf16(s1[2 * ks + 1][2], s1[2 * ks + 1][3]);
            }
        }

        // ---- O += P V (V frags shared across groups) ----
        #pragma unroll
        for (int ks = 0; ks < 4; ks++) {
            const uint32_t vbase = st + TILE9K + ks * 16 * KROWB
                                   + vrow_lane + vcol_lane;
            #pragma unroll
            for (int np = 0; np < 4; np++) {
                uint32_t bv[4];
                ldsm_x4_t(bv, vbase + np * 32);
                mma16816h(o0[2 * np + 0], pf0[ks], bv + 0);
                mma16816h(o0[2 * np + 1], pf0[ks], bv + 2);
                mma16816h(o1[2 * np + 0], pf1[ks], bv + 0);
                mma16816h(o1[2 * np + 1], pf1[ks], bv + 2);
            }
        }
    }

    // ---- epilogue -> ctx single fp16 ----
    {
        const float i00 = 1.0f / l00, i01 = 1.0f / l01;
        const size_t grow = qrow0 + wq + rrow;
        #pragma unroll
        for (int j = 0; j < 8; j++) {
            int col = h * 64 + j * 8 + (lid & 3) * 2;
            *(uint32_t*)(g_ch + grow * DM + col) =
                packf16(o0[j][0] * i00, o0[j][1] * i00);
            *(uint32_t*)(g_ch + (grow + 8) * DM + col) =
                packf16(o0[j][2] * i01, o0[j][3] * i01);
        }
        const float i10 = 1.0f / l10, i11 = 1.0f / l11;
        const size_t grow1 = grow + 16;
        #pragma unroll
        for (int j = 0; j < 8; j++) {
            int col = h * 64 + j * 8 + (lid & 3) * 2;
            *(uint32_t*)(g_ch + grow1 * DM + col) =
                packf16(o1[j][0] * i10, o1[j][1] * i10);
            *(uint32_t*)(g_ch + (grow1 + 8) * DM + col) =
                packf16(o1[j][2] * i11, o1[j][3] * i11);
        }
    }
}

// ---------------------------------------------------------------------------
// Launch
// ---------------------------------------------------------------------------
extern "C" void kernel_launch(void* const* d_in, const int* in_sizes, int n_in,
                              void* d_out, int out_size)
{
    const float* queries   = (const float*)d_in[0];
    const float* keys      = (const float*)d_in[1];
    const float* values    = (const float*)d_in[2];
    const float* attn_bias = (const float*)d_in[3];
    const float* Wq = (const float*)d_in[4];
    const float* bq = (const float*)d_in[5];
    const float* Wk = (const float*)d_in[6];
    const float* bk = (const float*)d_in[7];
    const float* Wv = (const float*)d_in[8];
    const float* bv = (const float*)d_in[9];
    const float* Wo = (const float*)d_in[10];
    const float* bo = (const float*)d_in[11];
    float* out = (float*)d_out;

    __nv_bfloat16 *ah, *wh, *qkvh, *ch;
    cudaGetSymbolAddress((void**)&ah,   g_ah);
    cudaGetSymbolAddress((void**)&wh,   g_wh);
    cudaGetSymbolAddress((void**)&qkvh, g_qkvh);
    cudaGetSymbolAddress((void**)&ch,   g_ch);

    cudaFuncSetAttribute(attn_mma,
                         cudaFuncAttributeMaxDynamicSharedMemorySize, ATTN_SMEM);
    cudaFuncSetAttribute(qk_gemm,
                         cudaFuncAttributeMaxDynamicSharedMemorySize, QK_SMEM);
    cudaFuncSetAttribute((const void*)h_gemm<false>,
                         cudaFuncAttributeMaxDynamicSharedMemorySize, H_SMEM);
    cudaFuncSetAttribute((const void*)h_gemm<true>,
                         cudaFuncAttributeMaxDynamicSharedMemorySize, H_SMEM);

    conv_act3<<<dim3(4096, 3), 256>>>(queries, keys, values);
    conv_wt4<<<dim3(32, 32, 4), dim3(32, 8)>>>(Wq, Wk, Wv, Wo);

    // Q and K projections (fp16 2-term, 3-stage ring, 2 CTAs/SM)
    qk_gemm<<<dim3(8, 32, 2), 256, QK_SMEM>>>(bq, bk);
    // V projection (fp16 1-term) -> single fp16
    h_gemm<false><<<dim3(8, 32), 256, H_SMEM>>>(
        ah + 2ull * ACT_ELEMS, wh + 2ull * W_ELEMS,
        bv, nullptr, qkvh + 2ull * ACT_ELEMS);

    attn_mma<<<dim3(64, 4), 256, ATTN_SMEM>>>(attn_bias);

    // Output projection (fp16 1-term) -> fp32
    h_gemm<true><<<dim3(8, 32), 256, H_SMEM>>>(
        ch, wh + 3ull * W_ELEMS, bo, out, nullptr);
}